// round 2
// baseline (speedup 1.0000x reference)
#include <cuda_runtime.h>

#define T_LEN 128

// ---------------- scratch layout (floats) ----------------
#define OFF_PRE   0                                   // [32][1024]
#define OFF_EXP   (OFF_PRE  + 32*1024)                // [32][1024] expanded (=h0)
#define OFF_A0IN  (OFF_EXP  + 32*1024)                // [160][1024]
#define OFF_C0    (OFF_A0IN + 160*1024)               // [160][2048]
#define OFF_P     (OFF_C0   + 160*2048)               // 2 sets x [4][2][32][1024]
#define OFF_X1    (OFF_P    + 2*4*2*32*1024)          // [4096][2048] rows t*32+b
#define OFF_G1    (OFF_X1   + 4096*2048)              // [4096][2048]
#define OFF_OUT2  (OFF_G1   + 4096*2048)              // [4096][2048] rows b*128+t
#define OFF_PROJ  (OFF_OUT2 + 4096*2048)              // [4096][512]
#define OFF_HE    (OFF_PROJ + 4096*512)               // [4096][512]
#define SCRATCH_TOTAL (OFF_HE + 4096*512)
#define PART_SET (4*2*32*1024)

__device__ float g_scratch[SCRATCH_TOTAL];

// ---------------- generic GEMM: C[M,N] = A[M,K] @ B[N,K]^T (+bias) ----------------
// 128x128 tile, BK=8, 256 threads, 8x8 register tile. M ragged; N%128==0, K%8==0.
__global__ __launch_bounds__(256) void gemm_tn_kernel(
    const float* __restrict__ A, const float* __restrict__ B,
    const float* __restrict__ bias, float* __restrict__ C,
    int M, int N, int K)
{
    __shared__ float As[8][128];
    __shared__ float Bs[8][128];
    const int tid = threadIdx.x;
    const int m0 = blockIdx.y * 128;
    const int n0 = blockIdx.x * 128;
    const int tm = tid >> 4;
    const int tn = tid & 15;
    const int lr = tid >> 1;
    const int lc = (tid & 1) * 4;

    float acc[8][8];
#pragma unroll
    for (int i = 0; i < 8; i++)
#pragma unroll
        for (int j = 0; j < 8; j++) acc[i][j] = 0.f;

    const bool aval = (m0 + lr) < M;
    const float* Ap = A + (size_t)(m0 + lr) * K + lc;
    const float* Bp = B + (size_t)(n0 + lr) * K + lc;

    for (int k0 = 0; k0 < K; k0 += 8) {
        float4 av = aval ? *(const float4*)Ap : make_float4(0.f, 0.f, 0.f, 0.f);
        float4 bv = *(const float4*)Bp;
        Ap += 8; Bp += 8;
        As[lc + 0][lr] = av.x; As[lc + 1][lr] = av.y;
        As[lc + 2][lr] = av.z; As[lc + 3][lr] = av.w;
        Bs[lc + 0][lr] = bv.x; Bs[lc + 1][lr] = bv.y;
        Bs[lc + 2][lr] = bv.z; Bs[lc + 3][lr] = bv.w;
        __syncthreads();
#pragma unroll
        for (int kk = 0; kk < 8; kk++) {
            float ar[8], br[8];
            *(float4*)&ar[0] = *(const float4*)&As[kk][tm * 8];
            *(float4*)&ar[4] = *(const float4*)&As[kk][tm * 8 + 4];
            *(float4*)&br[0] = *(const float4*)&Bs[kk][tn * 8];
            *(float4*)&br[4] = *(const float4*)&Bs[kk][tn * 8 + 4];
#pragma unroll
            for (int i = 0; i < 8; i++)
#pragma unroll
                for (int j = 0; j < 8; j++)
                    acc[i][j] += ar[i] * br[j];
        }
        __syncthreads();
    }

    float bvv[8];
#pragma unroll
    for (int j = 0; j < 8; j++) bvv[j] = bias ? bias[n0 + tn * 8 + j] : 0.f;
#pragma unroll
    for (int i = 0; i < 8; i++) {
        int row = m0 + tm * 8 + i;
        if (row < M) {
            float* Cp = C + (size_t)row * N + n0 + tn * 8;
            float4 o0, o1;
            o0.x = acc[i][0] + bvv[0]; o0.y = acc[i][1] + bvv[1];
            o0.z = acc[i][2] + bvv[2]; o0.w = acc[i][3] + bvv[3];
            o1.x = acc[i][4] + bvv[4]; o1.y = acc[i][5] + bvv[5];
            o1.z = acc[i][6] + bvv[6]; o1.w = acc[i][7] + bvv[7];
            *(float4*)Cp = o0;
            *(float4*)(Cp + 4) = o1;
        }
    }
}

// ---------------- LayerNorm + ReLU ----------------
__global__ __launch_bounds__(256) void ln_relu_kernel(
    const float* __restrict__ in, const float* __restrict__ g,
    const float* __restrict__ be, float* __restrict__ out, int C)
{
    __shared__ float red[256];
    const int row = blockIdx.x;
    const int tid = threadIdx.x;
    const float* rp = in + (size_t)row * C;
    float s = 0.f, sq = 0.f;
    for (int c = tid; c < C; c += 256) { float v = rp[c]; s += v; sq += v * v; }
    red[tid] = s; __syncthreads();
    for (int o = 128; o > 0; o >>= 1) { if (tid < o) red[tid] += red[tid + o]; __syncthreads(); }
    float mean = red[0] / (float)C;
    __syncthreads();
    red[tid] = sq; __syncthreads();
    for (int o = 128; o > 0; o >>= 1) { if (tid < o) red[tid] += red[tid + o]; __syncthreads(); }
    float var = red[0] / (float)C - mean * mean;
    float rs = rsqrtf(var + 1e-5f);
    float* op = out + (size_t)row * C;
    for (int c = tid; c < C; c += 256) {
        float v = (rp[c] - mean) * rs * g[c] + be[c];
        op[c] = fmaxf(v, 0.f);
    }
}

// ---------------- concat [expanded(32); pos(128)] ----------------
__global__ __launch_bounds__(256) void concat_kernel(
    const float* __restrict__ e, const float* __restrict__ pos, float* __restrict__ o)
{
    int i = blockIdx.x * 256 + threadIdx.x;   // 640 blocks, exact
    o[i] = (i < 32 * 1024) ? e[i] : pos[i - 32 * 1024];
}

// ---------------- one recurrence step (both dirs), split-K=4, deferred relu --------
// prevP/curP: [4 sp][2 d][32 b][1024 n]. sp==0 partial additionally carries gate+bias.
// h_{s-1} = relu(sum_sp prevP) computed at load; j==0 blocks emit it to Y.
__global__ __launch_bounds__(256) void step_kernel(
    const float* __restrict__ prevP, float* __restrict__ curP,
    const float* __restrict__ h0, const float* __restrict__ Whh,
    const float* __restrict__ gate, const float* __restrict__ bih,
    const float* __restrict__ bhh, float* __restrict__ Y,
    int s, int layer)
{
    const int tid = threadIdx.x;
    const int bx = blockIdx.x;        // 128 blocks
    const int j  = bx & 15;           // 64-col n block
    const int d  = (bx >> 4) & 1;
    const int sp = bx >> 5;           // 0..3 (k split)
    const int k0 = sp * 256;
    const int n0 = j * 64;

    __shared__ float Hs[32][257];
    __shared__ float Wst[32][68];

    // Phase 1: materialize h_{s-1}[b][k0..k0+255] for dir d
    const int tprev = (d == 0) ? (s - 2) : (T_LEN - s + 1);
    for (int i = tid; i < 32 * 256; i += 256) {
        const int b = i >> 8, k = i & 255;
        float v;
        if (s == 1) {
            v = h0[b * 1024 + k0 + k];
        } else {
            const float* pp = prevP + d * 32768 + b * 1024 + k0 + k;
            v = pp[0] + pp[65536] + pp[131072] + pp[196608];
            v = fmaxf(v, 0.f);
        }
        Hs[b][k] = v;
        if (j == 0 && s > 1) {
            const int col = d * 1024 + k0 + k;
            const int row = (layer == 0) ? (tprev * 32 + b) : (b * 128 + tprev);
            Y[(size_t)row * 2048 + col] = v;
        }
    }
    __syncthreads();

    // Phase 2: partial GEMM out[b][n0..n0+63] over k in [k0,k0+256)
    const int bg = (tid & 15) * 2;     // batch pair
    const int ng = (tid >> 4) * 4;     // 4 local n cols
    float acc0[4] = {0,0,0,0}, acc1[4] = {0,0,0,0};
    const float* Wbase = Whh + (size_t)d * 1048576 + (size_t)n0 * 1024 + k0;
    for (int kc = 0; kc < 256; kc += 32) {
#pragma unroll
        for (int r = 0; r < 8; r++) {
            int idx = tid + 256 * r;
            int nl = idx >> 5, kl = idx & 31;
            Wst[kl][nl] = Wbase[(size_t)nl * 1024 + kc + kl];
        }
        __syncthreads();
#pragma unroll
        for (int kk = 0; kk < 32; kk++) {
            float h0v = Hs[bg][kc + kk];
            float h1v = Hs[bg + 1][kc + kk];
            float4 wv = *(const float4*)&Wst[kk][ng];
            acc0[0] += h0v * wv.x; acc0[1] += h0v * wv.y;
            acc0[2] += h0v * wv.z; acc0[3] += h0v * wv.w;
            acc1[0] += h1v * wv.x; acc1[1] += h1v * wv.y;
            acc1[2] += h1v * wv.z; acc1[3] += h1v * wv.w;
        }
        __syncthreads();
    }

    float* cp = curP + sp * 65536 + d * 32768;
#pragma unroll
    for (int u = 0; u < 4; u++) {
        const int n = n0 + ng + u;
        float ga = 0.f, gb = 0.f;
        if (sp == 0) {
            const int t = (d == 0) ? (s - 1) : (T_LEN - s);
            const float bb = bih[d * 1024 + n] + bhh[d * 1024 + n];
            if (layer == 0) {
                const float pc = gate[(size_t)(32 + t) * 2048 + d * 1024 + n] + bb;
                ga = gate[(size_t)bg * 2048 + d * 1024 + n] + pc;
                gb = gate[(size_t)(bg + 1) * 2048 + d * 1024 + n] + pc;
            } else {
                ga = gate[(size_t)(t * 32 + bg) * 2048 + d * 1024 + n] + bb;
                gb = gate[(size_t)(t * 32 + bg + 1) * 2048 + d * 1024 + n] + bb;
            }
        }
        cp[bg * 1024 + n] = acc0[u] + ga;
        cp[(bg + 1) * 1024 + n] = acc1[u] + gb;
    }
}

// ---------------- flush final hidden state h_T into Y ----------------
__global__ __launch_bounds__(256) void flush_kernel(
    const float* __restrict__ P, float* __restrict__ Y, int layer)
{
    int idx = blockIdx.x * 256 + threadIdx.x;   // 256 blocks -> 65536
    const int d = idx >> 15;
    const int rem = idx & 32767;
    const int b = rem >> 10;
    const int n = rem & 1023;
    const float* pp = P + d * 32768 + b * 1024 + n;
    float v = fmaxf(pp[0] + pp[65536] + pp[131072] + pp[196608], 0.f);
    const int t = (d == 0) ? (T_LEN - 1) : 0;
    const int row = (layer == 0) ? (t * 32 + b) : (b * 128 + t);
    Y[(size_t)row * 2048 + d * 1024 + n] = v;
}

// ---------------- launch ----------------
static inline void gemm(const float* A, const float* B, const float* bias,
                        float* C, int M, int N, int K)
{
    dim3 grid(N / 128, (M + 127) / 128);
    gemm_tn_kernel<<<grid, 256>>>(A, B, bias, C, M, N, K);
}

extern "C" void kernel_launch(void* const* d_in, const int* in_sizes, int n_in,
                              void* d_out, int out_size)
{
    (void)in_sizes; (void)n_in; (void)out_size;
    const float* x     = (const float*)d_in[0];
    const float* W_exp = (const float*)d_in[1];
    const float* b_exp = (const float*)d_in[2];
    const float* g1    = (const float*)d_in[3];
    const float* be1   = (const float*)d_in[4];
    const float* pos   = (const float*)d_in[5];
    const float* Wih0  = (const float*)d_in[6];
    const float* Whh0  = (const float*)d_in[7];
    const float* bih0  = (const float*)d_in[8];
    const float* bhh0  = (const float*)d_in[9];
    const float* Wih1  = (const float*)d_in[10];
    const float* Whh1  = (const float*)d_in[11];
    const float* bih1  = (const float*)d_in[12];
    const float* bhh1  = (const float*)d_in[13];
    const float* Wp1   = (const float*)d_in[14];
    const float* bp1   = (const float*)d_in[15];
    const float* g2    = (const float*)d_in[16];
    const float* be2   = (const float*)d_in[17];
    const float* Wp2   = (const float*)d_in[18];
    const float* bp2   = (const float*)d_in[19];
    float* out = (float*)d_out;

    float* S = nullptr;
    cudaGetSymbolAddress((void**)&S, g_scratch);

    float* PRE  = S + OFF_PRE;
    float* EXP  = S + OFF_EXP;
    float* A0IN = S + OFF_A0IN;
    float* C0   = S + OFF_C0;
    float* P0   = S + OFF_P;               // set 0
    float* P1   = S + OFF_P + PART_SET;    // set 1
    float* X1   = S + OFF_X1;
    float* G1   = S + OFF_G1;
    float* OUT2 = S + OFF_OUT2;
    float* PROJ = S + OFF_PROJ;
    float* HE   = S + OFF_HE;

    // 1) expand: pre = x @ W_exp^T + b_exp ; expanded = relu(LN(pre))
    gemm(x, W_exp, b_exp, PRE, 32, 1024, 512);
    ln_relu_kernel<<<32, 256>>>(PRE, g1, be1, EXP, 1024);

    // 2) layer-0 gate factors: C0 = [expanded; pos] @ Wih0_stacked^T
    concat_kernel<<<640, 256>>>(EXP, pos, A0IN);
    gemm(A0IN, Wih0, nullptr, C0, 160, 2048, 1024);

    // 3) layer-0 recurrence (both dirs per step)
    for (int s = 1; s <= T_LEN; s++) {
        float* cur  = (s & 1) ? P1 : P0;
        float* prev = (s & 1) ? P0 : P1;
        step_kernel<<<128, 256>>>(prev, cur, EXP, Whh0, C0, bih0, bhh0, X1, s, 0);
    }
    flush_kernel<<<256, 256>>>(P0, X1, 0);   // s=128 wrote set 0

    // 4) layer-1 gates: G1 = X1 @ Wih1_stacked^T
    gemm(X1, Wih1, nullptr, G1, 4096, 2048, 2048);

    // 5) layer-1 recurrence
    for (int s = 1; s <= T_LEN; s++) {
        float* cur  = (s & 1) ? P1 : P0;
        float* prev = (s & 1) ? P0 : P1;
        step_kernel<<<128, 256>>>(prev, cur, EXP, Whh1, G1, bih1, bhh1, OUT2, s, 1);
    }
    flush_kernel<<<256, 256>>>(P0, OUT2, 1);

    // 6) projection head
    gemm(OUT2, Wp1, bp1, PROJ, 4096, 512, 2048);
    ln_relu_kernel<<<4096, 256>>>(PROJ, g2, be2, HE, 512);

    // 7) logits
    gemm(HE, Wp2, bp2, out, 4096, 32000, 512);
}

// round 3
// speedup vs baseline: 1.4380x; 1.4380x over previous
#include <cuda_runtime.h>

#define T_LEN 128

// ---------------- scratch layout (floats) ----------------
#define OFF_PRE   0                                   // [32][1024]
#define OFF_EXP   (OFF_PRE  + 32*1024)                // [32][1024] expanded (=h0)
#define OFF_A0IN  (OFF_EXP  + 32*1024)                // [160][1024]
#define OFF_C0    (OFF_A0IN + 160*1024)               // [160][2048]
#define OFF_P     (OFF_C0   + 160*2048)               // 2 sets x [4][2][32][1024]
#define OFF_X1    (OFF_P    + 2*4*2*32*1024)          // [4096][2048] rows t*32+b
#define OFF_G1    (OFF_X1   + 4096*2048)              // [4096][2048]
#define OFF_OUT2  (OFF_G1   + 4096*2048)              // [4096][2048] rows b*128+t
#define OFF_PROJ  (OFF_OUT2 + 4096*2048)              // [4096][512]
#define OFF_HE    (OFF_PROJ + 4096*512)               // [4096][512]
#define SCRATCH_TOTAL (OFF_HE + 4096*512)
#define PART_SET (4*2*32*1024)

__device__ float g_scratch[SCRATCH_TOTAL];

// ---------------- tf32 helpers ----------------
__device__ __forceinline__ unsigned f2tf32(float f) {
    unsigned u;
    asm("cvt.rna.tf32.f32 %0, %1;" : "=r"(u) : "f"(f));
    return u;
}

__device__ __forceinline__ void mma_tf32(float c[4], const unsigned a[4], const unsigned b[2]) {
    asm volatile(
        "mma.sync.aligned.m16n8k8.row.col.f32.tf32.tf32.f32 "
        "{%0,%1,%2,%3}, {%4,%5,%6,%7}, {%8,%9}, {%0,%1,%2,%3};"
        : "+f"(c[0]), "+f"(c[1]), "+f"(c[2]), "+f"(c[3])
        : "r"(a[0]), "r"(a[1]), "r"(a[2]), "r"(a[3]), "r"(b[0]), "r"(b[1]));
}

// ---------------- tf32 tensor-core GEMM: C[M,N] = A[M,K] @ B[N,K]^T (+bias) -------
// 128x128x16 tile, 256 threads (8 warps @ 64x32). M ragged; N%128==0, K%16==0.
#define SPITCH 136
__global__ __launch_bounds__(256, 2) void gemm_tf32_kernel(
    const float* __restrict__ A, const float* __restrict__ B,
    const float* __restrict__ bias, float* __restrict__ C,
    int M, int N, int K)
{
    __shared__ unsigned As[16][SPITCH];
    __shared__ unsigned Bs[16][SPITCH];

    const int tid  = threadIdx.x;
    const int warp = tid >> 5;
    const int lane = tid & 31;
    const int wm = warp & 1;          // 0..1 (64-row half)
    const int wn = warp >> 1;         // 0..3 (32-col quarter)
    const int gid = lane >> 2;        // 0..7
    const int tig = lane & 3;         // 0..3

    const int mblk = blockIdx.y * 128;
    const int nblk = blockIdx.x * 128;

    // global load mapping: row = tid>>1 (0..127), k offset = (tid&1)*8, 8 floats
    const int lr = tid >> 1;
    const int kc = (tid & 1) * 8;
    const int rowA = mblk + lr;
    const bool aval = rowA < M;
    const float* Ap = A + (size_t)(aval ? rowA : 0) * K + kc;
    const float* Bp = B + (size_t)(nblk + lr) * K + kc;

    float acc[4][4][4];
#pragma unroll
    for (int i = 0; i < 4; i++)
#pragma unroll
        for (int j = 0; j < 4; j++)
#pragma unroll
            for (int r = 0; r < 4; r++) acc[i][j][r] = 0.f;

    // prologue load
    float4 av0 = aval ? *(const float4*)Ap : make_float4(0,0,0,0);
    float4 av1 = aval ? *(const float4*)(Ap + 4) : make_float4(0,0,0,0);
    float4 bv0 = *(const float4*)Bp;
    float4 bv1 = *(const float4*)(Bp + 4);
    Ap += 16; Bp += 16;

    for (int k0 = 0; k0 < K; k0 += 16) {
        // store current tile to smem (tf32-converted), k-major
        As[kc + 0][lr] = f2tf32(av0.x); As[kc + 1][lr] = f2tf32(av0.y);
        As[kc + 2][lr] = f2tf32(av0.z); As[kc + 3][lr] = f2tf32(av0.w);
        As[kc + 4][lr] = f2tf32(av1.x); As[kc + 5][lr] = f2tf32(av1.y);
        As[kc + 6][lr] = f2tf32(av1.z); As[kc + 7][lr] = f2tf32(av1.w);
        Bs[kc + 0][lr] = f2tf32(bv0.x); Bs[kc + 1][lr] = f2tf32(bv0.y);
        Bs[kc + 2][lr] = f2tf32(bv0.z); Bs[kc + 3][lr] = f2tf32(bv0.w);
        Bs[kc + 4][lr] = f2tf32(bv1.x); Bs[kc + 5][lr] = f2tf32(bv1.y);
        Bs[kc + 6][lr] = f2tf32(bv1.z); Bs[kc + 7][lr] = f2tf32(bv1.w);
        __syncthreads();

        // prefetch next tile (overlaps with compute)
        if (k0 + 16 < K) {
            av0 = aval ? *(const float4*)Ap : make_float4(0,0,0,0);
            av1 = aval ? *(const float4*)(Ap + 4) : make_float4(0,0,0,0);
            bv0 = *(const float4*)Bp;
            bv1 = *(const float4*)(Bp + 4);
            Ap += 16; Bp += 16;
        }

#pragma unroll
        for (int ks = 0; ks < 2; ks++) {
            const int kb = ks * 8;
            unsigned afr[4][4], bfr[4][2];
#pragma unroll
            for (int mt = 0; mt < 4; mt++) {
                const int mr = wm * 64 + mt * 16 + gid;
                afr[mt][0] = As[kb + tig][mr];
                afr[mt][1] = As[kb + tig][mr + 8];
                afr[mt][2] = As[kb + tig + 4][mr];
                afr[mt][3] = As[kb + tig + 4][mr + 8];
            }
#pragma unroll
            for (int nt = 0; nt < 4; nt++) {
                const int nc = wn * 32 + nt * 8 + gid;
                bfr[nt][0] = Bs[kb + tig][nc];
                bfr[nt][1] = Bs[kb + tig + 4][nc];
            }
#pragma unroll
            for (int mt = 0; mt < 4; mt++)
#pragma unroll
                for (int nt = 0; nt < 4; nt++)
                    mma_tf32(acc[mt][nt], afr[mt], bfr[nt]);
        }
        __syncthreads();
    }

    // epilogue: bias + store (float2 per c-pair)
#pragma unroll
    for (int nt = 0; nt < 4; nt++) {
        const int col = nblk + wn * 32 + nt * 8 + tig * 2;
        const float b0 = bias ? bias[col] : 0.f;
        const float b1 = bias ? bias[col + 1] : 0.f;
#pragma unroll
        for (int mt = 0; mt < 4; mt++) {
            const int row = mblk + wm * 64 + mt * 16 + gid;
            if (row < M) {
                float2 v = make_float2(acc[mt][nt][0] + b0, acc[mt][nt][1] + b1);
                *(float2*)(C + (size_t)row * N + col) = v;
            }
            if (row + 8 < M) {
                float2 v = make_float2(acc[mt][nt][2] + b0, acc[mt][nt][3] + b1);
                *(float2*)(C + (size_t)(row + 8) * N + col) = v;
            }
        }
    }
}

// ---------------- LayerNorm + ReLU ----------------
__global__ __launch_bounds__(256) void ln_relu_kernel(
    const float* __restrict__ in, const float* __restrict__ g,
    const float* __restrict__ be, float* __restrict__ out, int C)
{
    __shared__ float red[256];
    const int row = blockIdx.x;
    const int tid = threadIdx.x;
    const float* rp = in + (size_t)row * C;
    float s = 0.f, sq = 0.f;
    for (int c = tid; c < C; c += 256) { float v = rp[c]; s += v; sq += v * v; }
    red[tid] = s; __syncthreads();
    for (int o = 128; o > 0; o >>= 1) { if (tid < o) red[tid] += red[tid + o]; __syncthreads(); }
    float mean = red[0] / (float)C;
    __syncthreads();
    red[tid] = sq; __syncthreads();
    for (int o = 128; o > 0; o >>= 1) { if (tid < o) red[tid] += red[tid + o]; __syncthreads(); }
    float var = red[0] / (float)C - mean * mean;
    float rs = rsqrtf(var + 1e-5f);
    float* op = out + (size_t)row * C;
    for (int c = tid; c < C; c += 256) {
        float v = (rp[c] - mean) * rs * g[c] + be[c];
        op[c] = fmaxf(v, 0.f);
    }
}

// ---------------- concat [expanded(32); pos(128)] ----------------
__global__ __launch_bounds__(256) void concat_kernel(
    const float* __restrict__ e, const float* __restrict__ pos, float* __restrict__ o)
{
    int i = blockIdx.x * 256 + threadIdx.x;   // 640 blocks, exact
    o[i] = (i < 32 * 1024) ? e[i] : pos[i - 32 * 1024];
}

// ---------------- one recurrence step (both dirs), split-K=4, deferred relu --------
__global__ __launch_bounds__(256) void step_kernel(
    const float* __restrict__ prevP, float* __restrict__ curP,
    const float* __restrict__ h0, const float* __restrict__ Whh,
    const float* __restrict__ gate, const float* __restrict__ bih,
    const float* __restrict__ bhh, float* __restrict__ Y,
    int s, int layer)
{
    const int tid = threadIdx.x;
    const int bx = blockIdx.x;        // 128 blocks
    const int j  = bx & 15;           // 64-col n block
    const int d  = (bx >> 4) & 1;
    const int sp = bx >> 5;           // 0..3 (k split)
    const int k0 = sp * 256;
    const int n0 = j * 64;

    __shared__ float Hs[32][257];
    __shared__ float Wst[32][68];

    const int tprev = (d == 0) ? (s - 2) : (T_LEN - s + 1);
    for (int i = tid; i < 32 * 256; i += 256) {
        const int b = i >> 8, k = i & 255;
        float v;
        if (s == 1) {
            v = h0[b * 1024 + k0 + k];
        } else {
            const float* pp = prevP + d * 32768 + b * 1024 + k0 + k;
            v = pp[0] + pp[65536] + pp[131072] + pp[196608];
            v = fmaxf(v, 0.f);
        }
        Hs[b][k] = v;
        if (j == 0 && s > 1) {
            const int col = d * 1024 + k0 + k;
            const int row = (layer == 0) ? (tprev * 32 + b) : (b * 128 + tprev);
            Y[(size_t)row * 2048 + col] = v;
        }
    }
    __syncthreads();

    const int bg = (tid & 15) * 2;
    const int ng = (tid >> 4) * 4;
    float acc0[4] = {0,0,0,0}, acc1[4] = {0,0,0,0};
    const float* Wbase = Whh + (size_t)d * 1048576 + (size_t)n0 * 1024 + k0;
    for (int kcb = 0; kcb < 256; kcb += 32) {
#pragma unroll
        for (int r = 0; r < 8; r++) {
            int idx = tid + 256 * r;
            int nl = idx >> 5, kl = idx & 31;
            Wst[kl][nl] = Wbase[(size_t)nl * 1024 + kcb + kl];
        }
        __syncthreads();
#pragma unroll
        for (int kk = 0; kk < 32; kk++) {
            float h0v = Hs[bg][kcb + kk];
            float h1v = Hs[bg + 1][kcb + kk];
            float4 wv = *(const float4*)&Wst[kk][ng];
            acc0[0] += h0v * wv.x; acc0[1] += h0v * wv.y;
            acc0[2] += h0v * wv.z; acc0[3] += h0v * wv.w;
            acc1[0] += h1v * wv.x; acc1[1] += h1v * wv.y;
            acc1[2] += h1v * wv.z; acc1[3] += h1v * wv.w;
        }
        __syncthreads();
    }

    float* cp = curP + sp * 65536 + d * 32768;
#pragma unroll
    for (int u = 0; u < 4; u++) {
        const int n = n0 + ng + u;
        float ga = 0.f, gb = 0.f;
        if (sp == 0) {
            const int t = (d == 0) ? (s - 1) : (T_LEN - s);
            const float bb = bih[d * 1024 + n] + bhh[d * 1024 + n];
            if (layer == 0) {
                const float pc = gate[(size_t)(32 + t) * 2048 + d * 1024 + n] + bb;
                ga = gate[(size_t)bg * 2048 + d * 1024 + n] + pc;
                gb = gate[(size_t)(bg + 1) * 2048 + d * 1024 + n] + pc;
            } else {
                ga = gate[(size_t)(t * 32 + bg) * 2048 + d * 1024 + n] + bb;
                gb = gate[(size_t)(t * 32 + bg + 1) * 2048 + d * 1024 + n] + bb;
            }
        }
        cp[bg * 1024 + n] = acc0[u] + ga;
        cp[(bg + 1) * 1024 + n] = acc1[u] + gb;
    }
}

// ---------------- flush final hidden state h_T into Y ----------------
__global__ __launch_bounds__(256) void flush_kernel(
    const float* __restrict__ P, float* __restrict__ Y, int layer)
{
    int idx = blockIdx.x * 256 + threadIdx.x;
    const int d = idx >> 15;
    const int rem = idx & 32767;
    const int b = rem >> 10;
    const int n = rem & 1023;
    const float* pp = P + d * 32768 + b * 1024 + n;
    float v = fmaxf(pp[0] + pp[65536] + pp[131072] + pp[196608], 0.f);
    const int t = (d == 0) ? (T_LEN - 1) : 0;
    const int row = (layer == 0) ? (t * 32 + b) : (b * 128 + t);
    Y[(size_t)row * 2048 + d * 1024 + n] = v;
}

// ---------------- launch ----------------
static inline void gemm(const float* A, const float* B, const float* bias,
                        float* C, int M, int N, int K)
{
    dim3 grid(N / 128, (M + 127) / 128);
    gemm_tf32_kernel<<<grid, 256>>>(A, B, bias, C, M, N, K);
}

extern "C" void kernel_launch(void* const* d_in, const int* in_sizes, int n_in,
                              void* d_out, int out_size)
{
    (void)in_sizes; (void)n_in; (void)out_size;
    const float* x     = (const float*)d_in[0];
    const float* W_exp = (const float*)d_in[1];
    const float* b_exp = (const float*)d_in[2];
    const float* g1    = (const float*)d_in[3];
    const float* be1   = (const float*)d_in[4];
    const float* pos   = (const float*)d_in[5];
    const float* Wih0  = (const float*)d_in[6];
    const float* Whh0  = (const float*)d_in[7];
    const float* bih0  = (const float*)d_in[8];
    const float* bhh0  = (const float*)d_in[9];
    const float* Wih1  = (const float*)d_in[10];
    const float* Whh1  = (const float*)d_in[11];
    const float* bih1  = (const float*)d_in[12];
    const float* bhh1  = (const float*)d_in[13];
    const float* Wp1   = (const float*)d_in[14];
    const float* bp1   = (const float*)d_in[15];
    const float* g2    = (const float*)d_in[16];
    const float* be2   = (const float*)d_in[17];
    const float* Wp2   = (const float*)d_in[18];
    const float* bp2   = (const float*)d_in[19];
    float* out = (float*)d_out;

    float* S = nullptr;
    cudaGetSymbolAddress((void**)&S, g_scratch);

    float* PRE  = S + OFF_PRE;
    float* EXP  = S + OFF_EXP;
    float* A0IN = S + OFF_A0IN;
    float* C0   = S + OFF_C0;
    float* P0   = S + OFF_P;
    float* P1   = S + OFF_P + PART_SET;
    float* X1   = S + OFF_X1;
    float* G1   = S + OFF_G1;
    float* OUT2 = S + OFF_OUT2;
    float* PROJ = S + OFF_PROJ;
    float* HE   = S + OFF_HE;

    // 1) expand
    gemm(x, W_exp, b_exp, PRE, 32, 1024, 512);
    ln_relu_kernel<<<32, 256>>>(PRE, g1, be1, EXP, 1024);

    // 2) layer-0 gate factors
    concat_kernel<<<640, 256>>>(EXP, pos, A0IN);
    gemm(A0IN, Wih0, nullptr, C0, 160, 2048, 1024);

    // 3) layer-0 recurrence
    for (int s = 1; s <= T_LEN; s++) {
        float* cur  = (s & 1) ? P1 : P0;
        float* prev = (s & 1) ? P0 : P1;
        step_kernel<<<128, 256>>>(prev, cur, EXP, Whh0, C0, bih0, bhh0, X1, s, 0);
    }
    flush_kernel<<<256, 256>>>(P0, X1, 0);

    // 4) layer-1 gates
    gemm(X1, Wih1, nullptr, G1, 4096, 2048, 2048);

    // 5) layer-1 recurrence
    for (int s = 1; s <= T_LEN; s++) {
        float* cur  = (s & 1) ? P1 : P0;
        float* prev = (s & 1) ? P0 : P1;
        step_kernel<<<128, 256>>>(prev, cur, EXP, Whh1, G1, bih1, bhh1, OUT2, s, 1);
    }
    flush_kernel<<<256, 256>>>(P0, OUT2, 1);

    // 6) projection head
    gemm(OUT2, Wp1, bp1, PROJ, 4096, 512, 2048);
    ln_relu_kernel<<<4096, 256>>>(PROJ, g2, be2, HE, 512);

    // 7) logits
    gemm(HE, Wp2, bp2, out, 4096, 32000, 512);
}

// round 4
// speedup vs baseline: 1.8323x; 1.2742x over previous
#include <cuda_runtime.h>

#define T_LEN 128
#define NB 128          // persistent RNN blocks

// ---------------- scratch layout (floats) ----------------
#define OFF_PRE   0                                   // [32][1024]
#define OFF_EXP   (OFF_PRE  + 32*1024)                // [32][1024] expanded (=h0)
#define OFF_A0IN  (OFF_EXP  + 32*1024)                // [160][1024]
#define OFF_C0    (OFF_A0IN + 160*1024)               // [160][2048]
#define OFF_P     (OFF_C0   + 160*2048)               // h exchange: 2 sets x [2][16][2048]
#define OFF_X1    (OFF_P    + 2*4*2*32*1024)          // [4096][2048] rows t*32+b
#define OFF_G1    (OFF_X1   + 4096*2048)              // [4096][2048]
#define OFF_OUT2  (OFF_G1   + 4096*2048)              // [4096][2048] rows b*128+t
#define OFF_PROJ  (OFF_OUT2 + 4096*2048)              // [4096][512]
#define OFF_HE    (OFF_PROJ + 4096*512)               // [4096][512]
#define SCRATCH_TOTAL (OFF_HE + 4096*512)

__device__ float g_scratch[SCRATCH_TOTAL];
__device__ unsigned g_bar_count;
__device__ unsigned g_bar_sense;

// ---------------- tf32 helpers ----------------
__device__ __forceinline__ unsigned f2tf32(float f) {
    unsigned u;
    asm("cvt.rna.tf32.f32 %0, %1;" : "=r"(u) : "f"(f));
    return u;
}

__device__ __forceinline__ void mma_tf32(float c[4], const unsigned a[4], const unsigned b[2]) {
    asm volatile(
        "mma.sync.aligned.m16n8k8.row.col.f32.tf32.tf32.f32 "
        "{%0,%1,%2,%3}, {%4,%5,%6,%7}, {%8,%9}, {%0,%1,%2,%3};"
        : "+f"(c[0]), "+f"(c[1]), "+f"(c[2]), "+f"(c[3])
        : "r"(a[0]), "r"(a[1]), "r"(a[2]), "r"(a[3]), "r"(b[0]), "r"(b[1]));
}

// ---------------- tf32 tensor-core GEMM: C[M,N] = A[M,K] @ B[N,K]^T (+bias) -------
// 128x128x16 tile, 256 threads (8 warps @ 64x32). Permuted-k smem layout so each
// fragment (both k-steps) is one LDS.128: slot(k) = (k&3)*4 + (k>>2), pitch 20.
__global__ __launch_bounds__(256, 2) void gemm_tf32_kernel(
    const float* __restrict__ A, const float* __restrict__ B,
    const float* __restrict__ bias, float* __restrict__ C,
    int M, int N, int K)
{
    __shared__ unsigned As[128][20];
    __shared__ unsigned Bs[128][20];

    const int tid  = threadIdx.x;
    const int warp = tid >> 5;
    const int lane = tid & 31;
    const int wm = warp & 1;
    const int wn = warp >> 1;
    const int gid = lane >> 2;        // 0..7
    const int tig = lane & 3;         // 0..3

    const int mblk = blockIdx.y * 128;
    const int nblk = blockIdx.x * 128;

    const int lr = tid >> 1;          // row 0..127
    const int kc = (tid & 1) * 8;     // k offset 0 or 8
    const int rowA = mblk + lr;
    const bool aval = rowA < M;
    const float* Ap = A + (size_t)(aval ? rowA : 0) * K + kc;
    const float* Bp = B + (size_t)(nblk + lr) * K + kc;

    float acc[4][4][4];
#pragma unroll
    for (int i = 0; i < 4; i++)
#pragma unroll
        for (int j = 0; j < 4; j++)
#pragma unroll
            for (int r = 0; r < 4; r++) acc[i][j][r] = 0.f;

    float4 av0 = aval ? *(const float4*)Ap : make_float4(0,0,0,0);
    float4 av1 = aval ? *(const float4*)(Ap + 4) : make_float4(0,0,0,0);
    float4 bv0 = *(const float4*)Bp;
    float4 bv1 = *(const float4*)(Bp + 4);
    Ap += 16; Bp += 16;

    for (int k0 = 0; k0 < K; k0 += 16) {
        float a8[8] = {av0.x, av0.y, av0.z, av0.w, av1.x, av1.y, av1.z, av1.w};
        float b8[8] = {bv0.x, bv0.y, bv0.z, bv0.w, bv1.x, bv1.y, bv1.z, bv1.w};
#pragma unroll
        for (int i = 0; i < 8; i++) {
            const int k = kc + i;
            const int slot = ((k & 3) << 2) | (k >> 2);
            As[lr][slot] = f2tf32(a8[i]);
            Bs[lr][slot] = f2tf32(b8[i]);
        }
        __syncthreads();

        if (k0 + 16 < K) {
            av0 = aval ? *(const float4*)Ap : make_float4(0,0,0,0);
            av1 = aval ? *(const float4*)(Ap + 4) : make_float4(0,0,0,0);
            bv0 = *(const float4*)Bp;
            bv1 = *(const float4*)(Bp + 4);
            Ap += 16; Bp += 16;
        }

        // vectorized fragment loads: one uint4 covers k = {tig, tig+4, tig+8, tig+12}
        uint4 va[4], v8[4], ub[4];
#pragma unroll
        for (int mt = 0; mt < 4; mt++) {
            const int mr = wm * 64 + mt * 16 + gid;
            va[mt] = *(const uint4*)&As[mr][tig * 4];
            v8[mt] = *(const uint4*)&As[mr + 8][tig * 4];
        }
#pragma unroll
        for (int nt = 0; nt < 4; nt++) {
            const int nc = wn * 32 + nt * 8 + gid;
            ub[nt] = *(const uint4*)&Bs[nc][tig * 4];
        }
#pragma unroll
        for (int ks = 0; ks < 2; ks++) {
            unsigned afr[4][4], bfr[4][2];
#pragma unroll
            for (int mt = 0; mt < 4; mt++) {
                if (ks == 0) {
                    afr[mt][0] = va[mt].x; afr[mt][1] = v8[mt].x;
                    afr[mt][2] = va[mt].y; afr[mt][3] = v8[mt].y;
                } else {
                    afr[mt][0] = va[mt].z; afr[mt][1] = v8[mt].z;
                    afr[mt][2] = va[mt].w; afr[mt][3] = v8[mt].w;
                }
            }
#pragma unroll
            for (int nt = 0; nt < 4; nt++) {
                if (ks == 0) { bfr[nt][0] = ub[nt].x; bfr[nt][1] = ub[nt].y; }
                else         { bfr[nt][0] = ub[nt].z; bfr[nt][1] = ub[nt].w; }
            }
#pragma unroll
            for (int mt = 0; mt < 4; mt++)
#pragma unroll
                for (int nt = 0; nt < 4; nt++)
                    mma_tf32(acc[mt][nt], afr[mt], bfr[nt]);
        }
        __syncthreads();
    }

#pragma unroll
    for (int nt = 0; nt < 4; nt++) {
        const int col = nblk + wn * 32 + nt * 8 + tig * 2;
        const float b0 = bias ? bias[col] : 0.f;
        const float b1 = bias ? bias[col + 1] : 0.f;
#pragma unroll
        for (int mt = 0; mt < 4; mt++) {
            const int row = mblk + wm * 64 + mt * 16 + gid;
            if (row < M) {
                float2 v = make_float2(acc[mt][nt][0] + b0, acc[mt][nt][1] + b1);
                *(float2*)(C + (size_t)row * N + col) = v;
            }
            if (row + 8 < M) {
                float2 v = make_float2(acc[mt][nt][2] + b0, acc[mt][nt][3] + b1);
                *(float2*)(C + (size_t)(row + 8) * N + col) = v;
            }
        }
    }
}

// ---------------- LayerNorm + ReLU ----------------
__global__ __launch_bounds__(256) void ln_relu_kernel(
    const float* __restrict__ in, const float* __restrict__ g,
    const float* __restrict__ be, float* __restrict__ out, int C)
{
    __shared__ float red[256];
    const int row = blockIdx.x;
    const int tid = threadIdx.x;
    const float* rp = in + (size_t)row * C;
    float s = 0.f, sq = 0.f;
    for (int c = tid; c < C; c += 256) { float v = rp[c]; s += v; sq += v * v; }
    red[tid] = s; __syncthreads();
    for (int o = 128; o > 0; o >>= 1) { if (tid < o) red[tid] += red[tid + o]; __syncthreads(); }
    float mean = red[0] / (float)C;
    __syncthreads();
    red[tid] = sq; __syncthreads();
    for (int o = 128; o > 0; o >>= 1) { if (tid < o) red[tid] += red[tid + o]; __syncthreads(); }
    float var = red[0] / (float)C - mean * mean;
    float rs = rsqrtf(var + 1e-5f);
    float* op = out + (size_t)row * C;
    for (int c = tid; c < C; c += 256) {
        float v = (rp[c] - mean) * rs * g[c] + be[c];
        op[c] = fmaxf(v, 0.f);
    }
}

// ---------------- concat [expanded(32); pos(128)] ----------------
__global__ __launch_bounds__(256) void concat_kernel(
    const float* __restrict__ e, const float* __restrict__ pos, float* __restrict__ o)
{
    int i = blockIdx.x * 256 + threadIdx.x;
    o[i] = (i < 32 * 1024) ? e[i] : pos[i - 32 * 1024];
}

// ---------------- pack h0 into exchange buffer set 0: [d][bp][k][c] ----------------
__global__ __launch_bounds__(256) void pack_h0_kernel(
    const float* __restrict__ EXP, float* __restrict__ HB)
{
    int i = blockIdx.x * 256 + threadIdx.x;     // 65536 threads -> 32768 per d
    const int bp = i >> 11;                      // 0..15
    const int j  = i & 2047;
    const int k  = j >> 1;
    const int c  = j & 1;
    const float v = EXP[(2 * bp + c) * 1024 + k];
    HB[i] = v;             // d=0
    HB[32768 + i] = v;     // d=1
}

// ---------------- persistent RNN layer: 128 blocks, 1 per SM ----------------
// block bid: d = bid>>6, nblk = bid&63 owns n-slice [nblk*16, +16).
// smem: Wsh[16][1028], Hsh2[16 bp][2052] (float2-packed h), Red[512][12].
#define W_PITCH 1028
#define H_PITCH 2052
#define WSH_OFF 0
#define HSH_OFF (16 * W_PITCH)
#define RED_OFF (HSH_OFF + 16 * H_PITCH)
#define RNN_SMEM_FLOATS (RED_OFF + 512 * 12)
#define RNN_SMEM_BYTES  (RNN_SMEM_FLOATS * 4)

__device__ __forceinline__ unsigned ld_acquire_u32(unsigned* p) {
    unsigned v;
    asm volatile("ld.acquire.gpu.global.u32 %0, [%1];" : "=r"(v) : "l"(p) : "memory");
    return v;
}
__device__ __forceinline__ unsigned atom_add_acqrel(unsigned* p, unsigned v) {
    unsigned o;
    asm volatile("atom.acq_rel.gpu.global.add.u32 %0, [%1], %2;" : "=r"(o) : "l"(p), "r"(v) : "memory");
    return o;
}
__device__ __forceinline__ void st_relaxed_u32(unsigned* p, unsigned v) {
    asm volatile("st.relaxed.gpu.global.u32 [%0], %1;" :: "l"(p), "r"(v) : "memory");
}
__device__ __forceinline__ void st_release_u32(unsigned* p, unsigned v) {
    asm volatile("st.release.gpu.global.u32 [%0], %1;" :: "l"(p), "r"(v) : "memory");
}

__global__ __launch_bounds__(256, 1) void rnn_layer_kernel(
    const float* __restrict__ Whh, const float* __restrict__ gate,
    const float* __restrict__ bih, const float* __restrict__ bhh,
    float* __restrict__ HB, float* __restrict__ Y, int layer)
{
    extern __shared__ float sm[];
    float* Wsh  = sm + WSH_OFF;
    float* Hsh  = sm + HSH_OFF;
    float* Red  = sm + RED_OFF;

    const int tid = threadIdx.x;
    const int bid = blockIdx.x;
    const int d = bid >> 6;
    const int n0 = (bid & 63) * 16;

    // thread mapping for compute: kq = warp (8), bq = lane&7 (4 b each), ng = lane>>3 (4 n each)
    const int kq = tid >> 5;
    const int lane = tid & 31;
    const int bq = lane & 7;
    const int ng = lane >> 3;

    // load W tile into smem: Wsh[n][k] = Whh[d*1024 + n0+n][k]
    for (int it = 0; it < 16; it++) {
        const int idx = tid + it * 256;         // 4096 float4s
        const int n = idx >> 8, k4 = idx & 255;
        float4 w = *(const float4*)&Whh[(size_t)(d * 1024 + n0 + n) * 1024 + k4 * 4];
        *(float4*)&Wsh[n * W_PITCH + k4 * 4] = w;
    }

    unsigned local_sense = 0;

    for (int s = 1; s <= T_LEN; s++) {
        // ---- copy h_{s-1} (set (s-1)&1) into smem, float2-packed layout ----
        const float* src = HB + ((s - 1) & 1) * 65536 + d * 32768;
        __syncthreads();
#pragma unroll
        for (int it = 0; it < 32; it++) {
            const int idx = (tid + it * 256) * 4;   // 8192 float4s = 32768 floats
            const int bp = idx >> 11, rem = idx & 2047;
            float4 v = *(const float4*)&src[idx];
            *(float4*)&Hsh[bp * H_PITCH + rem] = v;
        }
        __syncthreads();

        // ---- compute: acc[4 b][4 n] over k-slice [kq*128, +128) ----
        float acc[4][4];
#pragma unroll
        for (int i = 0; i < 4; i++)
#pragma unroll
            for (int j = 0; j < 4; j++) acc[i][j] = 0.f;

        const float* h0p = &Hsh[(2 * bq) * H_PITCH];
        const float* h1p = &Hsh[(2 * bq + 1) * H_PITCH];
        const float* wp  = &Wsh[(ng * 4) * W_PITCH];

        for (int k = kq * 128; k < kq * 128 + 128; k += 4) {
            float4 hA0 = *(const float4*)&h0p[2 * k];       // b0,b1 @ k,k+1
            float4 hA1 = *(const float4*)&h0p[2 * k + 4];   // b0,b1 @ k+2,k+3
            float4 hB0 = *(const float4*)&h1p[2 * k];       // b2,b3 @ k,k+1
            float4 hB1 = *(const float4*)&h1p[2 * k + 4];
            float hv[4][4];
            hv[0][0] = hA0.x; hv[0][1] = hA0.z; hv[0][2] = hA1.x; hv[0][3] = hA1.z;
            hv[1][0] = hA0.y; hv[1][1] = hA0.w; hv[1][2] = hA1.y; hv[1][3] = hA1.w;
            hv[2][0] = hB0.x; hv[2][1] = hB0.z; hv[2][2] = hB1.x; hv[2][3] = hB1.z;
            hv[3][0] = hB0.y; hv[3][1] = hB0.w; hv[3][2] = hB1.y; hv[3][3] = hB1.w;
            float wv[4][4];
#pragma unroll
            for (int j = 0; j < 4; j++) {
                float4 w = *(const float4*)&wp[j * W_PITCH + k];
                wv[j][0] = w.x; wv[j][1] = w.y; wv[j][2] = w.z; wv[j][3] = w.w;
            }
#pragma unroll
            for (int kk = 0; kk < 4; kk++)
#pragma unroll
                for (int bi = 0; bi < 4; bi++)
#pragma unroll
                    for (int ni = 0; ni < 4; ni++)
                        acc[bi][ni] += hv[bi][kk] * wv[ni][kk];
        }

        // ---- reduce over kq in smem ----
        __syncthreads();   // Red region free (Hsh read done)
#pragma unroll
        for (int bi = 0; bi < 4; bi++)
#pragma unroll
            for (int ni = 0; ni < 4; ni++) {
                const int o = (bq * 4 + bi) * 16 + ng * 4 + ni;
                Red[o * 12 + kq] = acc[bi][ni];
            }
        __syncthreads();

        // ---- epilogue: gate + bias + relu, write h_s and Y ----
        const int t = d ? (T_LEN - s) : (s - 1);
        float* dst = HB + (s & 1) * 65536 + d * 32768;
#pragma unroll
        for (int oo = 0; oo < 2; oo++) {
            const int o = tid + oo * 256;
            const float* rp = &Red[o * 12];
            float4 r0 = *(const float4*)rp;
            float4 r1 = *(const float4*)(rp + 4);
            float v = ((r0.x + r0.y) + (r0.z + r0.w)) + ((r1.x + r1.y) + (r1.z + r1.w));
            const int b = o >> 4, n = o & 15;
            const int ncol = n0 + n;
            const int col = d * 1024 + ncol;
            const float bb = bih[col] + bhh[col];
            float gv;
            if (layer == 0)
                gv = gate[(size_t)b * 2048 + col] + gate[(size_t)(32 + t) * 2048 + col];
            else
                gv = gate[(size_t)(t * 32 + b) * 2048 + col];
            const float hnew = fmaxf(v + gv + bb, 0.f);
            dst[(b >> 1) * 2048 + 2 * ncol + (b & 1)] = hnew;
            const int row = layer ? (b * 128 + t) : (t * 32 + b);
            Y[(size_t)row * 2048 + col] = hnew;
        }

        // ---- grid barrier (sense reversal) ----
        __syncthreads();
        if (tid == 0) {
            const unsigned target = local_sense ^ 1;
            unsigned old = atom_add_acqrel(&g_bar_count, 1);
            if (old == NB - 1) {
                st_relaxed_u32(&g_bar_count, 0);
                st_release_u32(&g_bar_sense, target);
            } else {
                while (ld_acquire_u32(&g_bar_sense) != target) { }
            }
        }
        local_sense ^= 1;
        __syncthreads();
    }
}

// ---------------- launch ----------------
static inline void gemm(const float* A, const float* B, const float* bias,
                        float* C, int M, int N, int K)
{
    dim3 grid(N / 128, (M + 127) / 128);
    gemm_tf32_kernel<<<grid, 256>>>(A, B, bias, C, M, N, K);
}

extern "C" void kernel_launch(void* const* d_in, const int* in_sizes, int n_in,
                              void* d_out, int out_size)
{
    (void)in_sizes; (void)n_in; (void)out_size;
    const float* x     = (const float*)d_in[0];
    const float* W_exp = (const float*)d_in[1];
    const float* b_exp = (const float*)d_in[2];
    const float* g1    = (const float*)d_in[3];
    const float* be1   = (const float*)d_in[4];
    const float* pos   = (const float*)d_in[5];
    const float* Wih0  = (const float*)d_in[6];
    const float* Whh0  = (const float*)d_in[7];
    const float* bih0  = (const float*)d_in[8];
    const float* bhh0  = (const float*)d_in[9];
    const float* Wih1  = (const float*)d_in[10];
    const float* Whh1  = (const float*)d_in[11];
    const float* bih1  = (const float*)d_in[12];
    const float* bhh1  = (const float*)d_in[13];
    const float* Wp1   = (const float*)d_in[14];
    const float* bp1   = (const float*)d_in[15];
    const float* g2    = (const float*)d_in[16];
    const float* be2   = (const float*)d_in[17];
    const float* Wp2   = (const float*)d_in[18];
    const float* bp2   = (const float*)d_in[19];
    float* out = (float*)d_out;

    float* S = nullptr;
    cudaGetSymbolAddress((void**)&S, g_scratch);

    float* PRE  = S + OFF_PRE;
    float* EXP  = S + OFF_EXP;
    float* A0IN = S + OFF_A0IN;
    float* C0   = S + OFF_C0;
    float* HB   = S + OFF_P;
    float* X1   = S + OFF_X1;
    float* G1   = S + OFF_G1;
    float* OUT2 = S + OFF_OUT2;
    float* PROJ = S + OFF_PROJ;
    float* HE   = S + OFF_HE;

    cudaFuncSetAttribute(rnn_layer_kernel,
                         cudaFuncAttributeMaxDynamicSharedMemorySize, RNN_SMEM_BYTES);

    // 1) expand
    gemm(x, W_exp, b_exp, PRE, 32, 1024, 512);
    ln_relu_kernel<<<32, 256>>>(PRE, g1, be1, EXP, 1024);

    // 2) layer-0 gate factors
    concat_kernel<<<640, 256>>>(EXP, pos, A0IN);
    gemm(A0IN, Wih0, nullptr, C0, 160, 2048, 1024);

    // 3) layer-0 recurrence (persistent)
    pack_h0_kernel<<<256, 256>>>(EXP, HB);
    rnn_layer_kernel<<<NB, 256, RNN_SMEM_BYTES>>>(Whh0, C0, bih0, bhh0, HB, X1, 0);

    // 4) layer-1 gates
    gemm(X1, Wih1, nullptr, G1, 4096, 2048, 2048);

    // 5) layer-1 recurrence (persistent)
    pack_h0_kernel<<<256, 256>>>(EXP, HB);
    rnn_layer_kernel<<<NB, 256, RNN_SMEM_BYTES>>>(Whh1, G1, bih1, bhh1, HB, OUT2, 1);

    // 6) projection head
    gemm(OUT2, Wp1, bp1, PROJ, 4096, 512, 2048);
    ln_relu_kernel<<<4096, 256>>>(PROJ, g2, be2, HE, 512);

    // 7) logits
    gemm(HE, Wp2, bp2, out, 4096, 32000, 512);
}

// round 5
// speedup vs baseline: 2.4548x; 1.3397x over previous
#include <cuda_runtime.h>

#define T_LEN 128
#define NB 128          // persistent RNN blocks

// ---------------- scratch layout (floats) ----------------
#define OFF_PRE   0                                   // [32][1024]
#define OFF_EXP   (OFF_PRE  + 32*1024)                // [32][1024] expanded (=h0)
#define OFF_A0IN  (OFF_EXP  + 32*1024)                // [160][1024]
#define OFF_C0    (OFF_A0IN + 160*1024)               // [160][2048]
#define OFF_P     (OFF_C0   + 160*2048)               // h exchange: 2 sets x [2][16][2048]
#define OFF_X1    (OFF_P    + 2*4*2*32*1024)          // [4096][2048] rows t*32+b
#define OFF_G1    (OFF_X1   + 4096*2048)              // [4096][2048]
#define OFF_OUT2  (OFF_G1   + 4096*2048)              // [4096][2048] rows b*128+t
#define OFF_PROJ  (OFF_OUT2 + 4096*2048)              // [4096][512]
#define OFF_HE    (OFF_PROJ + 4096*512)               // [4096][512]
#define OFF_WIH1T (OFF_HE   + 4096*512)               // [2][2048][2048] tf32 bits
#define OFF_WP1T  (OFF_WIH1T + 2*2048*2048)           // [512][2048]
#define OFF_WP2T  (OFF_WP1T  + 512*2048)              // [32000][512]
#define SCRATCH_TOTAL (OFF_WP2T + 32000*512)

__device__ float g_scratch[SCRATCH_TOTAL];
__device__ unsigned g_bar_count;
__device__ unsigned g_bar_sense;

// ---------------- tf32 helpers ----------------
__device__ __forceinline__ unsigned f2tf32(float f) {
    unsigned u;
    asm("cvt.rna.tf32.f32 %0, %1;" : "=r"(u) : "f"(f));
    return u;
}

__device__ __forceinline__ void mma_tf32(float c[4], const unsigned a[4], const unsigned b[2]) {
    asm volatile(
        "mma.sync.aligned.m16n8k8.row.col.f32.tf32.tf32.f32 "
        "{%0,%1,%2,%3}, {%4,%5,%6,%7}, {%8,%9}, {%0,%1,%2,%3};"
        : "+f"(c[0]), "+f"(c[1]), "+f"(c[2]), "+f"(c[3])
        : "r"(a[0]), "r"(a[1]), "r"(a[2]), "r"(a[3]), "r"(b[0]), "r"(b[1]));
}

__device__ __forceinline__ void cp16(void* smem_dst, const void* gsrc) {
    unsigned s = (unsigned)__cvta_generic_to_shared(smem_dst);
    asm volatile("cp.async.cg.shared.global [%0], [%1], 16;" :: "r"(s), "l"(gsrc));
}
#define CP_COMMIT() asm volatile("cp.async.commit_group;")
#define CP_WAIT1()  asm volatile("cp.async.wait_group 1;" ::: "memory")

// ---------------- weight pre-round to tf32 bits ----------------
__global__ __launch_bounds__(256) void round_tf32_kernel(
    const float* __restrict__ in, float* __restrict__ out, int n4)
{
    for (int i = blockIdx.x * 256 + threadIdx.x; i < n4; i += gridDim.x * 256) {
        float4 v = ((const float4*)in)[i];
        v.x = __uint_as_float(f2tf32(v.x));
        v.y = __uint_as_float(f2tf32(v.y));
        v.z = __uint_as_float(f2tf32(v.z));
        v.w = __uint_as_float(f2tf32(v.w));
        ((float4*)out)[i] = v;
    }
}

// ---------------- pipelined tf32 GEMM: C[M,N] = A[M,K] @ B[N,K]^T (+bias) --------
// 128x256x16 tile, 512 threads (16 warps @ 32x64), 3-stage cp.async pipeline.
// Inputs must already be tf32-rounded bit patterns. N%256==0, K%16==0, M%128==0.
#define PA 20
#define STG_A (128*PA)
#define STG_B (256*PA)
#define STG   (STG_A + STG_B)
#define PIPE_SMEM_BYTES (3 * STG * 4)

__global__ __launch_bounds__(512, 1) void gemm_pipe_kernel(
    const float* __restrict__ A, const float* __restrict__ B,
    const float* __restrict__ bias, float* __restrict__ C,
    int M, int N, int K)
{
    extern __shared__ float smp[];
    const int tid = threadIdx.x;
    const int warp = tid >> 5;
    const int lane = tid & 31;
    const int wm = warp & 3;          // 4 m-quarters (32 rows)
    const int wn = warp >> 2;         // 4 n-quarters (64 cols)
    const int gid = lane >> 2;
    const int tig = lane & 3;

    const int mblk = blockIdx.y * 128;
    const int nblk = blockIdx.x * 256;

    // loader mapping: A unit (m = tid>>2, u = tid&3); B units n = tid>>2, +128
    const int am = tid >> 2, au = tid & 3;
    int arow = mblk + am; if (arow >= M) arow = M - 1;
    const float* Ag  = A + (size_t)arow * K + au * 4;
    const float* Bg0 = B + (size_t)(nblk + am) * K + au * 4;
    const float* Bg1 = B + (size_t)(nblk + am + 128) * K + au * 4;
    const unsigned sA  = am * PA + au * 4;
    const unsigned sB0 = STG_A + am * PA + au * 4;
    const unsigned sB1 = STG_A + (am + 128) * PA + au * 4;

    float acc[2][8][4];
#pragma unroll
    for (int i = 0; i < 2; i++)
#pragma unroll
        for (int j = 0; j < 8; j++)
#pragma unroll
            for (int r = 0; r < 4; r++) acc[i][j][r] = 0.f;

    const int KT = K / 16;

    // prologue: stages 0,1
#pragma unroll
    for (int st = 0; st < 2; st++) {
        float* buf = smp + st * STG;
        cp16(buf + sA,  Ag  + st * 16);
        cp16(buf + sB0, Bg0 + st * 16);
        cp16(buf + sB1, Bg1 + st * 16);
        CP_COMMIT();
    }

    for (int i = 0; i < KT; i++) {
        CP_WAIT1();
        __syncthreads();

        if (i + 2 < KT) {
            float* buf = smp + ((i + 2) % 3) * STG;
            cp16(buf + sA,  Ag  + (i + 2) * 16);
            cp16(buf + sB0, Bg0 + (i + 2) * 16);
            cp16(buf + sB1, Bg1 + (i + 2) * 16);
        }
        CP_COMMIT();

        const float* As = smp + (i % 3) * STG;
        const float* Bs = As + STG_A;
#pragma unroll
        for (int ks = 0; ks < 2; ks++) {
            const int kb = ks * 8;
            unsigned afr[2][4], bfr[8][2];
#pragma unroll
            for (int mf = 0; mf < 2; mf++) {
                const int mr = wm * 32 + mf * 16 + gid;
                afr[mf][0] = __float_as_uint(As[mr * PA + kb + tig]);
                afr[mf][1] = __float_as_uint(As[(mr + 8) * PA + kb + tig]);
                afr[mf][2] = __float_as_uint(As[mr * PA + kb + tig + 4]);
                afr[mf][3] = __float_as_uint(As[(mr + 8) * PA + kb + tig + 4]);
            }
#pragma unroll
            for (int nf = 0; nf < 8; nf++) {
                const int nc = wn * 64 + nf * 8 + gid;
                bfr[nf][0] = __float_as_uint(Bs[nc * PA + kb + tig]);
                bfr[nf][1] = __float_as_uint(Bs[nc * PA + kb + tig + 4]);
            }
#pragma unroll
            for (int mf = 0; mf < 2; mf++)
#pragma unroll
                for (int nf = 0; nf < 8; nf++)
                    mma_tf32(acc[mf][nf], afr[mf], bfr[nf]);
        }
    }

    // epilogue
#pragma unroll
    for (int nf = 0; nf < 8; nf++) {
        const int col = nblk + wn * 64 + nf * 8 + tig * 2;
        const float b0 = bias ? bias[col] : 0.f;
        const float b1 = bias ? bias[col + 1] : 0.f;
#pragma unroll
        for (int mf = 0; mf < 2; mf++) {
            const int row = mblk + wm * 32 + mf * 16 + gid;
            if (row < M) {
                float2 v = make_float2(acc[mf][nf][0] + b0, acc[mf][nf][1] + b1);
                *(float2*)(C + (size_t)row * N + col) = v;
            }
            if (row + 8 < M) {
                float2 v = make_float2(acc[mf][nf][2] + b0, acc[mf][nf][3] + b1);
                *(float2*)(C + (size_t)(row + 8) * N + col) = v;
            }
        }
    }
}

// ---------------- small tf32 GEMM (round-3 version): C = A @ B^T (+bias) ----------
#define SPITCH 136
__global__ __launch_bounds__(256, 2) void gemm_tf32_kernel(
    const float* __restrict__ A, const float* __restrict__ B,
    const float* __restrict__ bias, float* __restrict__ C,
    int M, int N, int K)
{
    __shared__ unsigned As[16][SPITCH];
    __shared__ unsigned Bs[16][SPITCH];

    const int tid  = threadIdx.x;
    const int warp = tid >> 5;
    const int lane = tid & 31;
    const int wm = warp & 1;
    const int wn = warp >> 1;
    const int gid = lane >> 2;
    const int tig = lane & 3;

    const int mblk = blockIdx.y * 128;
    const int nblk = blockIdx.x * 128;

    const int lr = tid >> 1;
    const int kc = (tid & 1) * 8;
    const int rowA = mblk + lr;
    const bool aval = rowA < M;
    const float* Ap = A + (size_t)(aval ? rowA : 0) * K + kc;
    const float* Bp = B + (size_t)(nblk + lr) * K + kc;

    float acc[4][4][4];
#pragma unroll
    for (int i = 0; i < 4; i++)
#pragma unroll
        for (int j = 0; j < 4; j++)
#pragma unroll
            for (int r = 0; r < 4; r++) acc[i][j][r] = 0.f;

    float4 av0 = aval ? *(const float4*)Ap : make_float4(0,0,0,0);
    float4 av1 = aval ? *(const float4*)(Ap + 4) : make_float4(0,0,0,0);
    float4 bv0 = *(const float4*)Bp;
    float4 bv1 = *(const float4*)(Bp + 4);
    Ap += 16; Bp += 16;

    for (int k0 = 0; k0 < K; k0 += 16) {
        As[kc + 0][lr] = f2tf32(av0.x); As[kc + 1][lr] = f2tf32(av0.y);
        As[kc + 2][lr] = f2tf32(av0.z); As[kc + 3][lr] = f2tf32(av0.w);
        As[kc + 4][lr] = f2tf32(av1.x); As[kc + 5][lr] = f2tf32(av1.y);
        As[kc + 6][lr] = f2tf32(av1.z); As[kc + 7][lr] = f2tf32(av1.w);
        Bs[kc + 0][lr] = f2tf32(bv0.x); Bs[kc + 1][lr] = f2tf32(bv0.y);
        Bs[kc + 2][lr] = f2tf32(bv0.z); Bs[kc + 3][lr] = f2tf32(bv0.w);
        Bs[kc + 4][lr] = f2tf32(bv1.x); Bs[kc + 5][lr] = f2tf32(bv1.y);
        Bs[kc + 6][lr] = f2tf32(bv1.z); Bs[kc + 7][lr] = f2tf32(bv1.w);
        __syncthreads();

        if (k0 + 16 < K) {
            av0 = aval ? *(const float4*)Ap : make_float4(0,0,0,0);
            av1 = aval ? *(const float4*)(Ap + 4) : make_float4(0,0,0,0);
            bv0 = *(const float4*)Bp;
            bv1 = *(const float4*)(Bp + 4);
            Ap += 16; Bp += 16;
        }

#pragma unroll
        for (int ks = 0; ks < 2; ks++) {
            const int kb = ks * 8;
            unsigned afr[4][4], bfr[4][2];
#pragma unroll
            for (int mt = 0; mt < 4; mt++) {
                const int mr = wm * 64 + mt * 16 + gid;
                afr[mt][0] = As[kb + tig][mr];
                afr[mt][1] = As[kb + tig][mr + 8];
                afr[mt][2] = As[kb + tig + 4][mr];
                afr[mt][3] = As[kb + tig + 4][mr + 8];
            }
#pragma unroll
            for (int nt = 0; nt < 4; nt++) {
                const int nc = wn * 32 + nt * 8 + gid;
                bfr[nt][0] = Bs[kb + tig][nc];
                bfr[nt][1] = Bs[kb + tig + 4][nc];
            }
#pragma unroll
            for (int mt = 0; mt < 4; mt++)
#pragma unroll
                for (int nt = 0; nt < 4; nt++)
                    mma_tf32(acc[mt][nt], afr[mt], bfr[nt]);
        }
        __syncthreads();
    }

#pragma unroll
    for (int nt = 0; nt < 4; nt++) {
        const int col = nblk + wn * 32 + nt * 8 + tig * 2;
        const float b0 = bias ? bias[col] : 0.f;
        const float b1 = bias ? bias[col + 1] : 0.f;
#pragma unroll
        for (int mt = 0; mt < 4; mt++) {
            const int row = mblk + wm * 64 + mt * 16 + gid;
            if (row < M) {
                float2 v = make_float2(acc[mt][nt][0] + b0, acc[mt][nt][1] + b1);
                *(float2*)(C + (size_t)row * N + col) = v;
            }
            if (row + 8 < M) {
                float2 v = make_float2(acc[mt][nt][2] + b0, acc[mt][nt][3] + b1);
                *(float2*)(C + (size_t)(row + 8) * N + col) = v;
            }
        }
    }
}

// ---------------- LayerNorm + ReLU (optional tf32 rounding of output) -------------
__global__ __launch_bounds__(256) void ln_relu_kernel(
    const float* __restrict__ in, const float* __restrict__ g,
    const float* __restrict__ be, float* __restrict__ out, int C, int round_out)
{
    __shared__ float red[256];
    const int row = blockIdx.x;
    const int tid = threadIdx.x;
    const float* rp = in + (size_t)row * C;
    float s = 0.f, sq = 0.f;
    for (int c = tid; c < C; c += 256) { float v = rp[c]; s += v; sq += v * v; }
    red[tid] = s; __syncthreads();
    for (int o = 128; o > 0; o >>= 1) { if (tid < o) red[tid] += red[tid + o]; __syncthreads(); }
    float mean = red[0] / (float)C;
    __syncthreads();
    red[tid] = sq; __syncthreads();
    for (int o = 128; o > 0; o >>= 1) { if (tid < o) red[tid] += red[tid + o]; __syncthreads(); }
    float var = red[0] / (float)C - mean * mean;
    float rs = rsqrtf(var + 1e-5f);
    float* op = out + (size_t)row * C;
    for (int c = tid; c < C; c += 256) {
        float v = (rp[c] - mean) * rs * g[c] + be[c];
        v = fmaxf(v, 0.f);
        op[c] = round_out ? __uint_as_float(f2tf32(v)) : v;
    }
}

// ---------------- concat [expanded(32); pos(128)] ----------------
__global__ __launch_bounds__(256) void concat_kernel(
    const float* __restrict__ e, const float* __restrict__ pos, float* __restrict__ o)
{
    int i = blockIdx.x * 256 + threadIdx.x;
    o[i] = (i < 32 * 1024) ? e[i] : pos[i - 32 * 1024];
}

// ---------------- pack h0 into exchange buffer set 0 ----------------
__global__ __launch_bounds__(256) void pack_h0_kernel(
    const float* __restrict__ EXP, float* __restrict__ HB)
{
    int i = blockIdx.x * 256 + threadIdx.x;
    const int bp = i >> 11;
    const int j  = i & 2047;
    const int k  = j >> 1;
    const int c  = j & 1;
    const float v = EXP[(2 * bp + c) * 1024 + k];
    HB[i] = v;
    HB[32768 + i] = v;
}

// ---------------- persistent RNN layer ----------------
#define W_PITCH 1028
#define H_PITCH 2052
#define WSH_OFF 0
#define HSH_OFF (16 * W_PITCH)
#define RED_OFF (HSH_OFF + 16 * H_PITCH)
#define RNN_SMEM_FLOATS (RED_OFF + 512 * 12)
#define RNN_SMEM_BYTES  (RNN_SMEM_FLOATS * 4)

__device__ __forceinline__ unsigned ld_acquire_u32(unsigned* p) {
    unsigned v;
    asm volatile("ld.acquire.gpu.global.u32 %0, [%1];" : "=r"(v) : "l"(p) : "memory");
    return v;
}
__device__ __forceinline__ unsigned atom_add_acqrel(unsigned* p, unsigned v) {
    unsigned o;
    asm volatile("atom.acq_rel.gpu.global.add.u32 %0, [%1], %2;" : "=r"(o) : "l"(p), "r"(v) : "memory");
    return o;
}
__device__ __forceinline__ void st_relaxed_u32(unsigned* p, unsigned v) {
    asm volatile("st.relaxed.gpu.global.u32 [%0], %1;" :: "l"(p), "r"(v) : "memory");
}
__device__ __forceinline__ void st_release_u32(unsigned* p, unsigned v) {
    asm volatile("st.release.gpu.global.u32 [%0], %1;" :: "l"(p), "r"(v) : "memory");
}

__global__ __launch_bounds__(256, 1) void rnn_layer_kernel(
    const float* __restrict__ Whh, const float* __restrict__ gate,
    const float* __restrict__ bih, const float* __restrict__ bhh,
    float* __restrict__ HB, float* __restrict__ Y, int layer)
{
    extern __shared__ float sm[];
    float* Wsh  = sm + WSH_OFF;
    float* Hsh  = sm + HSH_OFF;
    float* Red  = sm + RED_OFF;

    const int tid = threadIdx.x;
    const int bid = blockIdx.x;
    const int d = bid >> 6;
    const int n0 = (bid & 63) * 16;

    const int kq = tid >> 5;
    const int lane = tid & 31;
    const int bq = lane & 7;
    const int ng = lane >> 3;

    for (int it = 0; it < 16; it++) {
        const int idx = tid + it * 256;
        const int n = idx >> 8, k4 = idx & 255;
        float4 w = *(const float4*)&Whh[(size_t)(d * 1024 + n0 + n) * 1024 + k4 * 4];
        *(float4*)&Wsh[n * W_PITCH + k4 * 4] = w;
    }

    unsigned local_sense = 0;

    for (int s = 1; s <= T_LEN; s++) {
        const float* src = HB + ((s - 1) & 1) * 65536 + d * 32768;
        __syncthreads();
#pragma unroll
        for (int it = 0; it < 32; it++) {
            const int idx = (tid + it * 256) * 4;
            const int bp = idx >> 11, rem = idx & 2047;
            float4 v = *(const float4*)&src[idx];
            *(float4*)&Hsh[bp * H_PITCH + rem] = v;
        }
        __syncthreads();

        float acc[4][4];
#pragma unroll
        for (int i = 0; i < 4; i++)
#pragma unroll
            for (int j = 0; j < 4; j++) acc[i][j] = 0.f;

        const float* h0p = &Hsh[(2 * bq) * H_PITCH];
        const float* h1p = &Hsh[(2 * bq + 1) * H_PITCH];
        const float* wp  = &Wsh[(ng * 4) * W_PITCH];

        for (int k = kq * 128; k < kq * 128 + 128; k += 4) {
            float4 hA0 = *(const float4*)&h0p[2 * k];
            float4 hA1 = *(const float4*)&h0p[2 * k + 4];
            float4 hB0 = *(const float4*)&h1p[2 * k];
            float4 hB1 = *(const float4*)&h1p[2 * k + 4];
            float hv[4][4];
            hv[0][0] = hA0.x; hv[0][1] = hA0.z; hv[0][2] = hA1.x; hv[0][3] = hA1.z;
            hv[1][0] = hA0.y; hv[1][1] = hA0.w; hv[1][2] = hA1.y; hv[1][3] = hA1.w;
            hv[2][0] = hB0.x; hv[2][1] = hB0.z; hv[2][2] = hB1.x; hv[2][3] = hB1.z;
            hv[3][0] = hB0.y; hv[3][1] = hB0.w; hv[3][2] = hB1.y; hv[3][3] = hB1.w;
            float wv[4][4];
#pragma unroll
            for (int j = 0; j < 4; j++) {
                float4 w = *(const float4*)&wp[j * W_PITCH + k];
                wv[j][0] = w.x; wv[j][1] = w.y; wv[j][2] = w.z; wv[j][3] = w.w;
            }
#pragma unroll
            for (int kk = 0; kk < 4; kk++)
#pragma unroll
                for (int bi = 0; bi < 4; bi++)
#pragma unroll
                    for (int ni = 0; ni < 4; ni++)
                        acc[bi][ni] += hv[bi][kk] * wv[ni][kk];
        }

        __syncthreads();
#pragma unroll
        for (int bi = 0; bi < 4; bi++)
#pragma unroll
            for (int ni = 0; ni < 4; ni++) {
                const int o = (bq * 4 + bi) * 16 + ng * 4 + ni;
                Red[o * 12 + kq] = acc[bi][ni];
            }
        __syncthreads();

        const int t = d ? (T_LEN - s) : (s - 1);
        float* dst = HB + (s & 1) * 65536 + d * 32768;
#pragma unroll
        for (int oo = 0; oo < 2; oo++) {
            const int o = tid + oo * 256;
            const float* rp = &Red[o * 12];
            float4 r0 = *(const float4*)rp;
            float4 r1 = *(const float4*)(rp + 4);
            float v = ((r0.x + r0.y) + (r0.z + r0.w)) + ((r1.x + r1.y) + (r1.z + r1.w));
            const int b = o >> 4, n = o & 15;
            const int ncol = n0 + n;
            const int col = d * 1024 + ncol;
            const float bb = bih[col] + bhh[col];
            float gv;
            if (layer == 0)
                gv = gate[(size_t)b * 2048 + col] + gate[(size_t)(32 + t) * 2048 + col];
            else
                gv = gate[(size_t)(t * 32 + b) * 2048 + col];
            const float hnew = fmaxf(v + gv + bb, 0.f);
            dst[(b >> 1) * 2048 + 2 * ncol + (b & 1)] = hnew;
            const int row = layer ? (b * 128 + t) : (t * 32 + b);
            // Y feeds a pipelined GEMM (no in-kernel cvt) -> emit tf32-rounded bits
            Y[(size_t)row * 2048 + col] = __uint_as_float(f2tf32(hnew));
        }

        __syncthreads();
        if (tid == 0) {
            const unsigned target = local_sense ^ 1;
            unsigned old = atom_add_acqrel(&g_bar_count, 1);
            if (old == NB - 1) {
                st_relaxed_u32(&g_bar_count, 0);
                st_release_u32(&g_bar_sense, target);
            } else {
                while (ld_acquire_u32(&g_bar_sense) != target) { }
            }
        }
        local_sense ^= 1;
        __syncthreads();
    }
}

// ---------------- launch helpers ----------------
static inline void gemm_small(const float* A, const float* B, const float* bias,
                              float* C, int M, int N, int K)
{
    dim3 grid(N / 128, (M + 127) / 128);
    gemm_tf32_kernel<<<grid, 256>>>(A, B, bias, C, M, N, K);
}

static inline void gemm_big(const float* A, const float* B, const float* bias,
                            float* C, int M, int N, int K)
{
    dim3 grid(N / 256, M / 128);
    gemm_pipe_kernel<<<grid, 512, PIPE_SMEM_BYTES>>>(A, B, bias, C, M, N, K);
}

extern "C" void kernel_launch(void* const* d_in, const int* in_sizes, int n_in,
                              void* d_out, int out_size)
{
    (void)in_sizes; (void)n_in; (void)out_size;
    const float* x     = (const float*)d_in[0];
    const float* W_exp = (const float*)d_in[1];
    const float* b_exp = (const float*)d_in[2];
    const float* g1    = (const float*)d_in[3];
    const float* be1   = (const float*)d_in[4];
    const float* pos   = (const float*)d_in[5];
    const float* Wih0  = (const float*)d_in[6];
    const float* Whh0  = (const float*)d_in[7];
    const float* bih0  = (const float*)d_in[8];
    const float* bhh0  = (const float*)d_in[9];
    const float* Wih1  = (const float*)d_in[10];
    const float* Whh1  = (const float*)d_in[11];
    const float* bih1  = (const float*)d_in[12];
    const float* bhh1  = (const float*)d_in[13];
    const float* Wp1   = (const float*)d_in[14];
    const float* bp1   = (const float*)d_in[15];
    const float* g2    = (const float*)d_in[16];
    const float* be2   = (const float*)d_in[17];
    const float* Wp2   = (const float*)d_in[18];
    const float* bp2   = (const float*)d_in[19];
    float* out = (float*)d_out;

    float* S = nullptr;
    cudaGetSymbolAddress((void**)&S, g_scratch);

    float* PRE   = S + OFF_PRE;
    float* EXP   = S + OFF_EXP;
    float* A0IN  = S + OFF_A0IN;
    float* C0    = S + OFF_C0;
    float* HB    = S + OFF_P;
    float* X1    = S + OFF_X1;
    float* G1    = S + OFF_G1;
    float* OUT2  = S + OFF_OUT2;
    float* PROJ  = S + OFF_PROJ;
    float* HE    = S + OFF_HE;
    float* WIH1T = S + OFF_WIH1T;
    float* WP1T  = S + OFF_WP1T;
    float* WP2T  = S + OFF_WP2T;

    cudaFuncSetAttribute(rnn_layer_kernel,
                         cudaFuncAttributeMaxDynamicSharedMemorySize, RNN_SMEM_BYTES);
    cudaFuncSetAttribute(gemm_pipe_kernel,
                         cudaFuncAttributeMaxDynamicSharedMemorySize, PIPE_SMEM_BYTES);

    // 0) pre-round weights for pipelined GEMMs
    round_tf32_kernel<<<512, 256>>>(Wih1, WIH1T, 2 * 2048 * 2048 / 4);
    round_tf32_kernel<<<512, 256>>>(Wp1,  WP1T,  512 * 2048 / 4);
    round_tf32_kernel<<<512, 256>>>(Wp2,  WP2T,  32000 * 512 / 4);

    // 1) expand
    gemm_small(x, W_exp, b_exp, PRE, 32, 1024, 512);
    ln_relu_kernel<<<32, 256>>>(PRE, g1, be1, EXP, 1024, 0);

    // 2) layer-0 gate factors
    concat_kernel<<<640, 256>>>(EXP, pos, A0IN);
    gemm_small(A0IN, Wih0, nullptr, C0, 160, 2048, 1024);

    // 3) layer-0 recurrence (persistent)
    pack_h0_kernel<<<256, 256>>>(EXP, HB);
    rnn_layer_kernel<<<NB, 256, RNN_SMEM_BYTES>>>(Whh0, C0, bih0, bhh0, HB, X1, 0);

    // 4) layer-1 gates (pipelined)
    gemm_big(X1, WIH1T, nullptr, G1, 4096, 2048, 2048);

    // 5) layer-1 recurrence (persistent)
    pack_h0_kernel<<<256, 256>>>(EXP, HB);
    rnn_layer_kernel<<<NB, 256, RNN_SMEM_BYTES>>>(Whh1, G1, bih1, bhh1, HB, OUT2, 1);

    // 6) projection head (pipelined)
    gemm_big(OUT2, WP1T, bp1, PROJ, 4096, 512, 2048);
    ln_relu_kernel<<<4096, 256>>>(PROJ, g2, be2, HE, 512, 1);

    // 7) logits (pipelined)
    gemm_big(HE, WP2T, bp2, out, 4096, 32000, 512);
}

// round 7
// speedup vs baseline: 2.8561x; 1.1635x over previous
#include <cuda_runtime.h>
#include <cuda.h>
#include <cstdint>

#define T_LEN 128
#define NB 128          // persistent RNN blocks

// ---------------- scratch layout (floats) ----------------
#define OFF_PRE   0                                   // [32][1024]
#define OFF_EXP   (OFF_PRE  + 32*1024)                // [32][1024] expanded (=h0)
#define OFF_A0IN  (OFF_EXP  + 32*1024)                // [160][1024]
#define OFF_C0    (OFF_A0IN + 160*1024)               // [160][2048]
#define OFF_P     (OFF_C0   + 160*2048)               // h exchange: 2 sets x [2][16][2048]
#define OFF_X1    (OFF_P    + 2*4*2*32*1024)          // [4096][2048] rows t*32+b
#define OFF_G1    (OFF_X1   + 4096*2048)              // [4096][2048]
#define OFF_OUT2  (OFF_G1   + 4096*2048)              // [4096][2048] rows b*128+t
#define OFF_PROJ  (OFF_OUT2 + 4096*2048)              // [4096][512]
#define OFF_HE    (OFF_PROJ + 4096*512)               // [4096][512]
#define OFF_WIH1T (OFF_HE   + 4096*512)               // [2048][2048] tf32 bits
#define OFF_WP1T  (OFF_WIH1T + 2048*2048)             // [512][2048]
#define OFF_WP2T  (OFF_WP1T  + 512*2048)              // [32000][512]
#define SCRATCH_TOTAL (OFF_WP2T + 32000*512)

__device__ __align__(1024) float g_scratch[SCRATCH_TOTAL];
__device__ unsigned g_bar_count;
__device__ unsigned g_bar_sense;

// ---------------- tf32 helpers ----------------
__device__ __forceinline__ unsigned f2tf32(float f) {
    unsigned u;
    asm("cvt.rna.tf32.f32 %0, %1;" : "=r"(u) : "f"(f));
    return u;
}

__device__ __forceinline__ void mma_tf32(float c[4], const unsigned a[4], const unsigned b[2]) {
    asm volatile(
        "mma.sync.aligned.m16n8k8.row.col.f32.tf32.tf32.f32 "
        "{%0,%1,%2,%3}, {%4,%5,%6,%7}, {%8,%9}, {%0,%1,%2,%3};"
        : "+f"(c[0]), "+f"(c[1]), "+f"(c[2]), "+f"(c[3])
        : "r"(a[0]), "r"(a[1]), "r"(a[2]), "r"(a[3]), "r"(b[0]), "r"(b[1]));
}

// ---------------- weight pre-round to tf32 bits ----------------
__global__ __launch_bounds__(256) void round_tf32_kernel(
    const float* __restrict__ in, float* __restrict__ out, int n4)
{
    for (int i = blockIdx.x * 256 + threadIdx.x; i < n4; i += gridDim.x * 256) {
        float4 v = ((const float4*)in)[i];
        v.x = __uint_as_float(f2tf32(v.x));
        v.y = __uint_as_float(f2tf32(v.y));
        v.z = __uint_as_float(f2tf32(v.z));
        v.w = __uint_as_float(f2tf32(v.w));
        ((float4*)out)[i] = v;
    }
}

// =================== TMA-fed tf32 GEMM (legacy mma.sync compute) ===================
// C[M,N] = A[M,K] @ B[N,K]^T (+bias). CTA tile 128x256, K-chunk 32, 4-stage TMA ring.
// M%128==0, N%256==0, K%32==0. Inputs must be tf32-rounded bit patterns.

#define TG_STAGES 4
#define TG_STAGE_BYTES 49152                   // A 128*128B + B 256*128B
#define TG_SMEM_BYTES  (1024 + TG_STAGES * TG_STAGE_BYTES)

__device__ __forceinline__ uint32_t smem_u32(const void* p) {
    return (uint32_t)__cvta_generic_to_shared((void*)p);
}
__device__ __forceinline__ void tma2d(uint32_t sdst, const CUtensorMap* tm,
                                      int x, int y, uint32_t bar) {
    asm volatile(
        "cp.async.bulk.tensor.2d.shared::cta.global.tile.mbarrier::complete_tx::bytes "
        "[%0], [%1, {%2, %3}], [%4];"
        :: "r"(sdst), "l"(tm), "r"(x), "r"(y), "r"(bar) : "memory");
}
#define MBAR_INIT(a, c) \
    asm volatile("mbarrier.init.shared.b64 [%0], %1;" :: "r"(a), "r"(c) : "memory")
#define MBAR_EXPECT_TX(a, b) \
    asm volatile("mbarrier.arrive.expect_tx.shared.b64 _, [%0], %1;" :: "r"(a), "r"(b) : "memory")
#define MBAR_ARRIVE(a) \
    asm volatile("mbarrier.arrive.shared.b64 _, [%0];" :: "r"(a) : "memory")
#define MBAR_WAIT(a, ph) do { \
    uint32_t _d_; \
    asm volatile("{\n\t.reg .pred p;\n\tmbarrier.try_wait.parity.acquire.cta.shared::cta.b64 p, [%1], %2;\n\tselp.b32 %0, 1, 0, p;\n\t}" \
        : "=r"(_d_) : "r"(a), "r"(ph) : "memory"); \
    while (!_d_) { \
        asm volatile("{\n\t.reg .pred p;\n\tmbarrier.try_wait.parity.acquire.cta.shared::cta.b64 p, [%1], %2, 0x989680;\n\tselp.b32 %0, 1, 0, p;\n\t}" \
            : "=r"(_d_) : "r"(a), "r"(ph) : "memory"); \
    } \
} while (0)

__global__ __launch_bounds__(512, 1) void gemm_tma_kernel(
    const __grid_constant__ CUtensorMap tmA,
    const __grid_constant__ CUtensorMap tmB,
    const float* __restrict__ bias, float* __restrict__ C,
    int N, int K)
{
    extern __shared__ char dsm[];
    __shared__ __align__(8) unsigned long long bars[8];  // full[4], empty[4]

    const int tid  = threadIdx.x;
    const int warp = tid >> 5;
    const int lane = tid & 31;
    const int wm   = warp & 3;        // 4 m-strips of 32 rows
    const int wn   = warp >> 2;       // 4 n-strips of 64 cols
    const int gid  = lane >> 2;       // 0..7
    const int tig  = lane & 3;        // 0..3
    const int mblk = blockIdx.y * 128;
    const int nblk = blockIdx.x * 256;
    const int KT   = K / 32;

    const uint32_t raw   = smem_u32(dsm);
    const uint32_t sbase = (raw + 1023) & ~1023u;
    char* tile0 = dsm + (sbase - raw);
    const uint32_t barb = smem_u32(bars);

    if (tid == 0) {
        for (int i = 0; i < 4; i++) MBAR_INIT(barb + i * 8, 1);        // full: tx-based
        for (int i = 4; i < 8; i++) MBAR_INIT(barb + i * 8, 16);       // empty: 16 warps
    }
    __syncthreads();

    // prologue: fill up to 4 stages
    if (tid == 0) {
        const int pre = KT < TG_STAGES ? KT : TG_STAGES;
        for (int st = 0; st < pre; st++) {
            const uint32_t full = barb + st * 8;
            MBAR_EXPECT_TX(full, TG_STAGE_BYTES);
            const uint32_t sa = sbase + st * TG_STAGE_BYTES;
            tma2d(sa,         &tmA, st * 32, mblk, full);
            tma2d(sa + 16384, &tmB, st * 32, nblk, full);
        }
    }

    float acc[2][8][4];
#pragma unroll
    for (int i = 0; i < 2; i++)
#pragma unroll
        for (int j = 0; j < 8; j++)
#pragma unroll
            for (int r = 0; r < 4; r++) acc[i][j][r] = 0.f;

    const uint32_t xorv = (uint32_t)gid << 4;   // swizzle XOR (row&7 == gid for our rows)

    for (int kt = 0; kt < KT; kt++) {
        const int st = kt & 3;
        const uint32_t ph = (kt >> 2) & 1;
        MBAR_WAIT(barb + st * 8, ph);

        const char* As = tile0 + st * TG_STAGE_BYTES;
        const char* Bs = As + 16384;

#pragma unroll
        for (int ks = 0; ks < 4; ks++) {
            const uint32_t c4a = (uint32_t)(ks * 32 + tig * 4) ^ xorv;
            const uint32_t c4b = (uint32_t)(ks * 32 + tig * 4 + 16) ^ xorv;
            unsigned afr[2][4], bfr[8][2];
#pragma unroll
            for (int mf = 0; mf < 2; mf++) {
                const int r0 = wm * 32 + mf * 16 + gid;
                afr[mf][0] = *(const unsigned*)(As + r0 * 128 + c4a);
                afr[mf][1] = *(const unsigned*)(As + (r0 + 8) * 128 + c4a);
                afr[mf][2] = *(const unsigned*)(As + r0 * 128 + c4b);
                afr[mf][3] = *(const unsigned*)(As + (r0 + 8) * 128 + c4b);
            }
#pragma unroll
            for (int nf = 0; nf < 8; nf++) {
                const int nc = wn * 64 + nf * 8 + gid;
                bfr[nf][0] = *(const unsigned*)(Bs + nc * 128 + c4a);
                bfr[nf][1] = *(const unsigned*)(Bs + nc * 128 + c4b);
            }
#pragma unroll
            for (int mf = 0; mf < 2; mf++)
#pragma unroll
                for (int nf = 0; nf < 8; nf++)
                    mma_tf32(acc[mf][nf], afr[mf], bfr[nf]);
        }

        __syncwarp();
        if (lane == 0) MBAR_ARRIVE(barb + (4 + st) * 8);

        if (tid == 0 && kt + TG_STAGES < KT) {
            MBAR_WAIT(barb + (4 + st) * 8, ph);    // all 16 warps done with this stage
            const uint32_t full = barb + st * 8;
            MBAR_EXPECT_TX(full, TG_STAGE_BYTES);
            const uint32_t sa = sbase + st * TG_STAGE_BYTES;
            tma2d(sa,         &tmA, (kt + TG_STAGES) * 32, mblk, full);
            tma2d(sa + 16384, &tmB, (kt + TG_STAGES) * 32, nblk, full);
        }
    }

    // epilogue
#pragma unroll
    for (int nf = 0; nf < 8; nf++) {
        const int col = nblk + wn * 64 + nf * 8 + tig * 2;
        const float b0 = bias ? bias[col] : 0.f;
        const float b1 = bias ? bias[col + 1] : 0.f;
#pragma unroll
        for (int mf = 0; mf < 2; mf++) {
            const int row = mblk + wm * 32 + mf * 16 + gid;
            {
                float2 v = make_float2(acc[mf][nf][0] + b0, acc[mf][nf][1] + b1);
                *(float2*)(C + (size_t)row * N + col) = v;
            }
            {
                float2 v = make_float2(acc[mf][nf][2] + b0, acc[mf][nf][3] + b1);
                *(float2*)(C + (size_t)(row + 8) * N + col) = v;
            }
        }
    }
}

// ---------------- small tf32 GEMM (legacy mma): C = A @ B^T (+bias) ----------
#define SPITCH 136
__global__ __launch_bounds__(256, 2) void gemm_tf32_kernel(
    const float* __restrict__ A, const float* __restrict__ B,
    const float* __restrict__ bias, float* __restrict__ C,
    int M, int N, int K)
{
    __shared__ unsigned As[16][SPITCH];
    __shared__ unsigned Bs[16][SPITCH];

    const int tid  = threadIdx.x;
    const int warp = tid >> 5;
    const int lane = tid & 31;
    const int wm = warp & 1;
    const int wn = warp >> 1;
    const int gid = lane >> 2;
    const int tig = lane & 3;

    const int mblk = blockIdx.y * 128;
    const int nblk = blockIdx.x * 128;

    const int lr = tid >> 1;
    const int kc = (tid & 1) * 8;
    const int rowA = mblk + lr;
    const bool aval = rowA < M;
    const float* Ap = A + (size_t)(aval ? rowA : 0) * K + kc;
    const float* Bp = B + (size_t)(nblk + lr) * K + kc;

    float acc[4][4][4];
#pragma unroll
    for (int i = 0; i < 4; i++)
#pragma unroll
        for (int j = 0; j < 4; j++)
#pragma unroll
            for (int r = 0; r < 4; r++) acc[i][j][r] = 0.f;

    float4 av0 = aval ? *(const float4*)Ap : make_float4(0,0,0,0);
    float4 av1 = aval ? *(const float4*)(Ap + 4) : make_float4(0,0,0,0);
    float4 bv0 = *(const float4*)Bp;
    float4 bv1 = *(const float4*)(Bp + 4);
    Ap += 16; Bp += 16;

    for (int k0 = 0; k0 < K; k0 += 16) {
        As[kc + 0][lr] = f2tf32(av0.x); As[kc + 1][lr] = f2tf32(av0.y);
        As[kc + 2][lr] = f2tf32(av0.z); As[kc + 3][lr] = f2tf32(av0.w);
        As[kc + 4][lr] = f2tf32(av1.x); As[kc + 5][lr] = f2tf32(av1.y);
        As[kc + 6][lr] = f2tf32(av1.z); As[kc + 7][lr] = f2tf32(av1.w);
        Bs[kc + 0][lr] = f2tf32(bv0.x); Bs[kc + 1][lr] = f2tf32(bv0.y);
        Bs[kc + 2][lr] = f2tf32(bv0.z); Bs[kc + 3][lr] = f2tf32(bv0.w);
        Bs[kc + 4][lr] = f2tf32(bv1.x); Bs[kc + 5][lr] = f2tf32(bv1.y);
        Bs[kc + 6][lr] = f2tf32(bv1.z); Bs[kc + 7][lr] = f2tf32(bv1.w);
        __syncthreads();

        if (k0 + 16 < K) {
            av0 = aval ? *(const float4*)Ap : make_float4(0,0,0,0);
            av1 = aval ? *(const float4*)(Ap + 4) : make_float4(0,0,0,0);
            bv0 = *(const float4*)Bp;
            bv1 = *(const float4*)(Bp + 4);
            Ap += 16; Bp += 16;
        }

#pragma unroll
        for (int ks = 0; ks < 2; ks++) {
            const int kb = ks * 8;
            unsigned afr[4][4], bfr[4][2];
#pragma unroll
            for (int mt = 0; mt < 4; mt++) {
                const int mr = wm * 64 + mt * 16 + gid;
                afr[mt][0] = As[kb + tig][mr];
                afr[mt][1] = As[kb + tig][mr + 8];
                afr[mt][2] = As[kb + tig + 4][mr];
                afr[mt][3] = As[kb + tig + 4][mr + 8];
            }
#pragma unroll
            for (int nt = 0; nt < 4; nt++) {
                const int nc = wn * 32 + nt * 8 + gid;
                bfr[nt][0] = Bs[kb + tig][nc];
                bfr[nt][1] = Bs[kb + tig + 4][nc];
            }
#pragma unroll
            for (int mt = 0; mt < 4; mt++)
#pragma unroll
                for (int nt = 0; nt < 4; nt++)
                    mma_tf32(acc[mt][nt], afr[mt], bfr[nt]);
        }
        __syncthreads();
    }

#pragma unroll
    for (int nt = 0; nt < 4; nt++) {
        const int col = nblk + wn * 32 + nt * 8 + tig * 2;
        const float b0 = bias ? bias[col] : 0.f;
        const float b1 = bias ? bias[col + 1] : 0.f;
#pragma unroll
        for (int mt = 0; mt < 4; mt++) {
            const int row = mblk + wm * 64 + mt * 16 + gid;
            if (row < M) {
                float2 v = make_float2(acc[mt][nt][0] + b0, acc[mt][nt][1] + b1);
                *(float2*)(C + (size_t)row * N + col) = v;
            }
            if (row + 8 < M) {
                float2 v = make_float2(acc[mt][nt][2] + b0, acc[mt][nt][3] + b1);
                *(float2*)(C + (size_t)(row + 8) * N + col) = v;
            }
        }
    }
}

// ---------------- LayerNorm + ReLU (optional tf32 rounding of output) -------------
__global__ __launch_bounds__(256) void ln_relu_kernel(
    const float* __restrict__ in, const float* __restrict__ g,
    const float* __restrict__ be, float* __restrict__ out, int C, int round_out)
{
    __shared__ float red[256];
    const int row = blockIdx.x;
    const int tid = threadIdx.x;
    const float* rp = in + (size_t)row * C;
    float s = 0.f, sq = 0.f;
    for (int c = tid; c < C; c += 256) { float v = rp[c]; s += v; sq += v * v; }
    red[tid] = s; __syncthreads();
    for (int o = 128; o > 0; o >>= 1) { if (tid < o) red[tid] += red[tid + o]; __syncthreads(); }
    float mean = red[0] / (float)C;
    __syncthreads();
    red[tid] = sq; __syncthreads();
    for (int o = 128; o > 0; o >>= 1) { if (tid < o) red[tid] += red[tid + o]; __syncthreads(); }
    float var = red[0] / (float)C - mean * mean;
    float rs = rsqrtf(var + 1e-5f);
    float* op = out + (size_t)row * C;
    for (int c = tid; c < C; c += 256) {
        float v = (rp[c] - mean) * rs * g[c] + be[c];
        v = fmaxf(v, 0.f);
        op[c] = round_out ? __uint_as_float(f2tf32(v)) : v;
    }
}

// ---------------- concat [expanded(32); pos(128)] ----------------
__global__ __launch_bounds__(256) void concat_kernel(
    const float* __restrict__ e, const float* __restrict__ pos, float* __restrict__ o)
{
    int i = blockIdx.x * 256 + threadIdx.x;
    o[i] = (i < 32 * 1024) ? e[i] : pos[i - 32 * 1024];
}

// ---------------- pack h0 into exchange buffer set 0 ----------------
__global__ __launch_bounds__(256) void pack_h0_kernel(
    const float* __restrict__ EXP, float* __restrict__ HB)
{
    int i = blockIdx.x * 256 + threadIdx.x;
    const int bp = i >> 11;
    const int j  = i & 2047;
    const int k  = j >> 1;
    const int c  = j & 1;
    const float v = EXP[(2 * bp + c) * 1024 + k];
    HB[i] = v;
    HB[32768 + i] = v;
}

// ---------------- persistent RNN layer ----------------
#define W_PITCH 1028
#define H_PITCH 2052
#define WSH_OFF 0
#define HSH_OFF (16 * W_PITCH)
#define RED_OFF (HSH_OFF + 16 * H_PITCH)
#define RNN_SMEM_FLOATS (RED_OFF + 512 * 12)
#define RNN_SMEM_BYTES  (RNN_SMEM_FLOATS * 4)

__device__ __forceinline__ unsigned ld_acquire_u32(unsigned* p) {
    unsigned v;
    asm volatile("ld.acquire.gpu.global.u32 %0, [%1];" : "=r"(v) : "l"(p) : "memory");
    return v;
}
__device__ __forceinline__ unsigned atom_add_acqrel(unsigned* p, unsigned v) {
    unsigned o;
    asm volatile("atom.acq_rel.gpu.global.add.u32 %0, [%1], %2;" : "=r"(o) : "l"(p), "r"(v) : "memory");
    return o;
}
__device__ __forceinline__ void st_relaxed_u32(unsigned* p, unsigned v) {
    asm volatile("st.relaxed.gpu.global.u32 [%0], %1;" :: "l"(p), "r"(v) : "memory");
}
__device__ __forceinline__ void st_release_u32(unsigned* p, unsigned v) {
    asm volatile("st.release.gpu.global.u32 [%0], %1;" :: "l"(p), "r"(v) : "memory");
}

__global__ __launch_bounds__(256, 1) void rnn_layer_kernel(
    const float* __restrict__ Whh, const float* __restrict__ gate,
    const float* __restrict__ bih, const float* __restrict__ bhh,
    float* __restrict__ HB, float* __restrict__ Y, int layer)
{
    extern __shared__ float sm[];
    float* Wsh  = sm + WSH_OFF;
    float* Hsh  = sm + HSH_OFF;
    float* Red  = sm + RED_OFF;

    const int tid = threadIdx.x;
    const int bid = blockIdx.x;
    const int d = bid >> 6;
    const int n0 = (bid & 63) * 16;

    const int kq = tid >> 5;
    const int lane = tid & 31;
    const int bq = lane & 7;
    const int ng = lane >> 3;

    for (int it = 0; it < 16; it++) {
        const int idx = tid + it * 256;
        const int n = idx >> 8, k4 = idx & 255;
        float4 w = *(const float4*)&Whh[(size_t)(d * 1024 + n0 + n) * 1024 + k4 * 4];
        *(float4*)&Wsh[n * W_PITCH + k4 * 4] = w;
    }

    unsigned local_sense = 0;

    for (int s = 1; s <= T_LEN; s++) {
        const float* src = HB + ((s - 1) & 1) * 65536 + d * 32768;
        __syncthreads();
#pragma unroll
        for (int it = 0; it < 32; it++) {
            const int idx = (tid + it * 256) * 4;
            const int bp = idx >> 11, rem = idx & 2047;
            float4 v = *(const float4*)&src[idx];
            *(float4*)&Hsh[bp * H_PITCH + rem] = v;
        }
        __syncthreads();

        float acc[4][4];
#pragma unroll
        for (int i = 0; i < 4; i++)
#pragma unroll
            for (int j = 0; j < 4; j++) acc[i][j] = 0.f;

        const float* h0p = &Hsh[(2 * bq) * H_PITCH];
        const float* h1p = &Hsh[(2 * bq + 1) * H_PITCH];
        const float* wp  = &Wsh[(ng * 4) * W_PITCH];

        for (int k = kq * 128; k < kq * 128 + 128; k += 4) {
            float4 hA0 = *(const float4*)&h0p[2 * k];
            float4 hA1 = *(const float4*)&h0p[2 * k + 4];
            float4 hB0 = *(const float4*)&h1p[2 * k];
            float4 hB1 = *(const float4*)&h1p[2 * k + 4];
            float hv[4][4];
            hv[0][0] = hA0.x; hv[0][1] = hA0.z; hv[0][2] = hA1.x; hv[0][3] = hA1.z;
            hv[1][0] = hA0.y; hv[1][1] = hA0.w; hv[1][2] = hA1.y; hv[1][3] = hA1.w;
            hv[2][0] = hB0.x; hv[2][1] = hB0.z; hv[2][2] = hB1.x; hv[2][3] = hB1.z;
            hv[3][0] = hB0.y; hv[3][1] = hB0.w; hv[3][2] = hB1.y; hv[3][3] = hB1.w;
            float wv[4][4];
#pragma unroll
            for (int j = 0; j < 4; j++) {
                float4 w = *(const float4*)&wp[j * W_PITCH + k];
                wv[j][0] = w.x; wv[j][1] = w.y; wv[j][2] = w.z; wv[j][3] = w.w;
            }
#pragma unroll
            for (int kk = 0; kk < 4; kk++)
#pragma unroll
                for (int bi = 0; bi < 4; bi++)
#pragma unroll
                    for (int ni = 0; ni < 4; ni++)
                        acc[bi][ni] += hv[bi][kk] * wv[ni][kk];
        }

        __syncthreads();
#pragma unroll
        for (int bi = 0; bi < 4; bi++)
#pragma unroll
            for (int ni = 0; ni < 4; ni++) {
                const int o = (bq * 4 + bi) * 16 + ng * 4 + ni;
                Red[o * 12 + kq] = acc[bi][ni];
            }
        __syncthreads();

        const int t = d ? (T_LEN - s) : (s - 1);
        float* dst = HB + (s & 1) * 65536 + d * 32768;
#pragma unroll
        for (int oo = 0; oo < 2; oo++) {
            const int o = tid + oo * 256;
            const float* rp = &Red[o * 12];
            float4 r0 = *(const float4*)rp;
            float4 r1 = *(const float4*)(rp + 4);
            float v = ((r0.x + r0.y) + (r0.z + r0.w)) + ((r1.x + r1.y) + (r1.z + r1.w));
            const int b = o >> 4, n = o & 15;
            const int ncol = n0 + n;
            const int col = d * 1024 + ncol;
            const float bb = bih[col] + bhh[col];
            float gv;
            if (layer == 0)
                gv = gate[(size_t)b * 2048 + col] + gate[(size_t)(32 + t) * 2048 + col];
            else
                gv = gate[(size_t)(t * 32 + b) * 2048 + col];
            const float hnew = fmaxf(v + gv + bb, 0.f);
            dst[(b >> 1) * 2048 + 2 * ncol + (b & 1)] = hnew;
            const int row = layer ? (b * 128 + t) : (t * 32 + b);
            // Y feeds TMA/mma GEMMs -> emit tf32-rounded bits
            Y[(size_t)row * 2048 + col] = __uint_as_float(f2tf32(hnew));
        }

        __syncthreads();
        if (tid == 0) {
            const unsigned target = local_sense ^ 1;
            unsigned old = atom_add_acqrel(&g_bar_count, 1);
            if (old == NB - 1) {
                st_relaxed_u32(&g_bar_count, 0);
                st_release_u32(&g_bar_sense, target);
            } else {
                while (ld_acquire_u32(&g_bar_sense) != target) { }
            }
        }
        local_sense ^= 1;
        __syncthreads();
    }
}

// ---------------- launch helpers ----------------
static inline void gemm_small(const float* A, const float* B, const float* bias,
                              float* C, int M, int N, int K)
{
    dim3 grid(N / 128, (M + 127) / 128);
    gemm_tf32_kernel<<<grid, 256>>>(A, B, bias, C, M, N, K);
}

typedef CUresult (CUDAAPI *PFN_encodeTiled)(
    CUtensorMap*, CUtensorMapDataType, cuuint32_t, void*,
    const cuuint64_t*, const cuuint64_t*, const cuuint32_t*, const cuuint32_t*,
    CUtensorMapInterleave, CUtensorMapSwizzle, CUtensorMapL2promotion,
    CUtensorMapFloatOOBfill);

static inline CUtensorMap make_map2d(PFN_encodeTiled enc, const float* ptr,
                                     int rows, int K, int boxRows)
{
    CUtensorMap m{};
    cuuint64_t dims[2]    = {(cuuint64_t)K, (cuuint64_t)rows};
    cuuint64_t strides[1] = {(cuuint64_t)K * 4};
    cuuint32_t box[2]     = {32u, (cuuint32_t)boxRows};
    cuuint32_t es[2]      = {1u, 1u};
    enc(&m, CU_TENSOR_MAP_DATA_TYPE_FLOAT32, 2, (void*)ptr,
        dims, strides, box, es,
        CU_TENSOR_MAP_INTERLEAVE_NONE, CU_TENSOR_MAP_SWIZZLE_128B,
        CU_TENSOR_MAP_L2_PROMOTION_L2_128B, CU_TENSOR_MAP_FLOAT_OOB_FILL_NONE);
    return m;
}

extern "C" void kernel_launch(void* const* d_in, const int* in_sizes, int n_in,
                              void* d_out, int out_size)
{
    (void)in_sizes; (void)n_in; (void)out_size;
    const float* x     = (const float*)d_in[0];
    const float* W_exp = (const float*)d_in[1];
    const float* b_exp = (const float*)d_in[2];
    const float* g1    = (const float*)d_in[3];
    const float* be1   = (const float*)d_in[4];
    const float* pos   = (const float*)d_in[5];
    const float* Wih0  = (const float*)d_in[6];
    const float* Whh0  = (const float*)d_in[7];
    const float* bih0  = (const float*)d_in[8];
    const float* bhh0  = (const float*)d_in[9];
    const float* Wih1  = (const float*)d_in[10];
    const float* Whh1  = (const float*)d_in[11];
    const float* bih1  = (const float*)d_in[12];
    const float* bhh1  = (const float*)d_in[13];
    const float* Wp1   = (const float*)d_in[14];
    const float* bp1   = (const float*)d_in[15];
    const float* g2    = (const float*)d_in[16];
    const float* be2   = (const float*)d_in[17];
    const float* Wp2   = (const float*)d_in[18];
    const float* bp2   = (const float*)d_in[19];
    float* out = (float*)d_out;

    float* S = nullptr;
    cudaGetSymbolAddress((void**)&S, g_scratch);

    float* PRE   = S + OFF_PRE;
    float* EXP   = S + OFF_EXP;
    float* A0IN  = S + OFF_A0IN;
    float* C0    = S + OFF_C0;
    float* HB    = S + OFF_P;
    float* X1    = S + OFF_X1;
    float* G1    = S + OFF_G1;
    float* OUT2  = S + OFF_OUT2;
    float* PROJ  = S + OFF_PROJ;
    float* HE    = S + OFF_HE;
    float* WIH1T = S + OFF_WIH1T;
    float* WP1T  = S + OFF_WP1T;
    float* WP2T  = S + OFF_WP2T;

    // driver entry point for tensor-map encode (no -lcuda needed)
    PFN_encodeTiled enc = nullptr;
    cudaGetDriverEntryPoint("cuTensorMapEncodeTiled", (void**)&enc, cudaEnableDefault);

    // Wih1 stacked = [2*1024 = 2048 rows][2048 cols]
    CUtensorMap tmA_G1  = make_map2d(enc, X1,    4096,  2048, 128);
    CUtensorMap tmB_G1  = make_map2d(enc, WIH1T, 2048,  2048, 256);
    CUtensorMap tmA_PRJ = make_map2d(enc, OUT2,  4096,  2048, 128);
    CUtensorMap tmB_PRJ = make_map2d(enc, WP1T,  512,   2048, 256);
    CUtensorMap tmA_LOG = make_map2d(enc, HE,    4096,  512,  128);
    CUtensorMap tmB_LOG = make_map2d(enc, WP2T,  32000, 512,  256);

    cudaFuncSetAttribute(rnn_layer_kernel,
                         cudaFuncAttributeMaxDynamicSharedMemorySize, RNN_SMEM_BYTES);
    cudaFuncSetAttribute(gemm_tma_kernel,
                         cudaFuncAttributeMaxDynamicSharedMemorySize, TG_SMEM_BYTES);

    // 0) pre-round weights for TMA GEMMs (Wih1 numel = 2*1024*2048)
    round_tf32_kernel<<<512, 256>>>(Wih1, WIH1T, 2 * 1024 * 2048 / 4);
    round_tf32_kernel<<<512, 256>>>(Wp1,  WP1T,  512 * 2048 / 4);
    round_tf32_kernel<<<512, 256>>>(Wp2,  WP2T,  32000 * 512 / 4);

    // 1) expand
    gemm_small(x, W_exp, b_exp, PRE, 32, 1024, 512);
    ln_relu_kernel<<<32, 256>>>(PRE, g1, be1, EXP, 1024, 0);

    // 2) layer-0 gate factors
    concat_kernel<<<640, 256>>>(EXP, pos, A0IN);
    gemm_small(A0IN, Wih0, nullptr, C0, 160, 2048, 1024);

    // 3) layer-0 recurrence (persistent)
    pack_h0_kernel<<<256, 256>>>(EXP, HB);
    rnn_layer_kernel<<<NB, 256, RNN_SMEM_BYTES>>>(Whh0, C0, bih0, bhh0, HB, X1, 0);

    // 4) layer-1 gates (TMA GEMM): G1[4096,2048] = X1 @ Wih1_stacked^T
    {
        dim3 grid(2048 / 256, 4096 / 128);
        gemm_tma_kernel<<<grid, 512, TG_SMEM_BYTES>>>(tmA_G1, tmB_G1, nullptr, G1, 2048, 2048);
    }

    // 5) layer-1 recurrence (persistent)
    pack_h0_kernel<<<256, 256>>>(EXP, HB);
    rnn_layer_kernel<<<NB, 256, RNN_SMEM_BYTES>>>(Whh1, G1, bih1, bhh1, HB, OUT2, 1);

    // 6) projection head (TMA GEMM)
    {
        dim3 grid(512 / 256, 4096 / 128);
        gemm_tma_kernel<<<grid, 512, TG_SMEM_BYTES>>>(tmA_PRJ, tmB_PRJ, bp1, PROJ, 512, 2048);
    }
    ln_relu_kernel<<<4096, 256>>>(PROJ, g2, be2, HE, 512, 1);

    // 7) logits (TMA GEMM)
    {
        dim3 grid(32000 / 256, 4096 / 128);
        gemm_tma_kernel<<<grid, 512, TG_SMEM_BYTES>>>(tmA_LOG, tmB_LOG, bp2, out, 32000, 512);
    }
}

// round 8
// speedup vs baseline: 3.4058x; 1.1925x over previous
#include <cuda_runtime.h>
#include <cuda.h>
#include <cuda_fp16.h>
#include <cstdint>

#define T_LEN 128
#define NB 128          // persistent RNN blocks

// ---------------- scratch layout (floats) ----------------
#define OFF_PRE   0                                   // [32][1024]
#define OFF_EXP   (OFF_PRE  + 32*1024)                // [32][1024] expanded (=h0)
#define OFF_A0IN  (OFF_EXP  + 32*1024)                // [160][1024]
#define OFF_C0    (OFF_A0IN + 160*1024)               // [160][2048]
#define OFF_P     (OFF_C0   + 160*2048)               // h exchange: 2 sets x [2][32][1024]
#define OFF_X1    (OFF_P    + 2*4*2*32*1024)          // [4096][2048] rows t*32+b
#define OFF_G1    (OFF_X1   + 4096*2048)              // [4096][2048]
#define OFF_OUT2  (OFF_G1   + 4096*2048)              // [4096][2048] rows b*128+t
#define OFF_PROJ  (OFF_OUT2 + 4096*2048)              // [4096][512]
#define OFF_HE    (OFF_PROJ + 4096*512)               // [4096][512]
#define OFF_WIH1T (OFF_HE   + 4096*512)               // [2048][2048] tf32 bits
#define OFF_WP1T  (OFF_WIH1T + 2048*2048)             // [512][2048]
#define OFF_WP2T  (OFF_WP1T  + 512*2048)              // [32000][512]
#define SCRATCH_TOTAL (OFF_WP2T + 32000*512)

__device__ __align__(1024) float g_scratch[SCRATCH_TOTAL];
__device__ unsigned g_bar_count;
__device__ unsigned g_bar_sense;

// ---------------- tf32 helpers ----------------
__device__ __forceinline__ unsigned f2tf32(float f) {
    unsigned u;
    asm("cvt.rna.tf32.f32 %0, %1;" : "=r"(u) : "f"(f));
    return u;
}

__device__ __forceinline__ void mma_tf32(float c[4], const unsigned a[4], const unsigned b[2]) {
    asm volatile(
        "mma.sync.aligned.m16n8k8.row.col.f32.tf32.tf32.f32 "
        "{%0,%1,%2,%3}, {%4,%5,%6,%7}, {%8,%9}, {%0,%1,%2,%3};"
        : "+f"(c[0]), "+f"(c[1]), "+f"(c[2]), "+f"(c[3])
        : "r"(a[0]), "r"(a[1]), "r"(a[2]), "r"(a[3]), "r"(b[0]), "r"(b[1]));
}

// ---------------- weight pre-round to tf32 bits ----------------
__global__ __launch_bounds__(256) void round_tf32_kernel(
    const float* __restrict__ in, float* __restrict__ out, int n4)
{
    for (int i = blockIdx.x * 256 + threadIdx.x; i < n4; i += gridDim.x * 256) {
        float4 v = ((const float4*)in)[i];
        v.x = __uint_as_float(f2tf32(v.x));
        v.y = __uint_as_float(f2tf32(v.y));
        v.z = __uint_as_float(f2tf32(v.z));
        v.w = __uint_as_float(f2tf32(v.w));
        ((float4*)out)[i] = v;
    }
}

// =================== TMA-fed tf32 GEMM (legacy mma.sync compute) ===================
#define TG_STAGES 4
#define TG_STAGE_BYTES 49152                   // A 128*128B + B 256*128B
#define TG_SMEM_BYTES  (1024 + TG_STAGES * TG_STAGE_BYTES)

__device__ __forceinline__ uint32_t smem_u32(const void* p) {
    return (uint32_t)__cvta_generic_to_shared((void*)p);
}
__device__ __forceinline__ void tma2d(uint32_t sdst, const CUtensorMap* tm,
                                      int x, int y, uint32_t bar) {
    asm volatile(
        "cp.async.bulk.tensor.2d.shared::cta.global.tile.mbarrier::complete_tx::bytes "
        "[%0], [%1, {%2, %3}], [%4];"
        :: "r"(sdst), "l"(tm), "r"(x), "r"(y), "r"(bar) : "memory");
}
#define MBAR_INIT(a, c) \
    asm volatile("mbarrier.init.shared.b64 [%0], %1;" :: "r"(a), "r"(c) : "memory")
#define MBAR_EXPECT_TX(a, b) \
    asm volatile("mbarrier.arrive.expect_tx.shared.b64 _, [%0], %1;" :: "r"(a), "r"(b) : "memory")
#define MBAR_ARRIVE(a) \
    asm volatile("mbarrier.arrive.shared.b64 _, [%0];" :: "r"(a) : "memory")
#define MBAR_WAIT(a, ph) do { \
    uint32_t _d_; \
    asm volatile("{\n\t.reg .pred p;\n\tmbarrier.try_wait.parity.acquire.cta.shared::cta.b64 p, [%1], %2;\n\tselp.b32 %0, 1, 0, p;\n\t}" \
        : "=r"(_d_) : "r"(a), "r"(ph) : "memory"); \
    while (!_d_) { \
        asm volatile("{\n\t.reg .pred p;\n\tmbarrier.try_wait.parity.acquire.cta.shared::cta.b64 p, [%1], %2, 0x989680;\n\tselp.b32 %0, 1, 0, p;\n\t}" \
            : "=r"(_d_) : "r"(a), "r"(ph) : "memory"); \
    } \
} while (0)

__global__ __launch_bounds__(512, 1) void gemm_tma_kernel(
    const __grid_constant__ CUtensorMap tmA,
    const __grid_constant__ CUtensorMap tmB,
    const float* __restrict__ bias, float* __restrict__ C,
    int N, int K)
{
    extern __shared__ char dsm[];
    __shared__ __align__(8) unsigned long long bars[8];  // full[4], empty[4]

    const int tid  = threadIdx.x;
    const int warp = tid >> 5;
    const int lane = tid & 31;
    const int wm   = warp & 3;
    const int wn   = warp >> 2;
    const int gid  = lane >> 2;
    const int tig  = lane & 3;
    const int mblk = blockIdx.y * 128;
    const int nblk = blockIdx.x * 256;
    const int KT   = K / 32;

    const uint32_t raw   = smem_u32(dsm);
    const uint32_t sbase = (raw + 1023) & ~1023u;
    char* tile0 = dsm + (sbase - raw);
    const uint32_t barb = smem_u32(bars);

    if (tid == 0) {
        for (int i = 0; i < 4; i++) MBAR_INIT(barb + i * 8, 1);
        for (int i = 4; i < 8; i++) MBAR_INIT(barb + i * 8, 16);
    }
    __syncthreads();

    if (tid == 0) {
        const int pre = KT < TG_STAGES ? KT : TG_STAGES;
        for (int st = 0; st < pre; st++) {
            const uint32_t full = barb + st * 8;
            MBAR_EXPECT_TX(full, TG_STAGE_BYTES);
            const uint32_t sa = sbase + st * TG_STAGE_BYTES;
            tma2d(sa,         &tmA, st * 32, mblk, full);
            tma2d(sa + 16384, &tmB, st * 32, nblk, full);
        }
    }

    float acc[2][8][4];
#pragma unroll
    for (int i = 0; i < 2; i++)
#pragma unroll
        for (int j = 0; j < 8; j++)
#pragma unroll
            for (int r = 0; r < 4; r++) acc[i][j][r] = 0.f;

    const uint32_t xorv = (uint32_t)gid << 4;

    for (int kt = 0; kt < KT; kt++) {
        const int st = kt & 3;
        const uint32_t ph = (kt >> 2) & 1;
        MBAR_WAIT(barb + st * 8, ph);

        const char* As = tile0 + st * TG_STAGE_BYTES;
        const char* Bs = As + 16384;

#pragma unroll
        for (int ks = 0; ks < 4; ks++) {
            const uint32_t c4a = (uint32_t)(ks * 32 + tig * 4) ^ xorv;
            const uint32_t c4b = (uint32_t)(ks * 32 + tig * 4 + 16) ^ xorv;
            unsigned afr[2][4], bfr[8][2];
#pragma unroll
            for (int mf = 0; mf < 2; mf++) {
                const int r0 = wm * 32 + mf * 16 + gid;
                afr[mf][0] = *(const unsigned*)(As + r0 * 128 + c4a);
                afr[mf][1] = *(const unsigned*)(As + (r0 + 8) * 128 + c4a);
                afr[mf][2] = *(const unsigned*)(As + r0 * 128 + c4b);
                afr[mf][3] = *(const unsigned*)(As + (r0 + 8) * 128 + c4b);
            }
#pragma unroll
            for (int nf = 0; nf < 8; nf++) {
                const int nc = wn * 64 + nf * 8 + gid;
                bfr[nf][0] = *(const unsigned*)(Bs + nc * 128 + c4a);
                bfr[nf][1] = *(const unsigned*)(Bs + nc * 128 + c4b);
            }
#pragma unroll
            for (int mf = 0; mf < 2; mf++)
#pragma unroll
                for (int nf = 0; nf < 8; nf++)
                    mma_tf32(acc[mf][nf], afr[mf], bfr[nf]);
        }

        __syncwarp();
        if (lane == 0) MBAR_ARRIVE(barb + (4 + st) * 8);

        if (tid == 0 && kt + TG_STAGES < KT) {
            MBAR_WAIT(barb + (4 + st) * 8, ph);
            const uint32_t full = barb + st * 8;
            MBAR_EXPECT_TX(full, TG_STAGE_BYTES);
            const uint32_t sa = sbase + st * TG_STAGE_BYTES;
            tma2d(sa,         &tmA, (kt + TG_STAGES) * 32, mblk, full);
            tma2d(sa + 16384, &tmB, (kt + TG_STAGES) * 32, nblk, full);
        }
    }

#pragma unroll
    for (int nf = 0; nf < 8; nf++) {
        const int col = nblk + wn * 64 + nf * 8 + tig * 2;
        const float b0 = bias ? bias[col] : 0.f;
        const float b1 = bias ? bias[col + 1] : 0.f;
#pragma unroll
        for (int mf = 0; mf < 2; mf++) {
            const int row = mblk + wm * 32 + mf * 16 + gid;
            {
                float2 v = make_float2(acc[mf][nf][0] + b0, acc[mf][nf][1] + b1);
                *(float2*)(C + (size_t)row * N + col) = v;
            }
            {
                float2 v = make_float2(acc[mf][nf][2] + b0, acc[mf][nf][3] + b1);
                *(float2*)(C + (size_t)(row + 8) * N + col) = v;
            }
        }
    }
}

// ---------------- small tf32 GEMM (legacy mma): C = A @ B^T (+bias) ----------
#define SPITCH 136
__global__ __launch_bounds__(256, 2) void gemm_tf32_kernel(
    const float* __restrict__ A, const float* __restrict__ B,
    const float* __restrict__ bias, float* __restrict__ C,
    int M, int N, int K)
{
    __shared__ unsigned As[16][SPITCH];
    __shared__ unsigned Bs[16][SPITCH];

    const int tid  = threadIdx.x;
    const int warp = tid >> 5;
    const int lane = tid & 31;
    const int wm = warp & 1;
    const int wn = warp >> 1;
    const int gid = lane >> 2;
    const int tig = lane & 3;

    const int mblk = blockIdx.y * 128;
    const int nblk = blockIdx.x * 128;

    const int lr = tid >> 1;
    const int kc = (tid & 1) * 8;
    const int rowA = mblk + lr;
    const bool aval = rowA < M;
    const float* Ap = A + (size_t)(aval ? rowA : 0) * K + kc;
    const float* Bp = B + (size_t)(nblk + lr) * K + kc;

    float acc[4][4][4];
#pragma unroll
    for (int i = 0; i < 4; i++)
#pragma unroll
        for (int j = 0; j < 4; j++)
#pragma unroll
            for (int r = 0; r < 4; r++) acc[i][j][r] = 0.f;

    float4 av0 = aval ? *(const float4*)Ap : make_float4(0,0,0,0);
    float4 av1 = aval ? *(const float4*)(Ap + 4) : make_float4(0,0,0,0);
    float4 bv0 = *(const float4*)Bp;
    float4 bv1 = *(const float4*)(Bp + 4);
    Ap += 16; Bp += 16;

    for (int k0 = 0; k0 < K; k0 += 16) {
        As[kc + 0][lr] = f2tf32(av0.x); As[kc + 1][lr] = f2tf32(av0.y);
        As[kc + 2][lr] = f2tf32(av0.z); As[kc + 3][lr] = f2tf32(av0.w);
        As[kc + 4][lr] = f2tf32(av1.x); As[kc + 5][lr] = f2tf32(av1.y);
        As[kc + 6][lr] = f2tf32(av1.z); As[kc + 7][lr] = f2tf32(av1.w);
        Bs[kc + 0][lr] = f2tf32(bv0.x); Bs[kc + 1][lr] = f2tf32(bv0.y);
        Bs[kc + 2][lr] = f2tf32(bv0.z); Bs[kc + 3][lr] = f2tf32(bv0.w);
        Bs[kc + 4][lr] = f2tf32(bv1.x); Bs[kc + 5][lr] = f2tf32(bv1.y);
        Bs[kc + 6][lr] = f2tf32(bv1.z); Bs[kc + 7][lr] = f2tf32(bv1.w);
        __syncthreads();

        if (k0 + 16 < K) {
            av0 = aval ? *(const float4*)Ap : make_float4(0,0,0,0);
            av1 = aval ? *(const float4*)(Ap + 4) : make_float4(0,0,0,0);
            bv0 = *(const float4*)Bp;
            bv1 = *(const float4*)(Bp + 4);
            Ap += 16; Bp += 16;
        }

#pragma unroll
        for (int ks = 0; ks < 2; ks++) {
            const int kb = ks * 8;
            unsigned afr[4][4], bfr[4][2];
#pragma unroll
            for (int mt = 0; mt < 4; mt++) {
                const int mr = wm * 64 + mt * 16 + gid;
                afr[mt][0] = As[kb + tig][mr];
                afr[mt][1] = As[kb + tig][mr + 8];
                afr[mt][2] = As[kb + tig + 4][mr];
                afr[mt][3] = As[kb + tig + 4][mr + 8];
            }
#pragma unroll
            for (int nt = 0; nt < 4; nt++) {
                const int nc = wn * 32 + nt * 8 + gid;
                bfr[nt][0] = Bs[kb + tig][nc];
                bfr[nt][1] = Bs[kb + tig + 4][nc];
            }
#pragma unroll
            for (int mt = 0; mt < 4; mt++)
#pragma unroll
                for (int nt = 0; nt < 4; nt++)
                    mma_tf32(acc[mt][nt], afr[mt], bfr[nt]);
        }
        __syncthreads();
    }

#pragma unroll
    for (int nt = 0; nt < 4; nt++) {
        const int col = nblk + wn * 32 + nt * 8 + tig * 2;
        const float b0 = bias ? bias[col] : 0.f;
        const float b1 = bias ? bias[col + 1] : 0.f;
#pragma unroll
        for (int mt = 0; mt < 4; mt++) {
            const int row = mblk + wm * 64 + mt * 16 + gid;
            if (row < M) {
                float2 v = make_float2(acc[mt][nt][0] + b0, acc[mt][nt][1] + b1);
                *(float2*)(C + (size_t)row * N + col) = v;
            }
            if (row + 8 < M) {
                float2 v = make_float2(acc[mt][nt][2] + b0, acc[mt][nt][3] + b1);
                *(float2*)(C + (size_t)(row + 8) * N + col) = v;
            }
        }
    }
}

// ---------------- LayerNorm + ReLU ----------------
__global__ __launch_bounds__(256) void ln_relu_kernel(
    const float* __restrict__ in, const float* __restrict__ g,
    const float* __restrict__ be, float* __restrict__ out, int C, int round_out)
{
    __shared__ float red[256];
    const int row = blockIdx.x;
    const int tid = threadIdx.x;
    const float* rp = in + (size_t)row * C;
    float s = 0.f, sq = 0.f;
    for (int c = tid; c < C; c += 256) { float v = rp[c]; s += v; sq += v * v; }
    red[tid] = s; __syncthreads();
    for (int o = 128; o > 0; o >>= 1) { if (tid < o) red[tid] += red[tid + o]; __syncthreads(); }
    float mean = red[0] / (float)C;
    __syncthreads();
    red[tid] = sq; __syncthreads();
    for (int o = 128; o > 0; o >>= 1) { if (tid < o) red[tid] += red[tid + o]; __syncthreads(); }
    float var = red[0] / (float)C - mean * mean;
    float rs = rsqrtf(var + 1e-5f);
    float* op = out + (size_t)row * C;
    for (int c = tid; c < C; c += 256) {
        float v = (rp[c] - mean) * rs * g[c] + be[c];
        v = fmaxf(v, 0.f);
        op[c] = round_out ? __uint_as_float(f2tf32(v)) : v;
    }
}

// ---------------- concat [expanded(32); pos(128)] ----------------
__global__ __launch_bounds__(256) void concat_kernel(
    const float* __restrict__ e, const float* __restrict__ pos, float* __restrict__ o)
{
    int i = blockIdx.x * 256 + threadIdx.x;
    o[i] = (i < 32 * 1024) ? e[i] : pos[i - 32 * 1024];
}

// ---------------- pack h0 into exchange buffer set 0: plain [d][b][k] --------------
__global__ __launch_bounds__(256) void pack_h0_kernel(
    const float* __restrict__ EXP, float* __restrict__ HB)
{
    int i = blockIdx.x * 256 + threadIdx.x;   // 128 blocks -> 32768
    const float v = EXP[i];
    HB[i] = v;
    HB[32768 + i] = v;
}

// ---------------- persistent RNN layer (3xTF32 tensor-core recurrence) -------------
// 128 blocks: d = bid>>6, n0 = (bid&63)*16. 256 threads = 8 warps, warp = k-split kq.
// smem: Hsh fp32 [32 b][pitch 1028] (131584 B) | Whi fp32 [1024 k][16 n] (65536 B)
//       | Wlo fp16 x2048 [1024][16] (32768 B).  Red (16 KB) aliases Hsh.
#define RNN2_HSH_PITCH 1028
#define RNN2_WHI_OFF   131584
#define RNN2_WLO_OFF   (131584 + 65536)
#define RNN2_SMEM_BYTES (RNN2_WLO_OFF + 32768)

__device__ __forceinline__ unsigned ld_acquire_u32(unsigned* p) {
    unsigned v;
    asm volatile("ld.acquire.gpu.global.u32 %0, [%1];" : "=r"(v) : "l"(p) : "memory");
    return v;
}
__device__ __forceinline__ unsigned atom_add_acqrel(unsigned* p, unsigned v) {
    unsigned o;
    asm volatile("atom.acq_rel.gpu.global.add.u32 %0, [%1], %2;" : "=r"(o) : "l"(p), "r"(v) : "memory");
    return o;
}
__device__ __forceinline__ void st_relaxed_u32(unsigned* p, unsigned v) {
    asm volatile("st.relaxed.gpu.global.u32 [%0], %1;" :: "l"(p), "r"(v) : "memory");
}
__device__ __forceinline__ void st_release_u32(unsigned* p, unsigned v) {
    asm volatile("st.release.gpu.global.u32 [%0], %1;" :: "l"(p), "r"(v) : "memory");
}

__global__ __launch_bounds__(256, 1) void rnn_layer_kernel(
    const float* __restrict__ Whh, const float* __restrict__ gate,
    const float* __restrict__ bih, const float* __restrict__ bhh,
    float* __restrict__ HB, float* __restrict__ Y, int layer)
{
    extern __shared__ char sm2[];
    float*  Hsh = (float*)sm2;
    float*  Whi = (float*)(sm2 + RNN2_WHI_OFF);
    __half* Wlo = (__half*)(sm2 + RNN2_WLO_OFF);

    const int tid  = threadIdx.x;
    const int bid  = blockIdx.x;
    const int d    = bid >> 6;
    const int n0   = (bid & 63) * 16;
    const int kq   = tid >> 5;
    const int lane = tid & 31;
    const int gid  = lane >> 2;
    const int tig  = lane & 3;

    // prologue: split W into hi (tf32-truncated fp32) + lo (x2048, fp16), k-major
    for (int i = tid; i < 16384; i += 256) {
        const int n = i >> 10, k = i & 1023;
        const float w = Whh[(size_t)(d * 1024 + n0 + n) * 1024 + k];
        const float hi = __uint_as_float(__float_as_uint(w) & 0xFFFFE000u);
        Whi[k * 16 + n] = hi;
        Wlo[k * 16 + n] = __float2half_rn((w - hi) * 2048.0f);
    }
    __syncthreads();

    unsigned local_sense = 0;

    for (int s = 1; s <= T_LEN; s++) {
        // ---- each warp copies ONLY its own k-slice of h (16 KB) ----
        const float* src = HB + ((s - 1) & 1) * 65536 + d * 32768;
        for (int j = lane; j < 1024; j += 32) {
            const int b = j >> 5, q = j & 31;
            float4 v = *(const float4*)&src[b * 1024 + kq * 128 + q * 4];
            *(float4*)&Hsh[b * RNN2_HSH_PITCH + kq * 128 + q * 4] = v;
        }
        __syncwarp();

        // ---- 3xTF32 mma over k-slice [kq*128, +128) ----
        float acc[2][2][4];
#pragma unroll
        for (int i = 0; i < 2; i++)
#pragma unroll
            for (int j = 0; j < 2; j++)
#pragma unroll
                for (int r = 0; r < 4; r++) acc[i][j][r] = 0.f;

#pragma unroll 4
        for (int kf = 0; kf < 16; kf++) {
            const int kk = kq * 128 + kf * 8;
            unsigned ah[2][4], al[2][4];
#pragma unroll
            for (int mt = 0; mt < 2; mt++) {
                const int r0 = (mt * 16 + gid) * RNN2_HSH_PITCH + kk;
                float v0 = Hsh[r0 + tig];
                float v1 = Hsh[r0 + 8 * RNN2_HSH_PITCH + tig];
                float v2 = Hsh[r0 + tig + 4];
                float v3 = Hsh[r0 + 8 * RNN2_HSH_PITCH + tig + 4];
                unsigned h0 = __float_as_uint(v0) & 0xFFFFE000u;
                unsigned h1 = __float_as_uint(v1) & 0xFFFFE000u;
                unsigned h2 = __float_as_uint(v2) & 0xFFFFE000u;
                unsigned h3 = __float_as_uint(v3) & 0xFFFFE000u;
                ah[mt][0] = h0; ah[mt][1] = h1; ah[mt][2] = h2; ah[mt][3] = h3;
                al[mt][0] = __float_as_uint(v0 - __uint_as_float(h0));
                al[mt][1] = __float_as_uint(v1 - __uint_as_float(h1));
                al[mt][2] = __float_as_uint(v2 - __uint_as_float(h2));
                al[mt][3] = __float_as_uint(v3 - __uint_as_float(h3));
            }
            unsigned bh[2][2], bl[2][2];
#pragma unroll
            for (int nt = 0; nt < 2; nt++) {
                const int c0 = (kk + tig) * 16 + nt * 8 + gid;
                const int c1 = (kk + tig + 4) * 16 + nt * 8 + gid;
                bh[nt][0] = __float_as_uint(Whi[c0]);
                bh[nt][1] = __float_as_uint(Whi[c1]);
                bl[nt][0] = __float_as_uint(__half2float(Wlo[c0]) * (1.0f / 2048.0f));
                bl[nt][1] = __float_as_uint(__half2float(Wlo[c1]) * (1.0f / 2048.0f));
            }
#pragma unroll
            for (int mt = 0; mt < 2; mt++)
#pragma unroll
                for (int nt = 0; nt < 2; nt++) {
                    mma_tf32(acc[mt][nt], ah[mt], bh[nt]);   // hi*hi
                    mma_tf32(acc[mt][nt], al[mt], bh[nt]);   // h_lo*W_hi
                    mma_tf32(acc[mt][nt], ah[mt], bl[nt]);   // h_hi*W_lo
                }
        }

        // ---- cross-warp k-reduction via Red (aliases Hsh) ----
        __syncthreads();
        float* Red = Hsh;   // Red[kq*512 + b*16 + n], 4096 floats
#pragma unroll
        for (int mt = 0; mt < 2; mt++)
#pragma unroll
            for (int nt = 0; nt < 2; nt++)
#pragma unroll
                for (int r = 0; r < 4; r++) {
                    const int b = mt * 16 + gid + ((r >> 1) << 3);
                    const int n = nt * 8 + tig * 2 + (r & 1);
                    Red[kq * 512 + b * 16 + n] = acc[mt][nt][r];
                }
        __syncthreads();

        // ---- epilogue: gate + bias + relu, write h_s and Y ----
        const int t = d ? (T_LEN - s) : (s - 1);
        float* dst = HB + (s & 1) * 65536 + d * 32768;
#pragma unroll
        for (int oo = 0; oo < 2; oo++) {
            const int o = tid + oo * 256;
            float v = 0.f;
#pragma unroll
            for (int kq2 = 0; kq2 < 8; kq2++) v += Red[kq2 * 512 + o];
            const int b = o >> 4, n = o & 15;
            const int ncol = n0 + n;
            const int col = d * 1024 + ncol;
            const float bb = bih[col] + bhh[col];
            float gv;
            if (layer == 0)
                gv = gate[(size_t)b * 2048 + col] + gate[(size_t)(32 + t) * 2048 + col];
            else
                gv = gate[(size_t)(t * 32 + b) * 2048 + col];
            const float hnew = fmaxf(v + gv + bb, 0.f);
            dst[b * 1024 + ncol] = hnew;
            const int row = layer ? (b * 128 + t) : (t * 32 + b);
            Y[(size_t)row * 2048 + col] = __uint_as_float(f2tf32(hnew));
        }

        // ---- grid barrier (sense reversal) ----
        __syncthreads();
        if (tid == 0) {
            const unsigned target = local_sense ^ 1;
            unsigned old = atom_add_acqrel(&g_bar_count, 1);
            if (old == NB - 1) {
                st_relaxed_u32(&g_bar_count, 0);
                st_release_u32(&g_bar_sense, target);
            } else {
                while (ld_acquire_u32(&g_bar_sense) != target) { }
            }
        }
        local_sense ^= 1;
        __syncthreads();
    }
}

// ---------------- launch helpers ----------------
static inline void gemm_small(const float* A, const float* B, const float* bias,
                              float* C, int M, int N, int K)
{
    dim3 grid(N / 128, (M + 127) / 128);
    gemm_tf32_kernel<<<grid, 256>>>(A, B, bias, C, M, N, K);
}

typedef CUresult (CUDAAPI *PFN_encodeTiled)(
    CUtensorMap*, CUtensorMapDataType, cuuint32_t, void*,
    const cuuint64_t*, const cuuint64_t*, const cuuint32_t*, const cuuint32_t*,
    CUtensorMapInterleave, CUtensorMapSwizzle, CUtensorMapL2promotion,
    CUtensorMapFloatOOBfill);

static inline CUtensorMap make_map2d(PFN_encodeTiled enc, const float* ptr,
                                     int rows, int K, int boxRows)
{
    CUtensorMap m{};
    cuuint64_t dims[2]    = {(cuuint64_t)K, (cuuint64_t)rows};
    cuuint64_t strides[1] = {(cuuint64_t)K * 4};
    cuuint32_t box[2]     = {32u, (cuuint32_t)boxRows};
    cuuint32_t es[2]      = {1u, 1u};
    enc(&m, CU_TENSOR_MAP_DATA_TYPE_FLOAT32, 2, (void*)ptr,
        dims, strides, box, es,
        CU_TENSOR_MAP_INTERLEAVE_NONE, CU_TENSOR_MAP_SWIZZLE_128B,
        CU_TENSOR_MAP_L2_PROMOTION_L2_128B, CU_TENSOR_MAP_FLOAT_OOB_FILL_NONE);
    return m;
}

extern "C" void kernel_launch(void* const* d_in, const int* in_sizes, int n_in,
                              void* d_out, int out_size)
{
    (void)in_sizes; (void)n_in; (void)out_size;
    const float* x     = (const float*)d_in[0];
    const float* W_exp = (const float*)d_in[1];
    const float* b_exp = (const float*)d_in[2];
    const float* g1    = (const float*)d_in[3];
    const float* be1   = (const float*)d_in[4];
    const float* pos   = (const float*)d_in[5];
    const float* Wih0  = (const float*)d_in[6];
    const float* Whh0  = (const float*)d_in[7];
    const float* bih0  = (const float*)d_in[8];
    const float* bhh0  = (const float*)d_in[9];
    const float* Wih1  = (const float*)d_in[10];
    const float* Whh1  = (const float*)d_in[11];
    const float* bih1  = (const float*)d_in[12];
    const float* bhh1  = (const float*)d_in[13];
    const float* Wp1   = (const float*)d_in[14];
    const float* bp1   = (const float*)d_in[15];
    const float* g2    = (const float*)d_in[16];
    const float* be2   = (const float*)d_in[17];
    const float* Wp2   = (const float*)d_in[18];
    const float* bp2   = (const float*)d_in[19];
    float* out = (float*)d_out;

    float* S = nullptr;
    cudaGetSymbolAddress((void**)&S, g_scratch);

    float* PRE   = S + OFF_PRE;
    float* EXP   = S + OFF_EXP;
    float* A0IN  = S + OFF_A0IN;
    float* C0    = S + OFF_C0;
    float* HB    = S + OFF_P;
    float* X1    = S + OFF_X1;
    float* G1    = S + OFF_G1;
    float* OUT2  = S + OFF_OUT2;
    float* PROJ  = S + OFF_PROJ;
    float* HE    = S + OFF_HE;
    float* WIH1T = S + OFF_WIH1T;
    float* WP1T  = S + OFF_WP1T;
    float* WP2T  = S + OFF_WP2T;

    PFN_encodeTiled enc = nullptr;
    cudaGetDriverEntryPoint("cuTensorMapEncodeTiled", (void**)&enc, cudaEnableDefault);

    CUtensorMap tmA_G1  = make_map2d(enc, X1,    4096,  2048, 128);
    CUtensorMap tmB_G1  = make_map2d(enc, WIH1T, 2048,  2048, 256);
    CUtensorMap tmA_PRJ = make_map2d(enc, OUT2,  4096,  2048, 128);
    CUtensorMap tmB_PRJ = make_map2d(enc, WP1T,  512,   2048, 256);
    CUtensorMap tmA_LOG = make_map2d(enc, HE,    4096,  512,  128);
    CUtensorMap tmB_LOG = make_map2d(enc, WP2T,  32000, 512,  256);

    cudaFuncSetAttribute(rnn_layer_kernel,
                         cudaFuncAttributeMaxDynamicSharedMemorySize, RNN2_SMEM_BYTES);
    cudaFuncSetAttribute(gemm_tma_kernel,
                         cudaFuncAttributeMaxDynamicSharedMemorySize, TG_SMEM_BYTES);

    // 0) pre-round weights for TMA GEMMs
    round_tf32_kernel<<<512, 256>>>(Wih1, WIH1T, 2 * 1024 * 2048 / 4);
    round_tf32_kernel<<<512, 256>>>(Wp1,  WP1T,  512 * 2048 / 4);
    round_tf32_kernel<<<512, 256>>>(Wp2,  WP2T,  32000 * 512 / 4);

    // 1) expand
    gemm_small(x, W_exp, b_exp, PRE, 32, 1024, 512);
    ln_relu_kernel<<<32, 256>>>(PRE, g1, be1, EXP, 1024, 0);

    // 2) layer-0 gate factors
    concat_kernel<<<640, 256>>>(EXP, pos, A0IN);
    gemm_small(A0IN, Wih0, nullptr, C0, 160, 2048, 1024);

    // 3) layer-0 recurrence (persistent, 3xTF32 tensor cores)
    pack_h0_kernel<<<128, 256>>>(EXP, HB);
    rnn_layer_kernel<<<NB, 256, RNN2_SMEM_BYTES>>>(Whh0, C0, bih0, bhh0, HB, X1, 0);

    // 4) layer-1 gates (TMA GEMM)
    {
        dim3 grid(2048 / 256, 4096 / 128);
        gemm_tma_kernel<<<grid, 512, TG_SMEM_BYTES>>>(tmA_G1, tmB_G1, nullptr, G1, 2048, 2048);
    }

    // 5) layer-1 recurrence (persistent, 3xTF32 tensor cores)
    pack_h0_kernel<<<128, 256>>>(EXP, HB);
    rnn_layer_kernel<<<NB, 256, RNN2_SMEM_BYTES>>>(Whh1, G1, bih1, bhh1, HB, OUT2, 1);

    // 6) projection head (TMA GEMM)
    {
        dim3 grid(512 / 256, 4096 / 128);
        gemm_tma_kernel<<<grid, 512, TG_SMEM_BYTES>>>(tmA_PRJ, tmB_PRJ, bp1, PROJ, 512, 2048);
    }
    ln_relu_kernel<<<4096, 256>>>(PROJ, g2, be2, HE, 512, 1);

    // 7) logits (TMA GEMM)
    {
        dim3 grid(32000 / 256, 4096 / 128);
        gemm_tma_kernel<<<grid, 512, TG_SMEM_BYTES>>>(tmA_LOG, tmB_LOG, bp2, out, 32000, 512);
    }
}

// round 9
// speedup vs baseline: 3.9463x; 1.1587x over previous
#include <cuda_runtime.h>
#include <cuda.h>
#include <cuda_fp16.h>
#include <cstdint>

#define T_LEN 128

// ---------------- scratch layout (floats) ----------------
#define OFF_PRE   0                                   // [32][1024]
#define OFF_EXP   (OFF_PRE  + 32*1024)                // [32][1024] expanded (=h0)
#define OFF_A0IN  (OFF_EXP  + 32*1024)                // [160][1024]
#define OFF_C0    (OFF_A0IN + 160*1024)               // [160][2048]
#define OFF_P     (OFF_C0   + 160*2048)               // h exchange: 2 sets x [2][32][1024]
#define OFF_X1    (OFF_P    + 2*4*2*32*1024)          // [4096][2048] rows t*32+b
#define OFF_G1    (OFF_X1   + 4096*2048)              // [4096][2048]
#define OFF_OUT2  (OFF_G1   + 4096*2048)              // [4096][2048] rows b*128+t
#define OFF_PROJ  (OFF_OUT2 + 4096*2048)              // [4096][512]
#define OFF_HE    (OFF_PROJ + 4096*512)               // [4096][512]
#define OFF_WIH1T (OFF_HE   + 4096*512)               // [2048][2048] tf32 bits
#define OFF_WP1T  (OFF_WIH1T + 2048*2048)             // [512][2048]
#define OFF_WP2T  (OFF_WP1T  + 512*2048)              // [32000][512]
#define SCRATCH_TOTAL (OFF_WP2T + 32000*512)

__device__ __align__(1024) float g_scratch[SCRATCH_TOTAL];
__device__ unsigned g_bar_count2[2];
__device__ unsigned g_bar_sense2[2];

// ---------------- tf32 helpers ----------------
__device__ __forceinline__ unsigned f2tf32(float f) {
    unsigned u;
    asm("cvt.rna.tf32.f32 %0, %1;" : "=r"(u) : "f"(f));
    return u;
}

__device__ __forceinline__ void mma_tf32(float c[4], const unsigned a[4], const unsigned b[2]) {
    asm volatile(
        "mma.sync.aligned.m16n8k8.row.col.f32.tf32.tf32.f32 "
        "{%0,%1,%2,%3}, {%4,%5,%6,%7}, {%8,%9}, {%0,%1,%2,%3};"
        : "+f"(c[0]), "+f"(c[1]), "+f"(c[2]), "+f"(c[3])
        : "r"(a[0]), "r"(a[1]), "r"(a[2]), "r"(a[3]), "r"(b[0]), "r"(b[1]));
}

// ---------------- weight pre-round to tf32 bits ----------------
__global__ __launch_bounds__(256) void round_tf32_kernel(
    const float* __restrict__ in, float* __restrict__ out, int n4)
{
    for (int i = blockIdx.x * 256 + threadIdx.x; i < n4; i += gridDim.x * 256) {
        float4 v = ((const float4*)in)[i];
        v.x = __uint_as_float(f2tf32(v.x));
        v.y = __uint_as_float(f2tf32(v.y));
        v.z = __uint_as_float(f2tf32(v.z));
        v.w = __uint_as_float(f2tf32(v.w));
        ((float4*)out)[i] = v;
    }
}

// =================== TMA-fed tf32 GEMM (legacy mma.sync compute) ===================
#define TG_STAGES 4
#define TG_STAGE_BYTES 49152                   // A 128*128B + B 256*128B
#define TG_SMEM_BYTES  (1024 + TG_STAGES * TG_STAGE_BYTES)

__device__ __forceinline__ uint32_t smem_u32(const void* p) {
    return (uint32_t)__cvta_generic_to_shared((void*)p);
}
__device__ __forceinline__ void tma2d(uint32_t sdst, const CUtensorMap* tm,
                                      int x, int y, uint32_t bar) {
    asm volatile(
        "cp.async.bulk.tensor.2d.shared::cta.global.tile.mbarrier::complete_tx::bytes "
        "[%0], [%1, {%2, %3}], [%4];"
        :: "r"(sdst), "l"(tm), "r"(x), "r"(y), "r"(bar) : "memory");
}
#define MBAR_INIT(a, c) \
    asm volatile("mbarrier.init.shared.b64 [%0], %1;" :: "r"(a), "r"(c) : "memory")
#define MBAR_EXPECT_TX(a, b) \
    asm volatile("mbarrier.arrive.expect_tx.shared.b64 _, [%0], %1;" :: "r"(a), "r"(b) : "memory")
#define MBAR_ARRIVE(a) \
    asm volatile("mbarrier.arrive.shared.b64 _, [%0];" :: "r"(a) : "memory")
#define MBAR_WAIT(a, ph) do { \
    uint32_t _d_; \
    asm volatile("{\n\t.reg .pred p;\n\tmbarrier.try_wait.parity.acquire.cta.shared::cta.b64 p, [%1], %2;\n\tselp.b32 %0, 1, 0, p;\n\t}" \
        : "=r"(_d_) : "r"(a), "r"(ph) : "memory"); \
    while (!_d_) { \
        asm volatile("{\n\t.reg .pred p;\n\tmbarrier.try_wait.parity.acquire.cta.shared::cta.b64 p, [%1], %2, 0x989680;\n\tselp.b32 %0, 1, 0, p;\n\t}" \
            : "=r"(_d_) : "r"(a), "r"(ph) : "memory"); \
    } \
} while (0)

__global__ __launch_bounds__(512, 1) void gemm_tma_kernel(
    const __grid_constant__ CUtensorMap tmA,
    const __grid_constant__ CUtensorMap tmB,
    const float* __restrict__ bias, float* __restrict__ C,
    int N, int K)
{
    extern __shared__ char dsm[];
    __shared__ __align__(8) unsigned long long bars[8];  // full[4], empty[4]

    const int tid  = threadIdx.x;
    const int warp = tid >> 5;
    const int lane = tid & 31;
    const int wm   = warp & 3;
    const int wn   = warp >> 2;
    const int gid  = lane >> 2;
    const int tig  = lane & 3;
    const int mblk = blockIdx.y * 128;
    const int nblk = blockIdx.x * 256;
    const int KT   = K / 32;

    const uint32_t raw   = smem_u32(dsm);
    const uint32_t sbase = (raw + 1023) & ~1023u;
    char* tile0 = dsm + (sbase - raw);
    const uint32_t barb = smem_u32(bars);

    if (tid == 0) {
        for (int i = 0; i < 4; i++) MBAR_INIT(barb + i * 8, 1);
        for (int i = 4; i < 8; i++) MBAR_INIT(barb + i * 8, 16);
    }
    __syncthreads();

    if (tid == 0) {
        const int pre = KT < TG_STAGES ? KT : TG_STAGES;
        for (int st = 0; st < pre; st++) {
            const uint32_t full = barb + st * 8;
            MBAR_EXPECT_TX(full, TG_STAGE_BYTES);
            const uint32_t sa = sbase + st * TG_STAGE_BYTES;
            tma2d(sa,         &tmA, st * 32, mblk, full);
            tma2d(sa + 16384, &tmB, st * 32, nblk, full);
        }
    }

    float acc[2][8][4];
#pragma unroll
    for (int i = 0; i < 2; i++)
#pragma unroll
        for (int j = 0; j < 8; j++)
#pragma unroll
            for (int r = 0; r < 4; r++) acc[i][j][r] = 0.f;

    const uint32_t xorv = (uint32_t)gid << 4;

    for (int kt = 0; kt < KT; kt++) {
        const int st = kt & 3;
        const uint32_t ph = (kt >> 2) & 1;
        MBAR_WAIT(barb + st * 8, ph);

        const char* As = tile0 + st * TG_STAGE_BYTES;
        const char* Bs = As + 16384;

#pragma unroll
        for (int ks = 0; ks < 4; ks++) {
            const uint32_t c4a = (uint32_t)(ks * 32 + tig * 4) ^ xorv;
            const uint32_t c4b = (uint32_t)(ks * 32 + tig * 4 + 16) ^ xorv;
            unsigned afr[2][4], bfr[8][2];
#pragma unroll
            for (int mf = 0; mf < 2; mf++) {
                const int r0 = wm * 32 + mf * 16 + gid;
                afr[mf][0] = *(const unsigned*)(As + r0 * 128 + c4a);
                afr[mf][1] = *(const unsigned*)(As + (r0 + 8) * 128 + c4a);
                afr[mf][2] = *(const unsigned*)(As + r0 * 128 + c4b);
                afr[mf][3] = *(const unsigned*)(As + (r0 + 8) * 128 + c4b);
            }
#pragma unroll
            for (int nf = 0; nf < 8; nf++) {
                const int nc = wn * 64 + nf * 8 + gid;
                bfr[nf][0] = *(const unsigned*)(Bs + nc * 128 + c4a);
                bfr[nf][1] = *(const unsigned*)(Bs + nc * 128 + c4b);
            }
#pragma unroll
            for (int mf = 0; mf < 2; mf++)
#pragma unroll
                for (int nf = 0; nf < 8; nf++)
                    mma_tf32(acc[mf][nf], afr[mf], bfr[nf]);
        }

        __syncwarp();
        if (lane == 0) MBAR_ARRIVE(barb + (4 + st) * 8);

        if (tid == 0 && kt + TG_STAGES < KT) {
            MBAR_WAIT(barb + (4 + st) * 8, ph);
            const uint32_t full = barb + st * 8;
            MBAR_EXPECT_TX(full, TG_STAGE_BYTES);
            const uint32_t sa = sbase + st * TG_STAGE_BYTES;
            tma2d(sa,         &tmA, (kt + TG_STAGES) * 32, mblk, full);
            tma2d(sa + 16384, &tmB, (kt + TG_STAGES) * 32, nblk, full);
        }
    }

#pragma unroll
    for (int nf = 0; nf < 8; nf++) {
        const int col = nblk + wn * 64 + nf * 8 + tig * 2;
        const float b0 = bias ? bias[col] : 0.f;
        const float b1 = bias ? bias[col + 1] : 0.f;
#pragma unroll
        for (int mf = 0; mf < 2; mf++) {
            const int row = mblk + wm * 32 + mf * 16 + gid;
            {
                float2 v = make_float2(acc[mf][nf][0] + b0, acc[mf][nf][1] + b1);
                *(float2*)(C + (size_t)row * N + col) = v;
            }
            {
                float2 v = make_float2(acc[mf][nf][2] + b0, acc[mf][nf][3] + b1);
                *(float2*)(C + (size_t)(row + 8) * N + col) = v;
            }
        }
    }
}

// ---------------- small tf32 GEMM (legacy mma): C = A @ B^T (+bias) ----------
#define SPITCH 136
__global__ __launch_bounds__(256, 2) void gemm_tf32_kernel(
    const float* __restrict__ A, const float* __restrict__ B,
    const float* __restrict__ bias, float* __restrict__ C,
    int M, int N, int K)
{
    __shared__ unsigned As[16][SPITCH];
    __shared__ unsigned Bs[16][SPITCH];

    const int tid  = threadIdx.x;
    const int warp = tid >> 5;
    const int lane = tid & 31;
    const int wm = warp & 1;
    const int wn = warp >> 1;
    const int gid = lane >> 2;
    const int tig = lane & 3;

    const int mblk = blockIdx.y * 128;
    const int nblk = blockIdx.x * 128;

    const int lr = tid >> 1;
    const int kc = (tid & 1) * 8;
    const int rowA = mblk + lr;
    const bool aval = rowA < M;
    const float* Ap = A + (size_t)(aval ? rowA : 0) * K + kc;
    const float* Bp = B + (size_t)(nblk + lr) * K + kc;

    float acc[4][4][4];
#pragma unroll
    for (int i = 0; i < 4; i++)
#pragma unroll
        for (int j = 0; j < 4; j++)
#pragma unroll
            for (int r = 0; r < 4; r++) acc[i][j][r] = 0.f;

    float4 av0 = aval ? *(const float4*)Ap : make_float4(0,0,0,0);
    float4 av1 = aval ? *(const float4*)(Ap + 4) : make_float4(0,0,0,0);
    float4 bv0 = *(const float4*)Bp;
    float4 bv1 = *(const float4*)(Bp + 4);
    Ap += 16; Bp += 16;

    for (int k0 = 0; k0 < K; k0 += 16) {
        As[kc + 0][lr] = f2tf32(av0.x); As[kc + 1][lr] = f2tf32(av0.y);
        As[kc + 2][lr] = f2tf32(av0.z); As[kc + 3][lr] = f2tf32(av0.w);
        As[kc + 4][lr] = f2tf32(av1.x); As[kc + 5][lr] = f2tf32(av1.y);
        As[kc + 6][lr] = f2tf32(av1.z); As[kc + 7][lr] = f2tf32(av1.w);
        Bs[kc + 0][lr] = f2tf32(bv0.x); Bs[kc + 1][lr] = f2tf32(bv0.y);
        Bs[kc + 2][lr] = f2tf32(bv0.z); Bs[kc + 3][lr] = f2tf32(bv0.w);
        Bs[kc + 4][lr] = f2tf32(bv1.x); Bs[kc + 5][lr] = f2tf32(bv1.y);
        Bs[kc + 6][lr] = f2tf32(bv1.z); Bs[kc + 7][lr] = f2tf32(bv1.w);
        __syncthreads();

        if (k0 + 16 < K) {
            av0 = aval ? *(const float4*)Ap : make_float4(0,0,0,0);
            av1 = aval ? *(const float4*)(Ap + 4) : make_float4(0,0,0,0);
            bv0 = *(const float4*)Bp;
            bv1 = *(const float4*)(Bp + 4);
            Ap += 16; Bp += 16;
        }

#pragma unroll
        for (int ks = 0; ks < 2; ks++) {
            const int kb = ks * 8;
            unsigned afr[4][4], bfr[4][2];
#pragma unroll
            for (int mt = 0; mt < 4; mt++) {
                const int mr = wm * 64 + mt * 16 + gid;
                afr[mt][0] = As[kb + tig][mr];
                afr[mt][1] = As[kb + tig][mr + 8];
                afr[mt][2] = As[kb + tig + 4][mr];
                afr[mt][3] = As[kb + tig + 4][mr + 8];
            }
#pragma unroll
            for (int nt = 0; nt < 4; nt++) {
                const int nc = wn * 32 + nt * 8 + gid;
                bfr[nt][0] = Bs[kb + tig][nc];
                bfr[nt][1] = Bs[kb + tig + 4][nc];
            }
#pragma unroll
            for (int mt = 0; mt < 4; mt++)
#pragma unroll
                for (int nt = 0; nt < 4; nt++)
                    mma_tf32(acc[mt][nt], afr[mt], bfr[nt]);
        }
        __syncthreads();
    }

#pragma unroll
    for (int nt = 0; nt < 4; nt++) {
        const int col = nblk + wn * 32 + nt * 8 + tig * 2;
        const float b0 = bias ? bias[col] : 0.f;
        const float b1 = bias ? bias[col + 1] : 0.f;
#pragma unroll
        for (int mt = 0; mt < 4; mt++) {
            const int row = mblk + wm * 64 + mt * 16 + gid;
            if (row < M) {
                float2 v = make_float2(acc[mt][nt][0] + b0, acc[mt][nt][1] + b1);
                *(float2*)(C + (size_t)row * N + col) = v;
            }
            if (row + 8 < M) {
                float2 v = make_float2(acc[mt][nt][2] + b0, acc[mt][nt][3] + b1);
                *(float2*)(C + (size_t)(row + 8) * N + col) = v;
            }
        }
    }
}

// ---------------- LayerNorm + ReLU ----------------
__global__ __launch_bounds__(256) void ln_relu_kernel(
    const float* __restrict__ in, const float* __restrict__ g,
    const float* __restrict__ be, float* __restrict__ out, int C, int round_out)
{
    __shared__ float red[256];
    const int row = blockIdx.x;
    const int tid = threadIdx.x;
    const float* rp = in + (size_t)row * C;
    float s = 0.f, sq = 0.f;
    for (int c = tid; c < C; c += 256) { float v = rp[c]; s += v; sq += v * v; }
    red[tid] = s; __syncthreads();
    for (int o = 128; o > 0; o >>= 1) { if (tid < o) red[tid] += red[tid + o]; __syncthreads(); }
    float mean = red[0] / (float)C;
    __syncthreads();
    red[tid] = sq; __syncthreads();
    for (int o = 128; o > 0; o >>= 1) { if (tid < o) red[tid] += red[tid + o]; __syncthreads(); }
    float var = red[0] / (float)C - mean * mean;
    float rs = rsqrtf(var + 1e-5f);
    float* op = out + (size_t)row * C;
    for (int c = tid; c < C; c += 256) {
        float v = (rp[c] - mean) * rs * g[c] + be[c];
        v = fmaxf(v, 0.f);
        op[c] = round_out ? __uint_as_float(f2tf32(v)) : v;
    }
}

// ---------------- concat [expanded(32); pos(128)] ----------------
__global__ __launch_bounds__(256) void concat_kernel(
    const float* __restrict__ e, const float* __restrict__ pos, float* __restrict__ o)
{
    int i = blockIdx.x * 256 + threadIdx.x;
    o[i] = (i < 32 * 1024) ? e[i] : pos[i - 32 * 1024];
}

// ---------------- pack h0 into exchange buffer set 0: plain [d][b][k] --------------
__global__ __launch_bounds__(256) void pack_h0_kernel(
    const float* __restrict__ EXP, float* __restrict__ HB)
{
    int i = blockIdx.x * 256 + threadIdx.x;   // 128 blocks -> 32768
    const float v = EXP[i];
    HB[i] = v;
    HB[32768 + i] = v;
}

// ---------------- persistent RNN layer (3xTF32, 512 thr, per-dir barriers) ---------
// 128 blocks: d = bid>>6, n0 = (bid&63)*16. 16 warps = 16-way k-split (64 k each).
// smem: Hsh fp32 [32 b][pitch 1028] | Whi fp32 [1024 k][16 n] | Wlo fp16 x2048.
// Red (32 KB) aliases Hsh.
#define RNN2_HSH_PITCH 1028
#define RNN2_WHI_OFF   131584
#define RNN2_WLO_OFF   (131584 + 65536)
#define RNN2_SMEM_BYTES (RNN2_WLO_OFF + 32768)

__device__ __forceinline__ unsigned ld_acquire_u32(unsigned* p) {
    unsigned v;
    asm volatile("ld.acquire.gpu.global.u32 %0, [%1];" : "=r"(v) : "l"(p) : "memory");
    return v;
}
__device__ __forceinline__ unsigned atom_add_acqrel(unsigned* p, unsigned v) {
    unsigned o;
    asm volatile("atom.acq_rel.gpu.global.add.u32 %0, [%1], %2;" : "=r"(o) : "l"(p), "r"(v) : "memory");
    return o;
}
__device__ __forceinline__ void st_relaxed_u32(unsigned* p, unsigned v) {
    asm volatile("st.relaxed.gpu.global.u32 [%0], %1;" :: "l"(p), "r"(v) : "memory");
}
__device__ __forceinline__ void st_release_u32(unsigned* p, unsigned v) {
    asm volatile("st.release.gpu.global.u32 [%0], %1;" :: "l"(p), "r"(v) : "memory");
}

__global__ __launch_bounds__(512, 1) void rnn_layer_kernel(
    const float* __restrict__ Whh, const float* __restrict__ gate,
    const float* __restrict__ bih, const float* __restrict__ bhh,
    float* __restrict__ HB, float* __restrict__ Y, int layer)
{
    extern __shared__ char sm2[];
    float*  Hsh = (float*)sm2;
    float*  Whi = (float*)(sm2 + RNN2_WHI_OFF);
    __half* Wlo = (__half*)(sm2 + RNN2_WLO_OFF);

    const int tid  = threadIdx.x;
    const int bid  = blockIdx.x;
    const int d    = bid >> 6;
    const int n0   = (bid & 63) * 16;
    const int kq   = tid >> 5;        // 0..15, k-slice [kq*64, +64)
    const int lane = tid & 31;
    const int gid  = lane >> 2;
    const int tig  = lane & 3;

    // prologue: split W into hi (tf32-truncated fp32) + lo (x2048 fp16), k-major
    for (int i = tid; i < 16384; i += 512) {
        const int n = i >> 10, k = i & 1023;
        const float w = Whh[(size_t)(d * 1024 + n0 + n) * 1024 + k];
        const float hi = __uint_as_float(__float_as_uint(w) & 0xFFFFE000u);
        Whi[k * 16 + n] = hi;
        Wlo[k * 16 + n] = __float2half_rn((w - hi) * 2048.0f);
    }
    __syncthreads();

    // step-invariant epilogue terms: thread tid owns output o=tid (b=o>>4, n=o&15)
    const int eb   = tid >> 4;
    const int encl = n0 + (tid & 15);
    const int ecol = d * 1024 + encl;
    const float bb = bih[ecol] + bhh[ecol];
    float gB = 0.f;
    if (layer == 0) gB = gate[(size_t)eb * 2048 + ecol];   // b-term, step-invariant

    unsigned bar_sense = 0;
    unsigned* bcount = &g_bar_count2[d];
    unsigned* bsense = &g_bar_sense2[d];

    for (int s = 1; s <= T_LEN; s++) {
        const int t = d ? (T_LEN - s) : (s - 1);

        // ---- prefetch per-step gate term (latency hides behind copy+MMA) ----
        float gT;
        if (layer == 0) gT = gate[(size_t)(32 + t) * 2048 + ecol];
        else            gT = gate[(size_t)(t * 32 + eb) * 2048 + ecol];

        // ---- each warp copies its own 64-wide k-slice of h (8 KB) ----
        const float* src = HB + ((s - 1) & 1) * 65536 + d * 32768;
        for (int j = lane; j < 512; j += 32) {
            const int b = j >> 4, q = j & 15;
            float4 v = *(const float4*)&src[b * 1024 + kq * 64 + q * 4];
            *(float4*)&Hsh[b * RNN2_HSH_PITCH + kq * 64 + q * 4] = v;
        }
        __syncwarp();

        // ---- 3xTF32 mma over k-slice [kq*64, +64) ----
        float acc[2][2][4];
#pragma unroll
        for (int i = 0; i < 2; i++)
#pragma unroll
            for (int j = 0; j < 2; j++)
#pragma unroll
                for (int r = 0; r < 4; r++) acc[i][j][r] = 0.f;

#pragma unroll
        for (int kf = 0; kf < 8; kf++) {
            const int kk = kq * 64 + kf * 8;
            unsigned ah[2][4], al[2][4];
#pragma unroll
            for (int mt = 0; mt < 2; mt++) {
                const int r0 = (mt * 16 + gid) * RNN2_HSH_PITCH + kk;
                float v0 = Hsh[r0 + tig];
                float v1 = Hsh[r0 + 8 * RNN2_HSH_PITCH + tig];
                float v2 = Hsh[r0 + tig + 4];
                float v3 = Hsh[r0 + 8 * RNN2_HSH_PITCH + tig + 4];
                unsigned h0 = __float_as_uint(v0) & 0xFFFFE000u;
                unsigned h1 = __float_as_uint(v1) & 0xFFFFE000u;
                unsigned h2 = __float_as_uint(v2) & 0xFFFFE000u;
                unsigned h3 = __float_as_uint(v3) & 0xFFFFE000u;
                ah[mt][0] = h0; ah[mt][1] = h1; ah[mt][2] = h2; ah[mt][3] = h3;
                al[mt][0] = __float_as_uint(v0 - __uint_as_float(h0));
                al[mt][1] = __float_as_uint(v1 - __uint_as_float(h1));
                al[mt][2] = __float_as_uint(v2 - __uint_as_float(h2));
                al[mt][3] = __float_as_uint(v3 - __uint_as_float(h3));
            }
            unsigned bh[2][2], bl[2][2];
#pragma unroll
            for (int nt = 0; nt < 2; nt++) {
                const int c0 = (kk + tig) * 16 + nt * 8 + gid;
                const int c1 = (kk + tig + 4) * 16 + nt * 8 + gid;
                bh[nt][0] = __float_as_uint(Whi[c0]);
                bh[nt][1] = __float_as_uint(Whi[c1]);
                bl[nt][0] = __float_as_uint(__half2float(Wlo[c0]) * (1.0f / 2048.0f));
                bl[nt][1] = __float_as_uint(__half2float(Wlo[c1]) * (1.0f / 2048.0f));
            }
#pragma unroll
            for (int mt = 0; mt < 2; mt++)
#pragma unroll
                for (int nt = 0; nt < 2; nt++) {
                    mma_tf32(acc[mt][nt], ah[mt], bh[nt]);   // hi*hi
                    mma_tf32(acc[mt][nt], al[mt], bh[nt]);   // h_lo*W_hi
                    mma_tf32(acc[mt][nt], ah[mt], bl[nt]);   // h_hi*W_lo
                }
        }

        // ---- cross-warp k-reduction via Red (aliases Hsh) ----
        __syncthreads();
        float* Red = Hsh;   // Red[kq*512 + b*16 + n], 8192 floats
#pragma unroll
        for (int mt = 0; mt < 2; mt++)
#pragma unroll
            for (int nt = 0; nt < 2; nt++)
#pragma unroll
                for (int r = 0; r < 4; r++) {
                    const int b = mt * 16 + gid + ((r >> 1) << 3);
                    const int n = nt * 8 + tig * 2 + (r & 1);
                    Red[kq * 512 + b * 16 + n] = acc[mt][nt][r];
                }
        __syncthreads();

        // ---- epilogue: one output per thread ----
        {
            float v = 0.f;
#pragma unroll
            for (int kq2 = 0; kq2 < 16; kq2++) v += Red[kq2 * 512 + tid];
            const float hnew = fmaxf(v + gB + gT + bb, 0.f);
            float* dst = HB + (s & 1) * 65536 + d * 32768;
            dst[eb * 1024 + encl] = hnew;
            const int row = layer ? (eb * 128 + t) : (t * 32 + eb);
            Y[(size_t)row * 2048 + ecol] = __uint_as_float(f2tf32(hnew));
        }

        // ---- per-direction grid barrier (64 blocks) ----
        __syncthreads();
        if (tid == 0) {
            const unsigned target = bar_sense ^ 1;
            unsigned old = atom_add_acqrel(bcount, 1);
            if (old == 63) {
                st_relaxed_u32(bcount, 0);
                st_release_u32(bsense, target);
            } else {
                while (ld_acquire_u32(bsense) != target) { }
            }
        }
        bar_sense ^= 1;
        __syncthreads();
    }
}

// ---------------- launch helpers ----------------
static inline void gemm_small(const float* A, const float* B, const float* bias,
                              float* C, int M, int N, int K)
{
    dim3 grid(N / 128, (M + 127) / 128);
    gemm_tf32_kernel<<<grid, 256>>>(A, B, bias, C, M, N, K);
}

typedef CUresult (CUDAAPI *PFN_encodeTiled)(
    CUtensorMap*, CUtensorMapDataType, cuuint32_t, void*,
    const cuuint64_t*, const cuuint64_t*, const cuuint32_t*, const cuuint32_t*,
    CUtensorMapInterleave, CUtensorMapSwizzle, CUtensorMapL2promotion,
    CUtensorMapFloatOOBfill);

static inline CUtensorMap make_map2d(PFN_encodeTiled enc, const float* ptr,
                                     int rows, int K, int boxRows)
{
    CUtensorMap m{};
    cuuint64_t dims[2]    = {(cuuint64_t)K, (cuuint64_t)rows};
    cuuint64_t strides[1] = {(cuuint64_t)K * 4};
    cuuint32_t box[2]     = {32u, (cuuint32_t)boxRows};
    cuuint32_t es[2]      = {1u, 1u};
    enc(&m, CU_TENSOR_MAP_DATA_TYPE_FLOAT32, 2, (void*)ptr,
        dims, strides, box, es,
        CU_TENSOR_MAP_INTERLEAVE_NONE, CU_TENSOR_MAP_SWIZZLE_128B,
        CU_TENSOR_MAP_L2_PROMOTION_L2_128B, CU_TENSOR_MAP_FLOAT_OOB_FILL_NONE);
    return m;
}

extern "C" void kernel_launch(void* const* d_in, const int* in_sizes, int n_in,
                              void* d_out, int out_size)
{
    (void)in_sizes; (void)n_in; (void)out_size;
    const float* x     = (const float*)d_in[0];
    const float* W_exp = (const float*)d_in[1];
    const float* b_exp = (const float*)d_in[2];
    const float* g1    = (const float*)d_in[3];
    const float* be1   = (const float*)d_in[4];
    const float* pos   = (const float*)d_in[5];
    const float* Wih0  = (const float*)d_in[6];
    const float* Whh0  = (const float*)d_in[7];
    const float* bih0  = (const float*)d_in[8];
    const float* bhh0  = (const float*)d_in[9];
    const float* Wih1  = (const float*)d_in[10];
    const float* Whh1  = (const float*)d_in[11];
    const float* bih1  = (const float*)d_in[12];
    const float* bhh1  = (const float*)d_in[13];
    const float* Wp1   = (const float*)d_in[14];
    const float* bp1   = (const float*)d_in[15];
    const float* g2    = (const float*)d_in[16];
    const float* be2   = (const float*)d_in[17];
    const float* Wp2   = (const float*)d_in[18];
    const float* bp2   = (const float*)d_in[19];
    float* out = (float*)d_out;

    float* S = nullptr;
    cudaGetSymbolAddress((void**)&S, g_scratch);

    float* PRE   = S + OFF_PRE;
    float* EXP   = S + OFF_EXP;
    float* A0IN  = S + OFF_A0IN;
    float* C0    = S + OFF_C0;
    float* HB    = S + OFF_P;
    float* X1    = S + OFF_X1;
    float* G1    = S + OFF_G1;
    float* OUT2  = S + OFF_OUT2;
    float* PROJ  = S + OFF_PROJ;
    float* HE    = S + OFF_HE;
    float* WIH1T = S + OFF_WIH1T;
    float* WP1T  = S + OFF_WP1T;
    float* WP2T  = S + OFF_WP2T;

    PFN_encodeTiled enc = nullptr;
    cudaGetDriverEntryPoint("cuTensorMapEncodeTiled", (void**)&enc, cudaEnableDefault);

    CUtensorMap tmA_G1  = make_map2d(enc, X1,    4096,  2048, 128);
    CUtensorMap tmB_G1  = make_map2d(enc, WIH1T, 2048,  2048, 256);
    CUtensorMap tmA_PRJ = make_map2d(enc, OUT2,  4096,  2048, 128);
    CUtensorMap tmB_PRJ = make_map2d(enc, WP1T,  512,   2048, 256);
    CUtensorMap tmA_LOG = make_map2d(enc, HE,    4096,  512,  128);
    CUtensorMap tmB_LOG = make_map2d(enc, WP2T,  32000, 512,  256);

    cudaFuncSetAttribute(rnn_layer_kernel,
                         cudaFuncAttributeMaxDynamicSharedMemorySize, RNN2_SMEM_BYTES);
    cudaFuncSetAttribute(gemm_tma_kernel,
                         cudaFuncAttributeMaxDynamicSharedMemorySize, TG_SMEM_BYTES);

    // 0) pre-round weights for TMA GEMMs
    round_tf32_kernel<<<512, 256>>>(Wih1, WIH1T, 2 * 1024 * 2048 / 4);
    round_tf32_kernel<<<512, 256>>>(Wp1,  WP1T,  512 * 2048 / 4);
    round_tf32_kernel<<<512, 256>>>(Wp2,  WP2T,  32000 * 512 / 4);

    // 1) expand
    gemm_small(x, W_exp, b_exp, PRE, 32, 1024, 512);
    ln_relu_kernel<<<32, 256>>>(PRE, g1, be1, EXP, 1024, 0);

    // 2) layer-0 gate factors
    concat_kernel<<<640, 256>>>(EXP, pos, A0IN);
    gemm_small(A0IN, Wih0, nullptr, C0, 160, 2048, 1024);

    // 3) layer-0 recurrence (persistent, 3xTF32)
    pack_h0_kernel<<<128, 256>>>(EXP, HB);
    rnn_layer_kernel<<<128, 512, RNN2_SMEM_BYTES>>>(Whh0, C0, bih0, bhh0, HB, X1, 0);

    // 4) layer-1 gates (TMA GEMM)
    {
        dim3 grid(2048 / 256, 4096 / 128);
        gemm_tma_kernel<<<grid, 512, TG_SMEM_BYTES>>>(tmA_G1, tmB_G1, nullptr, G1, 2048, 2048);
    }

    // 5) layer-1 recurrence (persistent, 3xTF32)
    pack_h0_kernel<<<128, 256>>>(EXP, HB);
    rnn_layer_kernel<<<128, 512, RNN2_SMEM_BYTES>>>(Whh1, G1, bih1, bhh1, HB, OUT2, 1);

    // 6) projection head (TMA GEMM)
    {
        dim3 grid(512 / 256, 4096 / 128);
        gemm_tma_kernel<<<grid, 512, TG_SMEM_BYTES>>>(tmA_PRJ, tmB_PRJ, bp1, PROJ, 512, 2048);
    }
    ln_relu_kernel<<<4096, 256>>>(PROJ, g2, be2, HE, 512, 1);

    // 7) logits (TMA GEMM)
    {
        dim3 grid(32000 / 256, 4096 / 128);
        gemm_tma_kernel<<<grid, 512, TG_SMEM_BYTES>>>(tmA_LOG, tmB_LOG, bp2, out, 32000, 512);
    }
}

// round 10
// speedup vs baseline: 4.7186x; 1.1957x over previous
#include <cuda_runtime.h>
#include <cuda.h>
#include <cuda_fp16.h>
#include <cstdint>

#define T_LEN 128

// ---------------- scratch layout (floats) ----------------
#define OFF_PRE   0                                   // [32][1024] f32
#define OFF_EXP   (OFF_PRE  + 32*1024)                // [32][1024] f32
#define OFF_A0IN  (OFF_EXP  + 32*1024)                // [160][1024] f32
#define OFF_C0    (OFF_A0IN + 160*1024)               // [160][2048] f32
#define OFF_HB    (OFF_C0   + 160*2048)               // 2 sets x [2][32][1024] f32
#define OFF_X1H   (OFF_HB   + 2*2*32*1024)            // half[4096][2048]
#define OFF_G1    (OFF_X1H  + 4096*1024)              // f32 [4096][2048]
#define OFF_OUT2H (OFF_G1   + 4096*2048)              // half[4096][2048]
#define OFF_PROJ  (OFF_OUT2H + 4096*1024)             // f32 [4096][512]
#define OFF_HEH   (OFF_PROJ + 4096*512)               // half[4096][512]
#define OFF_WIH1H (OFF_HEH  + 4096*256)               // half[2048][2048]
#define OFF_WP1H  (OFF_WIH1H + 2048*1024)             // half[512][2048]
#define OFF_WP2H  (OFF_WP1H  + 512*1024)              // half[32000][512]
#define SCRATCH_TOTAL (OFF_WP2H + 32000*256)

__device__ __align__(1024) float g_scratch[SCRATCH_TOTAL];
__device__ unsigned g_bar_count2[2];
__device__ unsigned g_bar_sense2[2];

// ---------------- helpers ----------------
__device__ __forceinline__ unsigned f2tf32(float f) {
    unsigned u;
    asm("cvt.rna.tf32.f32 %0, %1;" : "=r"(u) : "f"(f));
    return u;
}

__device__ __forceinline__ void mma_tf32(float c[4], const unsigned a[4], const unsigned b[2]) {
    asm volatile(
        "mma.sync.aligned.m16n8k8.row.col.f32.tf32.tf32.f32 "
        "{%0,%1,%2,%3}, {%4,%5,%6,%7}, {%8,%9}, {%0,%1,%2,%3};"
        : "+f"(c[0]), "+f"(c[1]), "+f"(c[2]), "+f"(c[3])
        : "r"(a[0]), "r"(a[1]), "r"(a[2]), "r"(a[3]), "r"(b[0]), "r"(b[1]));
}

__device__ __forceinline__ void mma_f16(float c[4], const unsigned a[4], const unsigned b[2]) {
    asm volatile(
        "mma.sync.aligned.m16n8k16.row.col.f32.f16.f16.f32 "
        "{%0,%1,%2,%3}, {%4,%5,%6,%7}, {%8,%9}, {%0,%1,%2,%3};"
        : "+f"(c[0]), "+f"(c[1]), "+f"(c[2]), "+f"(c[3])
        : "r"(a[0]), "r"(a[1]), "r"(a[2]), "r"(a[3]), "r"(b[0]), "r"(b[1]));
}

// ---------------- fp32 -> fp16 convert ----------------
__global__ __launch_bounds__(256) void tohalf_kernel(
    const float* __restrict__ in, __half2* __restrict__ out, int n4)
{
    for (int i = blockIdx.x * 256 + threadIdx.x; i < n4; i += gridDim.x * 256) {
        float4 v = ((const float4*)in)[i];
        out[2 * i]     = __floats2half2_rn(v.x, v.y);
        out[2 * i + 1] = __floats2half2_rn(v.z, v.w);
    }
}

// =================== TMA-fed fp16 GEMM (mma.sync f16, f32 accum) ===================
// C[M,N] = A[M,K] @ B[N,K]^T (+bias). CTA tile 128x256, K-chunk 64 halves (128B row).
// 4-stage TMA ring. M%128==0, N%256==0, K%64==0.
#define TG_STAGES 4
#define TG_STAGE_BYTES 49152                   // A 128*128B + B 256*128B
#define TG_SMEM_BYTES  (1024 + TG_STAGES * TG_STAGE_BYTES)

__device__ __forceinline__ uint32_t smem_u32(const void* p) {
    return (uint32_t)__cvta_generic_to_shared((void*)p);
}
__device__ __forceinline__ void tma2d(uint32_t sdst, const CUtensorMap* tm,
                                      int x, int y, uint32_t bar) {
    asm volatile(
        "cp.async.bulk.tensor.2d.shared::cta.global.tile.mbarrier::complete_tx::bytes "
        "[%0], [%1, {%2, %3}], [%4];"
        :: "r"(sdst), "l"(tm), "r"(x), "r"(y), "r"(bar) : "memory");
}
#define MBAR_INIT(a, c) \
    asm volatile("mbarrier.init.shared.b64 [%0], %1;" :: "r"(a), "r"(c) : "memory")
#define MBAR_EXPECT_TX(a, b) \
    asm volatile("mbarrier.arrive.expect_tx.shared.b64 _, [%0], %1;" :: "r"(a), "r"(b) : "memory")
#define MBAR_ARRIVE(a) \
    asm volatile("mbarrier.arrive.shared.b64 _, [%0];" :: "r"(a) : "memory")
#define MBAR_WAIT(a, ph) do { \
    uint32_t _d_; \
    asm volatile("{\n\t.reg .pred p;\n\tmbarrier.try_wait.parity.acquire.cta.shared::cta.b64 p, [%1], %2;\n\tselp.b32 %0, 1, 0, p;\n\t}" \
        : "=r"(_d_) : "r"(a), "r"(ph) : "memory"); \
    while (!_d_) { \
        asm volatile("{\n\t.reg .pred p;\n\tmbarrier.try_wait.parity.acquire.cta.shared::cta.b64 p, [%1], %2, 0x989680;\n\tselp.b32 %0, 1, 0, p;\n\t}" \
            : "=r"(_d_) : "r"(a), "r"(ph) : "memory"); \
    } \
} while (0)

__global__ __launch_bounds__(512, 1) void gemm_tma_f16_kernel(
    const __grid_constant__ CUtensorMap tmA,
    const __grid_constant__ CUtensorMap tmB,
    const float* __restrict__ bias, float* __restrict__ C,
    int N, int K)
{
    extern __shared__ char dsm[];
    __shared__ __align__(8) unsigned long long bars[8];  // full[4], empty[4]

    const int tid  = threadIdx.x;
    const int warp = tid >> 5;
    const int lane = tid & 31;
    const int wm   = warp & 3;
    const int wn   = warp >> 2;
    const int gid  = lane >> 2;
    const int tig  = lane & 3;
    const int mblk = blockIdx.y * 128;
    const int nblk = blockIdx.x * 256;
    const int KT   = K / 64;

    const uint32_t raw   = smem_u32(dsm);
    const uint32_t sbase = (raw + 1023) & ~1023u;
    char* tile0 = dsm + (sbase - raw);
    const uint32_t barb = smem_u32(bars);

    if (tid == 0) {
        for (int i = 0; i < 4; i++) MBAR_INIT(barb + i * 8, 1);
        for (int i = 4; i < 8; i++) MBAR_INIT(barb + i * 8, 16);
    }
    __syncthreads();

    if (tid == 0) {
        const int pre = KT < TG_STAGES ? KT : TG_STAGES;
        for (int st = 0; st < pre; st++) {
            const uint32_t full = barb + st * 8;
            MBAR_EXPECT_TX(full, TG_STAGE_BYTES);
            const uint32_t sa = sbase + st * TG_STAGE_BYTES;
            tma2d(sa,         &tmA, st * 64, mblk, full);
            tma2d(sa + 16384, &tmB, st * 64, nblk, full);
        }
    }

    float acc[2][8][4];
#pragma unroll
    for (int i = 0; i < 2; i++)
#pragma unroll
        for (int j = 0; j < 8; j++)
#pragma unroll
            for (int r = 0; r < 4; r++) acc[i][j][r] = 0.f;

    const uint32_t xorv = (uint32_t)gid << 4;

    for (int kt = 0; kt < KT; kt++) {
        const int st = kt & 3;
        const uint32_t ph = (kt >> 2) & 1;
        MBAR_WAIT(barb + st * 8, ph);

        const char* As = tile0 + st * TG_STAGE_BYTES;
        const char* Bs = As + 16384;

#pragma unroll
        for (int ks = 0; ks < 4; ks++) {   // each ks = k16 (32 bytes of the 128B row)
            const uint32_t c4a = (uint32_t)(ks * 32 + tig * 4) ^ xorv;
            const uint32_t c4b = (uint32_t)(ks * 32 + tig * 4 + 16) ^ xorv;
            unsigned afr[2][4], bfr[8][2];
#pragma unroll
            for (int mf = 0; mf < 2; mf++) {
                const int r0 = wm * 32 + mf * 16 + gid;
                afr[mf][0] = *(const unsigned*)(As + r0 * 128 + c4a);
                afr[mf][1] = *(const unsigned*)(As + (r0 + 8) * 128 + c4a);
                afr[mf][2] = *(const unsigned*)(As + r0 * 128 + c4b);
                afr[mf][3] = *(const unsigned*)(As + (r0 + 8) * 128 + c4b);
            }
#pragma unroll
            for (int nf = 0; nf < 8; nf++) {
                const int nc = wn * 64 + nf * 8 + gid;
                bfr[nf][0] = *(const unsigned*)(Bs + nc * 128 + c4a);
                bfr[nf][1] = *(const unsigned*)(Bs + nc * 128 + c4b);
            }
#pragma unroll
            for (int mf = 0; mf < 2; mf++)
#pragma unroll
                for (int nf = 0; nf < 8; nf++)
                    mma_f16(acc[mf][nf], afr[mf], bfr[nf]);
        }

        __syncwarp();
        if (lane == 0) MBAR_ARRIVE(barb + (4 + st) * 8);

        if (tid == 0 && kt + TG_STAGES < KT) {
            MBAR_WAIT(barb + (4 + st) * 8, ph);
            const uint32_t full = barb + st * 8;
            MBAR_EXPECT_TX(full, TG_STAGE_BYTES);
            const uint32_t sa = sbase + st * TG_STAGE_BYTES;
            tma2d(sa,         &tmA, (kt + TG_STAGES) * 64, mblk, full);
            tma2d(sa + 16384, &tmB, (kt + TG_STAGES) * 64, nblk, full);
        }
    }

#pragma unroll
    for (int nf = 0; nf < 8; nf++) {
        const int col = nblk + wn * 64 + nf * 8 + tig * 2;
        const float b0 = bias ? bias[col] : 0.f;
        const float b1 = bias ? bias[col + 1] : 0.f;
#pragma unroll
        for (int mf = 0; mf < 2; mf++) {
            const int row = mblk + wm * 32 + mf * 16 + gid;
            {
                float2 v = make_float2(acc[mf][nf][0] + b0, acc[mf][nf][1] + b1);
                *(float2*)(C + (size_t)row * N + col) = v;
            }
            {
                float2 v = make_float2(acc[mf][nf][2] + b0, acc[mf][nf][3] + b1);
                *(float2*)(C + (size_t)(row + 8) * N + col) = v;
            }
        }
    }
}

// ---------------- small tf32 GEMM (legacy mma): C = A @ B^T (+bias) ----------
#define SPITCH 136
__global__ __launch_bounds__(256, 2) void gemm_tf32_kernel(
    const float* __restrict__ A, const float* __restrict__ B,
    const float* __restrict__ bias, float* __restrict__ C,
    int M, int N, int K)
{
    __shared__ unsigned As[16][SPITCH];
    __shared__ unsigned Bs[16][SPITCH];

    const int tid  = threadIdx.x;
    const int warp = tid >> 5;
    const int lane = tid & 31;
    const int wm = warp & 1;
    const int wn = warp >> 1;
    const int gid = lane >> 2;
    const int tig = lane & 3;

    const int mblk = blockIdx.y * 128;
    const int nblk = blockIdx.x * 128;

    const int lr = tid >> 1;
    const int kc = (tid & 1) * 8;
    const int rowA = mblk + lr;
    const bool aval = rowA < M;
    const float* Ap = A + (size_t)(aval ? rowA : 0) * K + kc;
    const float* Bp = B + (size_t)(nblk + lr) * K + kc;

    float acc[4][4][4];
#pragma unroll
    for (int i = 0; i < 4; i++)
#pragma unroll
        for (int j = 0; j < 4; j++)
#pragma unroll
            for (int r = 0; r < 4; r++) acc[i][j][r] = 0.f;

    float4 av0 = aval ? *(const float4*)Ap : make_float4(0,0,0,0);
    float4 av1 = aval ? *(const float4*)(Ap + 4) : make_float4(0,0,0,0);
    float4 bv0 = *(const float4*)Bp;
    float4 bv1 = *(const float4*)(Bp + 4);
    Ap += 16; Bp += 16;

    for (int k0 = 0; k0 < K; k0 += 16) {
        As[kc + 0][lr] = f2tf32(av0.x); As[kc + 1][lr] = f2tf32(av0.y);
        As[kc + 2][lr] = f2tf32(av0.z); As[kc + 3][lr] = f2tf32(av0.w);
        As[kc + 4][lr] = f2tf32(av1.x); As[kc + 5][lr] = f2tf32(av1.y);
        As[kc + 6][lr] = f2tf32(av1.z); As[kc + 7][lr] = f2tf32(av1.w);
        Bs[kc + 0][lr] = f2tf32(bv0.x); Bs[kc + 1][lr] = f2tf32(bv0.y);
        Bs[kc + 2][lr] = f2tf32(bv0.z); Bs[kc + 3][lr] = f2tf32(bv0.w);
        Bs[kc + 4][lr] = f2tf32(bv1.x); Bs[kc + 5][lr] = f2tf32(bv1.y);
        Bs[kc + 6][lr] = f2tf32(bv1.z); Bs[kc + 7][lr] = f2tf32(bv1.w);
        __syncthreads();

        if (k0 + 16 < K) {
            av0 = aval ? *(const float4*)Ap : make_float4(0,0,0,0);
            av1 = aval ? *(const float4*)(Ap + 4) : make_float4(0,0,0,0);
            bv0 = *(const float4*)Bp;
            bv1 = *(const float4*)(Bp + 4);
            Ap += 16; Bp += 16;
        }

#pragma unroll
        for (int ks = 0; ks < 2; ks++) {
            const int kb = ks * 8;
            unsigned afr[4][4], bfr[4][2];
#pragma unroll
            for (int mt = 0; mt < 4; mt++) {
                const int mr = wm * 64 + mt * 16 + gid;
                afr[mt][0] = As[kb + tig][mr];
                afr[mt][1] = As[kb + tig][mr + 8];
                afr[mt][2] = As[kb + tig + 4][mr];
                afr[mt][3] = As[kb + tig + 4][mr + 8];
            }
#pragma unroll
            for (int nt = 0; nt < 4; nt++) {
                const int nc = wn * 32 + nt * 8 + gid;
                bfr[nt][0] = Bs[kb + tig][nc];
                bfr[nt][1] = Bs[kb + tig + 4][nc];
            }
#pragma unroll
            for (int mt = 0; mt < 4; mt++)
#pragma unroll
                for (int nt = 0; nt < 4; nt++)
                    mma_tf32(acc[mt][nt], afr[mt], bfr[nt]);
        }
        __syncthreads();
    }

#pragma unroll
    for (int nt = 0; nt < 4; nt++) {
        const int col = nblk + wn * 32 + nt * 8 + tig * 2;
        const float b0 = bias ? bias[col] : 0.f;
        const float b1 = bias ? bias[col + 1] : 0.f;
#pragma unroll
        for (int mt = 0; mt < 4; mt++) {
            const int row = mblk + wm * 64 + mt * 16 + gid;
            if (row < M) {
                float2 v = make_float2(acc[mt][nt][0] + b0, acc[mt][nt][1] + b1);
                *(float2*)(C + (size_t)row * N + col) = v;
            }
            if (row + 8 < M) {
                float2 v = make_float2(acc[mt][nt][2] + b0, acc[mt][nt][3] + b1);
                *(float2*)(C + (size_t)(row + 8) * N + col) = v;
            }
        }
    }
}

// ---------------- LayerNorm + ReLU (fp32 out) ----------------
__global__ __launch_bounds__(256) void ln_relu_kernel(
    const float* __restrict__ in, const float* __restrict__ g,
    const float* __restrict__ be, float* __restrict__ out, int C)
{
    __shared__ float red[256];
    const int row = blockIdx.x;
    const int tid = threadIdx.x;
    const float* rp = in + (size_t)row * C;
    float s = 0.f, sq = 0.f;
    for (int c = tid; c < C; c += 256) { float v = rp[c]; s += v; sq += v * v; }
    red[tid] = s; __syncthreads();
    for (int o = 128; o > 0; o >>= 1) { if (tid < o) red[tid] += red[tid + o]; __syncthreads(); }
    float mean = red[0] / (float)C;
    __syncthreads();
    red[tid] = sq; __syncthreads();
    for (int o = 128; o > 0; o >>= 1) { if (tid < o) red[tid] += red[tid + o]; __syncthreads(); }
    float var = red[0] / (float)C - mean * mean;
    float rs = rsqrtf(var + 1e-5f);
    float* op = out + (size_t)row * C;
    for (int c = tid; c < C; c += 256) {
        float v = (rp[c] - mean) * rs * g[c] + be[c];
        op[c] = fmaxf(v, 0.f);
    }
}

// ---------------- LayerNorm + ReLU (fp16 out) ----------------
__global__ __launch_bounds__(256) void ln_relu_f16_kernel(
    const float* __restrict__ in, const float* __restrict__ g,
    const float* __restrict__ be, __half* __restrict__ out, int C)
{
    __shared__ float red[256];
    const int row = blockIdx.x;
    const int tid = threadIdx.x;
    const float* rp = in + (size_t)row * C;
    float s = 0.f, sq = 0.f;
    for (int c = tid; c < C; c += 256) { float v = rp[c]; s += v; sq += v * v; }
    red[tid] = s; __syncthreads();
    for (int o = 128; o > 0; o >>= 1) { if (tid < o) red[tid] += red[tid + o]; __syncthreads(); }
    float mean = red[0] / (float)C;
    __syncthreads();
    red[tid] = sq; __syncthreads();
    for (int o = 128; o > 0; o >>= 1) { if (tid < o) red[tid] += red[tid + o]; __syncthreads(); }
    float var = red[0] / (float)C - mean * mean;
    float rs = rsqrtf(var + 1e-5f);
    __half* op = out + (size_t)row * C;
    for (int c = tid; c < C; c += 256) {
        float v = (rp[c] - mean) * rs * g[c] + be[c];
        op[c] = __float2half_rn(fmaxf(v, 0.f));
    }
}

// ---------------- concat [expanded(32); pos(128)] ----------------
__global__ __launch_bounds__(256) void concat_kernel(
    const float* __restrict__ e, const float* __restrict__ pos, float* __restrict__ o)
{
    int i = blockIdx.x * 256 + threadIdx.x;
    o[i] = (i < 32 * 1024) ? e[i] : pos[i - 32 * 1024];
}

// ---------------- pack h0 into exchange buffer set 0: plain [d][b][k] --------------
__global__ __launch_bounds__(256) void pack_h0_kernel(
    const float* __restrict__ EXP, float* __restrict__ HB)
{
    int i = blockIdx.x * 256 + threadIdx.x;   // 128 blocks -> 32768
    const float v = EXP[i];
    HB[i] = v;
    HB[32768 + i] = v;
}

// ---------------- persistent RNN layer (3xTF32, 512 thr, per-dir barriers) ---------
#define RNN2_HSH_PITCH 1028
#define RNN2_WHI_OFF   131584
#define RNN2_WLO_OFF   (131584 + 65536)
#define RNN2_SMEM_BYTES (RNN2_WLO_OFF + 32768)

__device__ __forceinline__ unsigned ld_acquire_u32(unsigned* p) {
    unsigned v;
    asm volatile("ld.acquire.gpu.global.u32 %0, [%1];" : "=r"(v) : "l"(p) : "memory");
    return v;
}
__device__ __forceinline__ unsigned atom_add_acqrel(unsigned* p, unsigned v) {
    unsigned o;
    asm volatile("atom.acq_rel.gpu.global.add.u32 %0, [%1], %2;" : "=r"(o) : "l"(p), "r"(v) : "memory");
    return o;
}
__device__ __forceinline__ void st_relaxed_u32(unsigned* p, unsigned v) {
    asm volatile("st.relaxed.gpu.global.u32 [%0], %1;" :: "l"(p), "r"(v) : "memory");
}
__device__ __forceinline__ void st_release_u32(unsigned* p, unsigned v) {
    asm volatile("st.release.gpu.global.u32 [%0], %1;" :: "l"(p), "r"(v) : "memory");
}

__global__ __launch_bounds__(512, 1) void rnn_layer_kernel(
    const float* __restrict__ Whh, const float* __restrict__ gate,
    const float* __restrict__ bih, const float* __restrict__ bhh,
    float* __restrict__ HB, __half* __restrict__ Y, int layer)
{
    extern __shared__ char sm2[];
    float*  Hsh = (float*)sm2;
    float*  Whi = (float*)(sm2 + RNN2_WHI_OFF);
    __half* Wlo = (__half*)(sm2 + RNN2_WLO_OFF);

    const int tid  = threadIdx.x;
    const int bid  = blockIdx.x;
    const int d    = bid >> 6;
    const int n0   = (bid & 63) * 16;
    const int kq   = tid >> 5;        // 0..15, k-slice [kq*64, +64)
    const int lane = tid & 31;
    const int gid  = lane >> 2;
    const int tig  = lane & 3;

    for (int i = tid; i < 16384; i += 512) {
        const int n = i >> 10, k = i & 1023;
        const float w = Whh[(size_t)(d * 1024 + n0 + n) * 1024 + k];
        const float hi = __uint_as_float(__float_as_uint(w) & 0xFFFFE000u);
        Whi[k * 16 + n] = hi;
        Wlo[k * 16 + n] = __float2half_rn((w - hi) * 2048.0f);
    }
    __syncthreads();

    const int eb   = tid >> 4;
    const int encl = n0 + (tid & 15);
    const int ecol = d * 1024 + encl;
    const float bb = bih[ecol] + bhh[ecol];
    float gB = 0.f;
    if (layer == 0) gB = gate[(size_t)eb * 2048 + ecol];

    unsigned bar_sense = 0;
    unsigned* bcount = &g_bar_count2[d];
    unsigned* bsense = &g_bar_sense2[d];

    for (int s = 1; s <= T_LEN; s++) {
        const int t = d ? (T_LEN - s) : (s - 1);

        float gT;
        if (layer == 0) gT = gate[(size_t)(32 + t) * 2048 + ecol];
        else            gT = gate[(size_t)(t * 32 + eb) * 2048 + ecol];

        const float* src = HB + ((s - 1) & 1) * 65536 + d * 32768;
        for (int j = lane; j < 512; j += 32) {
            const int b = j >> 4, q = j & 15;
            float4 v = *(const float4*)&src[b * 1024 + kq * 64 + q * 4];
            *(float4*)&Hsh[b * RNN2_HSH_PITCH + kq * 64 + q * 4] = v;
        }
        __syncwarp();

        float acc[2][2][4];
#pragma unroll
        for (int i = 0; i < 2; i++)
#pragma unroll
            for (int j = 0; j < 2; j++)
#pragma unroll
                for (int r = 0; r < 4; r++) acc[i][j][r] = 0.f;

#pragma unroll
        for (int kf = 0; kf < 8; kf++) {
            const int kk = kq * 64 + kf * 8;
            unsigned ah[2][4], al[2][4];
#pragma unroll
            for (int mt = 0; mt < 2; mt++) {
                const int r0 = (mt * 16 + gid) * RNN2_HSH_PITCH + kk;
                float v0 = Hsh[r0 + tig];
                float v1 = Hsh[r0 + 8 * RNN2_HSH_PITCH + tig];
                float v2 = Hsh[r0 + tig + 4];
                float v3 = Hsh[r0 + 8 * RNN2_HSH_PITCH + tig + 4];
                unsigned h0 = __float_as_uint(v0) & 0xFFFFE000u;
                unsigned h1 = __float_as_uint(v1) & 0xFFFFE000u;
                unsigned h2 = __float_as_uint(v2) & 0xFFFFE000u;
                unsigned h3 = __float_as_uint(v3) & 0xFFFFE000u;
                ah[mt][0] = h0; ah[mt][1] = h1; ah[mt][2] = h2; ah[mt][3] = h3;
                al[mt][0] = __float_as_uint(v0 - __uint_as_float(h0));
                al[mt][1] = __float_as_uint(v1 - __uint_as_float(h1));
                al[mt][2] = __float_as_uint(v2 - __uint_as_float(h2));
                al[mt][3] = __float_as_uint(v3 - __uint_as_float(h3));
            }
            unsigned bh[2][2], bl[2][2];
#pragma unroll
            for (int nt = 0; nt < 2; nt++) {
                const int c0 = (kk + tig) * 16 + nt * 8 + gid;
                const int c1 = (kk + tig + 4) * 16 + nt * 8 + gid;
                bh[nt][0] = __float_as_uint(Whi[c0]);
                bh[nt][1] = __float_as_uint(Whi[c1]);
                bl[nt][0] = __float_as_uint(__half2float(Wlo[c0]) * (1.0f / 2048.0f));
                bl[nt][1] = __float_as_uint(__half2float(Wlo[c1]) * (1.0f / 2048.0f));
            }
#pragma unroll
            for (int mt = 0; mt < 2; mt++)
#pragma unroll
                for (int nt = 0; nt < 2; nt++) {
                    mma_tf32(acc[mt][nt], ah[mt], bh[nt]);
                    mma_tf32(acc[mt][nt], al[mt], bh[nt]);
                    mma_tf32(acc[mt][nt], ah[mt], bl[nt]);
                }
        }

        __syncthreads();
        float* Red = Hsh;
#pragma unroll
        for (int mt = 0; mt < 2; mt++)
#pragma unroll
            for (int nt = 0; nt < 2; nt++)
#pragma unroll
                for (int r = 0; r < 4; r++) {
                    const int b = mt * 16 + gid + ((r >> 1) << 3);
                    const int n = nt * 8 + tig * 2 + (r & 1);
                    Red[kq * 512 + b * 16 + n] = acc[mt][nt][r];
                }
        __syncthreads();

        {
            float v = 0.f;
#pragma unroll
            for (int kq2 = 0; kq2 < 16; kq2++) v += Red[kq2 * 512 + tid];
            const float hnew = fmaxf(v + gB + gT + bb, 0.f);
            float* dst = HB + (s & 1) * 65536 + d * 32768;
            dst[eb * 1024 + encl] = hnew;
            const int row = layer ? (eb * 128 + t) : (t * 32 + eb);
            Y[(size_t)row * 2048 + ecol] = __float2half_rn(hnew);
        }

        __syncthreads();
        if (tid == 0) {
            const unsigned target = bar_sense ^ 1;
            unsigned old = atom_add_acqrel(bcount, 1);
            if (old == 63) {
                st_relaxed_u32(bcount, 0);
                st_release_u32(bsense, target);
            } else {
                while (ld_acquire_u32(bsense) != target) { }
            }
        }
        bar_sense ^= 1;
        __syncthreads();
    }
}

// ---------------- launch helpers ----------------
static inline void gemm_small(const float* A, const float* B, const float* bias,
                              float* C, int M, int N, int K)
{
    dim3 grid(N / 128, (M + 127) / 128);
    gemm_tf32_kernel<<<grid, 256>>>(A, B, bias, C, M, N, K);
}

typedef CUresult (CUDAAPI *PFN_encodeTiled)(
    CUtensorMap*, CUtensorMapDataType, cuuint32_t, void*,
    const cuuint64_t*, const cuuint64_t*, const cuuint32_t*, const cuuint32_t*,
    CUtensorMapInterleave, CUtensorMapSwizzle, CUtensorMapL2promotion,
    CUtensorMapFloatOOBfill);

static inline CUtensorMap make_map2d_f16(PFN_encodeTiled enc, const void* ptr,
                                         int rows, int K, int boxRows)
{
    CUtensorMap m{};
    cuuint64_t dims[2]    = {(cuuint64_t)K, (cuuint64_t)rows};
    cuuint64_t strides[1] = {(cuuint64_t)K * 2};
    cuuint32_t box[2]     = {64u, (cuuint32_t)boxRows};
    cuuint32_t es[2]      = {1u, 1u};
    enc(&m, CU_TENSOR_MAP_DATA_TYPE_UINT16, 2, (void*)ptr,
        dims, strides, box, es,
        CU_TENSOR_MAP_INTERLEAVE_NONE, CU_TENSOR_MAP_SWIZZLE_128B,
        CU_TENSOR_MAP_L2_PROMOTION_L2_128B, CU_TENSOR_MAP_FLOAT_OOB_FILL_NONE);
    return m;
}

extern "C" void kernel_launch(void* const* d_in, const int* in_sizes, int n_in,
                              void* d_out, int out_size)
{
    (void)in_sizes; (void)n_in; (void)out_size;
    const float* x     = (const float*)d_in[0];
    const float* W_exp = (const float*)d_in[1];
    const float* b_exp = (const float*)d_in[2];
    const float* g1    = (const float*)d_in[3];
    const float* be1   = (const float*)d_in[4];
    const float* pos   = (const float*)d_in[5];
    const float* Wih0  = (const float*)d_in[6];
    const float* Whh0  = (const float*)d_in[7];
    const float* bih0  = (const float*)d_in[8];
    const float* bhh0  = (const float*)d_in[9];
    const float* Wih1  = (const float*)d_in[10];
    const float* Whh1  = (const float*)d_in[11];
    const float* bih1  = (const float*)d_in[12];
    const float* bhh1  = (const float*)d_in[13];
    const float* Wp1   = (const float*)d_in[14];
    const float* bp1   = (const float*)d_in[15];
    const float* g2    = (const float*)d_in[16];
    const float* be2   = (const float*)d_in[17];
    const float* Wp2   = (const float*)d_in[18];
    const float* bp2   = (const float*)d_in[19];
    float* out = (float*)d_out;

    float* S = nullptr;
    cudaGetSymbolAddress((void**)&S, g_scratch);

    float*  PRE   = S + OFF_PRE;
    float*  EXP   = S + OFF_EXP;
    float*  A0IN  = S + OFF_A0IN;
    float*  C0    = S + OFF_C0;
    float*  HB    = S + OFF_HB;
    __half* X1H   = (__half*)(S + OFF_X1H);
    float*  G1    = S + OFF_G1;
    __half* OUT2H = (__half*)(S + OFF_OUT2H);
    float*  PROJ  = S + OFF_PROJ;
    __half* HEH   = (__half*)(S + OFF_HEH);
    __half* WIH1H = (__half*)(S + OFF_WIH1H);
    __half* WP1H  = (__half*)(S + OFF_WP1H);
    __half* WP2H  = (__half*)(S + OFF_WP2H);

    PFN_encodeTiled enc = nullptr;
    cudaGetDriverEntryPoint("cuTensorMapEncodeTiled", (void**)&enc, cudaEnableDefault);

    CUtensorMap tmA_G1  = make_map2d_f16(enc, X1H,   4096,  2048, 128);
    CUtensorMap tmB_G1  = make_map2d_f16(enc, WIH1H, 2048,  2048, 256);
    CUtensorMap tmA_PRJ = make_map2d_f16(enc, OUT2H, 4096,  2048, 128);
    CUtensorMap tmB_PRJ = make_map2d_f16(enc, WP1H,  512,   2048, 256);
    CUtensorMap tmA_LOG = make_map2d_f16(enc, HEH,   4096,  512,  128);
    CUtensorMap tmB_LOG = make_map2d_f16(enc, WP2H,  32000, 512,  256);

    cudaFuncSetAttribute(rnn_layer_kernel,
                         cudaFuncAttributeMaxDynamicSharedMemorySize, RNN2_SMEM_BYTES);
    cudaFuncSetAttribute(gemm_tma_f16_kernel,
                         cudaFuncAttributeMaxDynamicSharedMemorySize, TG_SMEM_BYTES);

    // 0) pre-convert weights to fp16
    tohalf_kernel<<<512, 256>>>(Wih1, (__half2*)WIH1H, 2 * 1024 * 2048 / 4);
    tohalf_kernel<<<512, 256>>>(Wp1,  (__half2*)WP1H,  512 * 2048 / 4);
    tohalf_kernel<<<512, 256>>>(Wp2,  (__half2*)WP2H,  32000 * 512 / 4);

    // 1) expand
    gemm_small(x, W_exp, b_exp, PRE, 32, 1024, 512);
    ln_relu_kernel<<<32, 256>>>(PRE, g1, be1, EXP, 1024);

    // 2) layer-0 gate factors
    concat_kernel<<<640, 256>>>(EXP, pos, A0IN);
    gemm_small(A0IN, Wih0, nullptr, C0, 160, 2048, 1024);

    // 3) layer-0 recurrence (persistent, 3xTF32), writes X1 as fp16
    pack_h0_kernel<<<128, 256>>>(EXP, HB);
    rnn_layer_kernel<<<128, 512, RNN2_SMEM_BYTES>>>(Whh0, C0, bih0, bhh0, HB, X1H, 0);

    // 4) layer-1 gates (fp16 TMA GEMM): G1[4096,2048] fp32 out
    {
        dim3 grid(2048 / 256, 4096 / 128);
        gemm_tma_f16_kernel<<<grid, 512, TG_SMEM_BYTES>>>(tmA_G1, tmB_G1, nullptr, G1, 2048, 2048);
    }

    // 5) layer-1 recurrence (persistent, 3xTF32), writes OUT2 as fp16
    pack_h0_kernel<<<128, 256>>>(EXP, HB);
    rnn_layer_kernel<<<128, 512, RNN2_SMEM_BYTES>>>(Whh1, G1, bih1, bhh1, HB, OUT2H, 1);

    // 6) projection head (fp16 TMA GEMM) + LN+ReLU -> fp16
    {
        dim3 grid(512 / 256, 4096 / 128);
        gemm_tma_f16_kernel<<<grid, 512, TG_SMEM_BYTES>>>(tmA_PRJ, tmB_PRJ, bp1, PROJ, 512, 2048);
    }
    ln_relu_f16_kernel<<<4096, 256>>>(PROJ, g2, be2, HEH, 512);

    // 7) logits (fp16 TMA GEMM)
    {
        dim3 grid(32000 / 256, 4096 / 128);
        gemm_tma_f16_kernel<<<grid, 512, TG_SMEM_BYTES>>>(tmA_LOG, tmB_LOG, bp2, out, 32000, 512);
    }
}

// round 11
// speedup vs baseline: 5.4571x; 1.1565x over previous
#include <cuda_runtime.h>
#include <cuda.h>
#include <cuda_fp16.h>
#include <cstdint>

#define T_LEN 128

// ---------------- scratch layout (floats) ----------------
#define OFF_PRE   0                                   // [32][1024] f32
#define OFF_EXP   (OFF_PRE  + 32*1024)                // [32][1024] f32
#define OFF_A0IN  (OFF_EXP  + 32*1024)                // [160][1024] f32
#define OFF_C0    (OFF_A0IN + 160*1024)               // [160][2048] f32
#define OFF_HB    (OFF_C0   + 160*2048)               // half: 2 sets x [2 d][2 pl][32][1024]
#define OFF_X1H   (OFF_HB   + 2*2*32*1024)            // half[4096][2048]
#define OFF_G1    (OFF_X1H  + 4096*1024)              // f32 [4096][2048]
#define OFF_OUT2H (OFF_G1   + 4096*2048)              // half[4096][2048]
#define OFF_PROJ  (OFF_OUT2H + 4096*1024)             // f32 [4096][512]
#define OFF_HEH   (OFF_PROJ + 4096*512)               // half[4096][512]
#define OFF_WIH1H (OFF_HEH  + 4096*256)               // half[2048][2048]
#define OFF_WP1H  (OFF_WIH1H + 2048*1024)             // half[512][2048]
#define OFF_WP2H  (OFF_WP1H  + 512*1024)              // half[32000][512]
#define SCRATCH_TOTAL (OFF_WP2H + 32000*256)

__device__ __align__(1024) float g_scratch[SCRATCH_TOTAL];
__device__ unsigned g_bar_count2[2];
__device__ unsigned g_bar_sense2[2];

// ---------------- helpers ----------------
__device__ __forceinline__ unsigned f2tf32(float f) {
    unsigned u;
    asm("cvt.rna.tf32.f32 %0, %1;" : "=r"(u) : "f"(f));
    return u;
}

__device__ __forceinline__ void mma_tf32(float c[4], const unsigned a[4], const unsigned b[2]) {
    asm volatile(
        "mma.sync.aligned.m16n8k8.row.col.f32.tf32.tf32.f32 "
        "{%0,%1,%2,%3}, {%4,%5,%6,%7}, {%8,%9}, {%0,%1,%2,%3};"
        : "+f"(c[0]), "+f"(c[1]), "+f"(c[2]), "+f"(c[3])
        : "r"(a[0]), "r"(a[1]), "r"(a[2]), "r"(a[3]), "r"(b[0]), "r"(b[1]));
}

__device__ __forceinline__ void mma_f16(float c[4], const unsigned a[4], const unsigned b[2]) {
    asm volatile(
        "mma.sync.aligned.m16n8k16.row.col.f32.f16.f16.f32 "
        "{%0,%1,%2,%3}, {%4,%5,%6,%7}, {%8,%9}, {%0,%1,%2,%3};"
        : "+f"(c[0]), "+f"(c[1]), "+f"(c[2]), "+f"(c[3])
        : "r"(a[0]), "r"(a[1]), "r"(a[2]), "r"(a[3]), "r"(b[0]), "r"(b[1]));
}

// ---------------- fp32 -> fp16 convert ----------------
__global__ __launch_bounds__(256) void tohalf_kernel(
    const float* __restrict__ in, __half2* __restrict__ out, int n4)
{
    for (int i = blockIdx.x * 256 + threadIdx.x; i < n4; i += gridDim.x * 256) {
        float4 v = ((const float4*)in)[i];
        out[2 * i]     = __floats2half2_rn(v.x, v.y);
        out[2 * i + 1] = __floats2half2_rn(v.z, v.w);
    }
}

// =================== TMA-fed fp16 GEMM (mma.sync f16, f32 accum) ===================
#define TG_STAGES 4
#define TG_STAGE_BYTES 49152                   // A 128*128B + B 256*128B
#define TG_SMEM_BYTES  (1024 + TG_STAGES * TG_STAGE_BYTES)

__device__ __forceinline__ uint32_t smem_u32(const void* p) {
    return (uint32_t)__cvta_generic_to_shared((void*)p);
}
__device__ __forceinline__ void tma2d(uint32_t sdst, const CUtensorMap* tm,
                                      int x, int y, uint32_t bar) {
    asm volatile(
        "cp.async.bulk.tensor.2d.shared::cta.global.tile.mbarrier::complete_tx::bytes "
        "[%0], [%1, {%2, %3}], [%4];"
        :: "r"(sdst), "l"(tm), "r"(x), "r"(y), "r"(bar) : "memory");
}
#define MBAR_INIT(a, c) \
    asm volatile("mbarrier.init.shared.b64 [%0], %1;" :: "r"(a), "r"(c) : "memory")
#define MBAR_EXPECT_TX(a, b) \
    asm volatile("mbarrier.arrive.expect_tx.shared.b64 _, [%0], %1;" :: "r"(a), "r"(b) : "memory")
#define MBAR_ARRIVE(a) \
    asm volatile("mbarrier.arrive.shared.b64 _, [%0];" :: "r"(a) : "memory")
#define MBAR_WAIT(a, ph) do { \
    uint32_t _d_; \
    asm volatile("{\n\t.reg .pred p;\n\tmbarrier.try_wait.parity.acquire.cta.shared::cta.b64 p, [%1], %2;\n\tselp.b32 %0, 1, 0, p;\n\t}" \
        : "=r"(_d_) : "r"(a), "r"(ph) : "memory"); \
    while (!_d_) { \
        asm volatile("{\n\t.reg .pred p;\n\tmbarrier.try_wait.parity.acquire.cta.shared::cta.b64 p, [%1], %2, 0x989680;\n\tselp.b32 %0, 1, 0, p;\n\t}" \
            : "=r"(_d_) : "r"(a), "r"(ph) : "memory"); \
    } \
} while (0)

__global__ __launch_bounds__(512, 1) void gemm_tma_f16_kernel(
    const __grid_constant__ CUtensorMap tmA,
    const __grid_constant__ CUtensorMap tmB,
    const float* __restrict__ bias, float* __restrict__ C,
    int N, int K)
{
    extern __shared__ char dsm[];
    __shared__ __align__(8) unsigned long long bars[8];  // full[4], empty[4]

    const int tid  = threadIdx.x;
    const int warp = tid >> 5;
    const int lane = tid & 31;
    const int wm   = warp & 3;
    const int wn   = warp >> 2;
    const int gid  = lane >> 2;
    const int tig  = lane & 3;
    const int mblk = blockIdx.y * 128;
    const int nblk = blockIdx.x * 256;
    const int KT   = K / 64;

    const uint32_t raw   = smem_u32(dsm);
    const uint32_t sbase = (raw + 1023) & ~1023u;
    char* tile0 = dsm + (sbase - raw);
    const uint32_t barb = smem_u32(bars);

    if (tid == 0) {
        for (int i = 0; i < 4; i++) MBAR_INIT(barb + i * 8, 1);
        for (int i = 4; i < 8; i++) MBAR_INIT(barb + i * 8, 16);
    }
    __syncthreads();

    if (tid == 0) {
        const int pre = KT < TG_STAGES ? KT : TG_STAGES;
        for (int st = 0; st < pre; st++) {
            const uint32_t full = barb + st * 8;
            MBAR_EXPECT_TX(full, TG_STAGE_BYTES);
            const uint32_t sa = sbase + st * TG_STAGE_BYTES;
            tma2d(sa,         &tmA, st * 64, mblk, full);
            tma2d(sa + 16384, &tmB, st * 64, nblk, full);
        }
    }

    float acc[2][8][4];
#pragma unroll
    for (int i = 0; i < 2; i++)
#pragma unroll
        for (int j = 0; j < 8; j++)
#pragma unroll
            for (int r = 0; r < 4; r++) acc[i][j][r] = 0.f;

    const uint32_t xorv = (uint32_t)gid << 4;

    for (int kt = 0; kt < KT; kt++) {
        const int st = kt & 3;
        const uint32_t ph = (kt >> 2) & 1;
        MBAR_WAIT(barb + st * 8, ph);

        const char* As = tile0 + st * TG_STAGE_BYTES;
        const char* Bs = As + 16384;

#pragma unroll
        for (int ks = 0; ks < 4; ks++) {
            const uint32_t c4a = (uint32_t)(ks * 32 + tig * 4) ^ xorv;
            const uint32_t c4b = (uint32_t)(ks * 32 + tig * 4 + 16) ^ xorv;
            unsigned afr[2][4], bfr[8][2];
#pragma unroll
            for (int mf = 0; mf < 2; mf++) {
                const int r0 = wm * 32 + mf * 16 + gid;
                afr[mf][0] = *(const unsigned*)(As + r0 * 128 + c4a);
                afr[mf][1] = *(const unsigned*)(As + (r0 + 8) * 128 + c4a);
                afr[mf][2] = *(const unsigned*)(As + r0 * 128 + c4b);
                afr[mf][3] = *(const unsigned*)(As + (r0 + 8) * 128 + c4b);
            }
#pragma unroll
            for (int nf = 0; nf < 8; nf++) {
                const int nc = wn * 64 + nf * 8 + gid;
                bfr[nf][0] = *(const unsigned*)(Bs + nc * 128 + c4a);
                bfr[nf][1] = *(const unsigned*)(Bs + nc * 128 + c4b);
            }
#pragma unroll
            for (int mf = 0; mf < 2; mf++)
#pragma unroll
                for (int nf = 0; nf < 8; nf++)
                    mma_f16(acc[mf][nf], afr[mf], bfr[nf]);
        }

        __syncwarp();
        if (lane == 0) MBAR_ARRIVE(barb + (4 + st) * 8);

        if (tid == 0 && kt + TG_STAGES < KT) {
            MBAR_WAIT(barb + (4 + st) * 8, ph);
            const uint32_t full = barb + st * 8;
            MBAR_EXPECT_TX(full, TG_STAGE_BYTES);
            const uint32_t sa = sbase + st * TG_STAGE_BYTES;
            tma2d(sa,         &tmA, (kt + TG_STAGES) * 64, mblk, full);
            tma2d(sa + 16384, &tmB, (kt + TG_STAGES) * 64, nblk, full);
        }
    }

#pragma unroll
    for (int nf = 0; nf < 8; nf++) {
        const int col = nblk + wn * 64 + nf * 8 + tig * 2;
        const float b0 = bias ? bias[col] : 0.f;
        const float b1 = bias ? bias[col + 1] : 0.f;
#pragma unroll
        for (int mf = 0; mf < 2; mf++) {
            const int row = mblk + wm * 32 + mf * 16 + gid;
            {
                float2 v = make_float2(acc[mf][nf][0] + b0, acc[mf][nf][1] + b1);
                *(float2*)(C + (size_t)row * N + col) = v;
            }
            {
                float2 v = make_float2(acc[mf][nf][2] + b0, acc[mf][nf][3] + b1);
                *(float2*)(C + (size_t)(row + 8) * N + col) = v;
            }
        }
    }
}

// ---------------- small tf32 GEMM (legacy mma): C = A @ B^T (+bias) ----------
#define SPITCH 136
__global__ __launch_bounds__(256, 2) void gemm_tf32_kernel(
    const float* __restrict__ A, const float* __restrict__ B,
    const float* __restrict__ bias, float* __restrict__ C,
    int M, int N, int K)
{
    __shared__ unsigned As[16][SPITCH];
    __shared__ unsigned Bs[16][SPITCH];

    const int tid  = threadIdx.x;
    const int warp = tid >> 5;
    const int lane = tid & 31;
    const int wm = warp & 1;
    const int wn = warp >> 1;
    const int gid = lane >> 2;
    const int tig = lane & 3;

    const int mblk = blockIdx.y * 128;
    const int nblk = blockIdx.x * 128;

    const int lr = tid >> 1;
    const int kc = (tid & 1) * 8;
    const int rowA = mblk + lr;
    const bool aval = rowA < M;
    const float* Ap = A + (size_t)(aval ? rowA : 0) * K + kc;
    const float* Bp = B + (size_t)(nblk + lr) * K + kc;

    float acc[4][4][4];
#pragma unroll
    for (int i = 0; i < 4; i++)
#pragma unroll
        for (int j = 0; j < 4; j++)
#pragma unroll
            for (int r = 0; r < 4; r++) acc[i][j][r] = 0.f;

    float4 av0 = aval ? *(const float4*)Ap : make_float4(0,0,0,0);
    float4 av1 = aval ? *(const float4*)(Ap + 4) : make_float4(0,0,0,0);
    float4 bv0 = *(const float4*)Bp;
    float4 bv1 = *(const float4*)(Bp + 4);
    Ap += 16; Bp += 16;

    for (int k0 = 0; k0 < K; k0 += 16) {
        As[kc + 0][lr] = f2tf32(av0.x); As[kc + 1][lr] = f2tf32(av0.y);
        As[kc + 2][lr] = f2tf32(av0.z); As[kc + 3][lr] = f2tf32(av0.w);
        As[kc + 4][lr] = f2tf32(av1.x); As[kc + 5][lr] = f2tf32(av1.y);
        As[kc + 6][lr] = f2tf32(av1.z); As[kc + 7][lr] = f2tf32(av1.w);
        Bs[kc + 0][lr] = f2tf32(bv0.x); Bs[kc + 1][lr] = f2tf32(bv0.y);
        Bs[kc + 2][lr] = f2tf32(bv0.z); Bs[kc + 3][lr] = f2tf32(bv0.w);
        Bs[kc + 4][lr] = f2tf32(bv1.x); Bs[kc + 5][lr] = f2tf32(bv1.y);
        Bs[kc + 6][lr] = f2tf32(bv1.z); Bs[kc + 7][lr] = f2tf32(bv1.w);
        __syncthreads();

        if (k0 + 16 < K) {
            av0 = aval ? *(const float4*)Ap : make_float4(0,0,0,0);
            av1 = aval ? *(const float4*)(Ap + 4) : make_float4(0,0,0,0);
            bv0 = *(const float4*)Bp;
            bv1 = *(const float4*)(Bp + 4);
            Ap += 16; Bp += 16;
        }

#pragma unroll
        for (int ks = 0; ks < 2; ks++) {
            const int kb = ks * 8;
            unsigned afr[4][4], bfr[4][2];
#pragma unroll
            for (int mt = 0; mt < 4; mt++) {
                const int mr = wm * 64 + mt * 16 + gid;
                afr[mt][0] = As[kb + tig][mr];
                afr[mt][1] = As[kb + tig][mr + 8];
                afr[mt][2] = As[kb + tig + 4][mr];
                afr[mt][3] = As[kb + tig + 4][mr + 8];
            }
#pragma unroll
            for (int nt = 0; nt < 4; nt++) {
                const int nc = wn * 32 + nt * 8 + gid;
                bfr[nt][0] = Bs[kb + tig][nc];
                bfr[nt][1] = Bs[kb + tig + 4][nc];
            }
#pragma unroll
            for (int mt = 0; mt < 4; mt++)
#pragma unroll
                for (int nt = 0; nt < 4; nt++)
                    mma_tf32(acc[mt][nt], afr[mt], bfr[nt]);
        }
        __syncthreads();
    }

#pragma unroll
    for (int nt = 0; nt < 4; nt++) {
        const int col = nblk + wn * 32 + nt * 8 + tig * 2;
        const float b0 = bias ? bias[col] : 0.f;
        const float b1 = bias ? bias[col + 1] : 0.f;
#pragma unroll
        for (int mt = 0; mt < 4; mt++) {
            const int row = mblk + wm * 64 + mt * 16 + gid;
            if (row < M) {
                float2 v = make_float2(acc[mt][nt][0] + b0, acc[mt][nt][1] + b1);
                *(float2*)(C + (size_t)row * N + col) = v;
            }
            if (row + 8 < M) {
                float2 v = make_float2(acc[mt][nt][2] + b0, acc[mt][nt][3] + b1);
                *(float2*)(C + (size_t)(row + 8) * N + col) = v;
            }
        }
    }
}

// ---------------- LayerNorm + ReLU (fp32 out) ----------------
__global__ __launch_bounds__(256) void ln_relu_kernel(
    const float* __restrict__ in, const float* __restrict__ g,
    const float* __restrict__ be, float* __restrict__ out, int C)
{
    __shared__ float red[256];
    const int row = blockIdx.x;
    const int tid = threadIdx.x;
    const float* rp = in + (size_t)row * C;
    float s = 0.f, sq = 0.f;
    for (int c = tid; c < C; c += 256) { float v = rp[c]; s += v; sq += v * v; }
    red[tid] = s; __syncthreads();
    for (int o = 128; o > 0; o >>= 1) { if (tid < o) red[tid] += red[tid + o]; __syncthreads(); }
    float mean = red[0] / (float)C;
    __syncthreads();
    red[tid] = sq; __syncthreads();
    for (int o = 128; o > 0; o >>= 1) { if (tid < o) red[tid] += red[tid + o]; __syncthreads(); }
    float var = red[0] / (float)C - mean * mean;
    float rs = rsqrtf(var + 1e-5f);
    float* op = out + (size_t)row * C;
    for (int c = tid; c < C; c += 256) {
        float v = (rp[c] - mean) * rs * g[c] + be[c];
        op[c] = fmaxf(v, 0.f);
    }
}

// ---------------- LayerNorm + ReLU (fp16 out) ----------------
__global__ __launch_bounds__(256) void ln_relu_f16_kernel(
    const float* __restrict__ in, const float* __restrict__ g,
    const float* __restrict__ be, __half* __restrict__ out, int C)
{
    __shared__ float red[256];
    const int row = blockIdx.x;
    const int tid = threadIdx.x;
    const float* rp = in + (size_t)row * C;
    float s = 0.f, sq = 0.f;
    for (int c = tid; c < C; c += 256) { float v = rp[c]; s += v; sq += v * v; }
    red[tid] = s; __syncthreads();
    for (int o = 128; o > 0; o >>= 1) { if (tid < o) red[tid] += red[tid + o]; __syncthreads(); }
    float mean = red[0] / (float)C;
    __syncthreads();
    red[tid] = sq; __syncthreads();
    for (int o = 128; o > 0; o >>= 1) { if (tid < o) red[tid] += red[tid + o]; __syncthreads(); }
    float var = red[0] / (float)C - mean * mean;
    float rs = rsqrtf(var + 1e-5f);
    __half* op = out + (size_t)row * C;
    for (int c = tid; c < C; c += 256) {
        float v = (rp[c] - mean) * rs * g[c] + be[c];
        op[c] = __float2half_rn(fmaxf(v, 0.f));
    }
}

// ---------------- concat [expanded(32); pos(128)] ----------------
__global__ __launch_bounds__(256) void concat_kernel(
    const float* __restrict__ e, const float* __restrict__ pos, float* __restrict__ o)
{
    int i = blockIdx.x * 256 + threadIdx.x;
    o[i] = (i < 32 * 1024) ? e[i] : pos[i - 32 * 1024];
}

// ---------------- pack h0 into exchange set 0 as (hi, lo*2048) half planes --------
__global__ __launch_bounds__(256) void pack_h0_kernel(
    const float* __restrict__ EXP, __half* __restrict__ HBh)
{
    int i = blockIdx.x * 256 + threadIdx.x;   // 128 blocks -> 32768 (b*1024+k)
    const float v = EXP[i];
    const __half hi = __float2half_rn(v);
    const __half lo = __float2half_rn((v - __half2float(hi)) * 2048.0f);
    // set 0: [d][plane][32*1024]
    HBh[i] = hi;            HBh[32768 + i] = lo;            // d=0
    HBh[65536 + i] = hi;    HBh[65536 + 32768 + i] = lo;    // d=1
}

// ---------------- persistent RNN layer (fp16 2-term split, 512 thr) ---------------
// 128 blocks: d = bid>>6, n0 = (bid&63)*16. 16 warps = 16-way k-split (64 k each).
// smem halves: Hh[32][1032] | Hl[32][1032] | Wh[16][1032] | Wl[16][1032].
// Red (32 KB fp32) aliases Hh.
#define RNP 1032
#define RNN2_HL_OFF  (32 * RNP * 2)
#define RNN2_WH_OFF  (RNN2_HL_OFF * 2)
#define RNN2_WL_OFF  (RNN2_WH_OFF + 16 * RNP * 2)
#define RNN2_SMEM_BYTES (RNN2_WL_OFF + 16 * RNP * 2)

__device__ __forceinline__ unsigned ld_acquire_u32(unsigned* p) {
    unsigned v;
    asm volatile("ld.acquire.gpu.global.u32 %0, [%1];" : "=r"(v) : "l"(p) : "memory");
    return v;
}
__device__ __forceinline__ unsigned atom_add_acqrel(unsigned* p, unsigned v) {
    unsigned o;
    asm volatile("atom.acq_rel.gpu.global.add.u32 %0, [%1], %2;" : "=r"(o) : "l"(p), "r"(v) : "memory");
    return o;
}
__device__ __forceinline__ void st_relaxed_u32(unsigned* p, unsigned v) {
    asm volatile("st.relaxed.gpu.global.u32 [%0], %1;" :: "l"(p), "r"(v) : "memory");
}
__device__ __forceinline__ void st_release_u32(unsigned* p, unsigned v) {
    asm volatile("st.release.gpu.global.u32 [%0], %1;" :: "l"(p), "r"(v) : "memory");
}

__global__ __launch_bounds__(512, 1) void rnn_layer_kernel(
    const float* __restrict__ Whh, const float* __restrict__ gate,
    const float* __restrict__ bih, const float* __restrict__ bhh,
    __half* __restrict__ HBh, __half* __restrict__ Y, int layer)
{
    extern __shared__ char sm2[];
    __half* Hh = (__half*)sm2;
    __half* Hl = (__half*)(sm2 + RNN2_HL_OFF);
    __half* Wh = (__half*)(sm2 + RNN2_WH_OFF);
    __half* Wl = (__half*)(sm2 + RNN2_WL_OFF);

    const int tid  = threadIdx.x;
    const int bid  = blockIdx.x;
    const int d    = bid >> 6;
    const int n0   = (bid & 63) * 16;
    const int kq   = tid >> 5;        // 0..15, k-slice [kq*64, +64)
    const int lane = tid & 31;
    const int gid  = lane >> 2;
    const int tig  = lane & 3;

    // prologue: split W into hi fp16 + lo fp16 (x2048), layout [n][k]
    for (int i = tid; i < 16384; i += 512) {
        const int n = i >> 10, k = i & 1023;
        const float w = Whh[(size_t)(d * 1024 + n0 + n) * 1024 + k];
        const __half hi = __float2half_rn(w);
        Wh[n * RNP + k] = hi;
        Wl[n * RNP + k] = __float2half_rn((w - __half2float(hi)) * 2048.0f);
    }
    __syncthreads();

    // step-invariant epilogue terms
    const int eb   = tid >> 4;
    const int encl = n0 + (tid & 15);
    const int ecol = d * 1024 + encl;
    const float bb = bih[ecol] + bhh[ecol];
    float gB = 0.f;
    if (layer == 0) gB = gate[(size_t)eb * 2048 + ecol];

    unsigned bar_sense = 0;
    unsigned* bcount = &g_bar_count2[d];
    unsigned* bsense = &g_bar_sense2[d];

    for (int s = 1; s <= T_LEN; s++) {
        const int t = d ? (T_LEN - s) : (s - 1);

        float gT;
        if (layer == 0) gT = gate[(size_t)(32 + t) * 2048 + ecol];
        else            gT = gate[(size_t)(t * 32 + eb) * 2048 + ecol];

        // ---- each warp copies its 64-wide k-slice of both h planes ----
        const __half* srcH = HBh + ((s - 1) & 1) * 131072 + d * 65536;
        const __half* srcL = srcH + 32768;
        for (int j = lane; j < 256; j += 32) {
            const int b = j >> 3, u = j & 7;     // 8 uint4 per 64-half row slice
            const int go = b * 1024 + kq * 64 + u * 8;
            const int so = b * RNP + kq * 64 + u * 8;
            *(uint4*)&Hh[so] = *(const uint4*)&srcH[go];
            *(uint4*)&Hl[so] = *(const uint4*)&srcL[go];
        }
        __syncwarp();

        // ---- fp16 2-term mma over k-slice [kq*64, +64) ----
        float acc1[2][2][4], acc2[2][2][4];
#pragma unroll
        for (int i = 0; i < 2; i++)
#pragma unroll
            for (int j = 0; j < 2; j++)
#pragma unroll
                for (int r = 0; r < 4; r++) { acc1[i][j][r] = 0.f; acc2[i][j][r] = 0.f; }

#pragma unroll
        for (int kf = 0; kf < 4; kf++) {
            const int kk = kq * 64 + kf * 16;
            unsigned ahi[2][4], alo[2][4];
#pragma unroll
            for (int mt = 0; mt < 2; mt++) {
                const int r0 = (mt * 16 + gid) * RNP + kk + tig * 2;
                const int r1 = (mt * 16 + gid + 8) * RNP + kk + tig * 2;
                ahi[mt][0] = *(const unsigned*)&Hh[r0];
                ahi[mt][1] = *(const unsigned*)&Hh[r1];
                ahi[mt][2] = *(const unsigned*)&Hh[r0 + 8];
                ahi[mt][3] = *(const unsigned*)&Hh[r1 + 8];
                alo[mt][0] = *(const unsigned*)&Hl[r0];
                alo[mt][1] = *(const unsigned*)&Hl[r1];
                alo[mt][2] = *(const unsigned*)&Hl[r0 + 8];
                alo[mt][3] = *(const unsigned*)&Hl[r1 + 8];
            }
            unsigned bhi[2][2], blo[2][2];
#pragma unroll
            for (int nt = 0; nt < 2; nt++) {
                const int c0 = (nt * 8 + gid) * RNP + kk + tig * 2;
                bhi[nt][0] = *(const unsigned*)&Wh[c0];
                bhi[nt][1] = *(const unsigned*)&Wh[c0 + 8];
                blo[nt][0] = *(const unsigned*)&Wl[c0];
                blo[nt][1] = *(const unsigned*)&Wl[c0 + 8];
            }
#pragma unroll
            for (int mt = 0; mt < 2; mt++)
#pragma unroll
                for (int nt = 0; nt < 2; nt++) {
                    mma_f16(acc1[mt][nt], ahi[mt], bhi[nt]);   // hi*hi
                    mma_f16(acc2[mt][nt], alo[mt], bhi[nt]);   // lo*hi (x2048)
                    mma_f16(acc2[mt][nt], ahi[mt], blo[nt]);   // hi*lo (x2048)
                }
        }

        // ---- cross-warp k-reduction via Red (fp32, aliases Hh) ----
        __syncthreads();
        float* Red = (float*)Hh;   // Red[kq*512 + b*16 + n], 8192 floats = 32KB
#pragma unroll
        for (int mt = 0; mt < 2; mt++)
#pragma unroll
            for (int nt = 0; nt < 2; nt++)
#pragma unroll
                for (int r = 0; r < 4; r++) {
                    const int b = mt * 16 + gid + ((r >> 1) << 3);
                    const int n = nt * 8 + tig * 2 + (r & 1);
                    Red[kq * 512 + b * 16 + n] =
                        acc1[mt][nt][r] + acc2[mt][nt][r] * (1.0f / 2048.0f);
                }
        __syncthreads();

        // ---- epilogue: one output per thread ----
        {
            float v = 0.f;
#pragma unroll
            for (int kq2 = 0; kq2 < 16; kq2++) v += Red[kq2 * 512 + tid];
            const float hnew = fmaxf(v + gB + gT + bb, 0.f);
            const __half hhi = __float2half_rn(hnew);
            const __half hlo = __float2half_rn((hnew - __half2float(hhi)) * 2048.0f);
            __half* dstH = HBh + (s & 1) * 131072 + d * 65536;
            dstH[eb * 1024 + encl] = hhi;
            dstH[32768 + eb * 1024 + encl] = hlo;
            const int row = layer ? (eb * 128 + t) : (t * 32 + eb);
            Y[(size_t)row * 2048 + ecol] = hhi;
        }

        // ---- per-direction grid barrier (64 blocks) ----
        __syncthreads();
        if (tid == 0) {
            const unsigned target = bar_sense ^ 1;
            unsigned old = atom_add_acqrel(bcount, 1);
            if (old == 63) {
                st_relaxed_u32(bcount, 0);
                st_release_u32(bsense, target);
            } else {
                while (ld_acquire_u32(bsense) != target) { }
            }
        }
        bar_sense ^= 1;
        __syncthreads();
    }
}

// ---------------- launch helpers ----------------
static inline void gemm_small(const float* A, const float* B, const float* bias,
                              float* C, int M, int N, int K)
{
    dim3 grid(N / 128, (M + 127) / 128);
    gemm_tf32_kernel<<<grid, 256>>>(A, B, bias, C, M, N, K);
}

typedef CUresult (CUDAAPI *PFN_encodeTiled)(
    CUtensorMap*, CUtensorMapDataType, cuuint32_t, void*,
    const cuuint64_t*, const cuuint64_t*, const cuuint32_t*, const cuuint32_t*,
    CUtensorMapInterleave, CUtensorMapSwizzle, CUtensorMapL2promotion,
    CUtensorMapFloatOOBfill);

static inline CUtensorMap make_map2d_f16(PFN_encodeTiled enc, const void* ptr,
                                         int rows, int K, int boxRows)
{
    CUtensorMap m{};
    cuuint64_t dims[2]    = {(cuuint64_t)K, (cuuint64_t)rows};
    cuuint64_t strides[1] = {(cuuint64_t)K * 2};
    cuuint32_t box[2]     = {64u, (cuuint32_t)boxRows};
    cuuint32_t es[2]      = {1u, 1u};
    enc(&m, CU_TENSOR_MAP_DATA_TYPE_UINT16, 2, (void*)ptr,
        dims, strides, box, es,
        CU_TENSOR_MAP_INTERLEAVE_NONE, CU_TENSOR_MAP_SWIZZLE_128B,
        CU_TENSOR_MAP_L2_PROMOTION_L2_128B, CU_TENSOR_MAP_FLOAT_OOB_FILL_NONE);
    return m;
}

extern "C" void kernel_launch(void* const* d_in, const int* in_sizes, int n_in,
                              void* d_out, int out_size)
{
    (void)in_sizes; (void)n_in; (void)out_size;
    const float* x     = (const float*)d_in[0];
    const float* W_exp = (const float*)d_in[1];
    const float* b_exp = (const float*)d_in[2];
    const float* g1    = (const float*)d_in[3];
    const float* be1   = (const float*)d_in[4];
    const float* pos   = (const float*)d_in[5];
    const float* Wih0  = (const float*)d_in[6];
    const float* Whh0  = (const float*)d_in[7];
    const float* bih0  = (const float*)d_in[8];
    const float* bhh0  = (const float*)d_in[9];
    const float* Wih1  = (const float*)d_in[10];
    const float* Whh1  = (const float*)d_in[11];
    const float* bih1  = (const float*)d_in[12];
    const float* bhh1  = (const float*)d_in[13];
    const float* Wp1   = (const float*)d_in[14];
    const float* bp1   = (const float*)d_in[15];
    const float* g2    = (const float*)d_in[16];
    const float* be2   = (const float*)d_in[17];
    const float* Wp2   = (const float*)d_in[18];
    const float* bp2   = (const float*)d_in[19];
    float* out = (float*)d_out;

    float* S = nullptr;
    cudaGetSymbolAddress((void**)&S, g_scratch);

    float*  PRE   = S + OFF_PRE;
    float*  EXP   = S + OFF_EXP;
    float*  A0IN  = S + OFF_A0IN;
    float*  C0    = S + OFF_C0;
    __half* HBh   = (__half*)(S + OFF_HB);
    __half* X1H   = (__half*)(S + OFF_X1H);
    float*  G1    = S + OFF_G1;
    __half* OUT2H = (__half*)(S + OFF_OUT2H);
    float*  PROJ  = S + OFF_PROJ;
    __half* HEH   = (__half*)(S + OFF_HEH);
    __half* WIH1H = (__half*)(S + OFF_WIH1H);
    __half* WP1H  = (__half*)(S + OFF_WP1H);
    __half* WP2H  = (__half*)(S + OFF_WP2H);

    PFN_encodeTiled enc = nullptr;
    cudaGetDriverEntryPoint("cuTensorMapEncodeTiled", (void**)&enc, cudaEnableDefault);

    CUtensorMap tmA_G1  = make_map2d_f16(enc, X1H,   4096,  2048, 128);
    CUtensorMap tmB_G1  = make_map2d_f16(enc, WIH1H, 2048,  2048, 256);
    CUtensorMap tmA_PRJ = make_map2d_f16(enc, OUT2H, 4096,  2048, 128);
    CUtensorMap tmB_PRJ = make_map2d_f16(enc, WP1H,  512,   2048, 256);
    CUtensorMap tmA_LOG = make_map2d_f16(enc, HEH,   4096,  512,  128);
    CUtensorMap tmB_LOG = make_map2d_f16(enc, WP2H,  32000, 512,  256);

    cudaFuncSetAttribute(rnn_layer_kernel,
                         cudaFuncAttributeMaxDynamicSharedMemorySize, RNN2_SMEM_BYTES);
    cudaFuncSetAttribute(gemm_tma_f16_kernel,
                         cudaFuncAttributeMaxDynamicSharedMemorySize, TG_SMEM_BYTES);

    // 0) pre-convert weights to fp16
    tohalf_kernel<<<512, 256>>>(Wih1, (__half2*)WIH1H, 2 * 1024 * 2048 / 4);
    tohalf_kernel<<<512, 256>>>(Wp1,  (__half2*)WP1H,  512 * 2048 / 4);
    tohalf_kernel<<<512, 256>>>(Wp2,  (__half2*)WP2H,  32000 * 512 / 4);

    // 1) expand
    gemm_small(x, W_exp, b_exp, PRE, 32, 1024, 512);
    ln_relu_kernel<<<32, 256>>>(PRE, g1, be1, EXP, 1024);

    // 2) layer-0 gate factors
    concat_kernel<<<640, 256>>>(EXP, pos, A0IN);
    gemm_small(A0IN, Wih0, nullptr, C0, 160, 2048, 1024);

    // 3) layer-0 recurrence (persistent, fp16 2-term), writes X1 as fp16
    pack_h0_kernel<<<128, 256>>>(EXP, HBh);
    rnn_layer_kernel<<<128, 512, RNN2_SMEM_BYTES>>>(Whh0, C0, bih0, bhh0, HBh, X1H, 0);

    // 4) layer-1 gates (fp16 TMA GEMM): G1[4096,2048] fp32 out
    {
        dim3 grid(2048 / 256, 4096 / 128);
        gemm_tma_f16_kernel<<<grid, 512, TG_SMEM_BYTES>>>(tmA_G1, tmB_G1, nullptr, G1, 2048, 2048);
    }

    // 5) layer-1 recurrence (persistent, fp16 2-term), writes OUT2 as fp16
    pack_h0_kernel<<<128, 256>>>(EXP, HBh);
    rnn_layer_kernel<<<128, 512, RNN2_SMEM_BYTES>>>(Whh1, G1, bih1, bhh1, HBh, OUT2H, 1);

    // 6) projection head (fp16 TMA GEMM) + LN+ReLU -> fp16
    {
        dim3 grid(512 / 256, 4096 / 128);
        gemm_tma_f16_kernel<<<grid, 512, TG_SMEM_BYTES>>>(tmA_PRJ, tmB_PRJ, bp1, PROJ, 512, 2048);
    }
    ln_relu_f16_kernel<<<4096, 256>>>(PROJ, g2, be2, HEH, 512);

    // 7) logits (fp16 TMA GEMM)
    {
        dim3 grid(32000 / 256, 4096 / 128);
        gemm_tma_f16_kernel<<<grid, 512, TG_SMEM_BYTES>>>(tmA_LOG, tmB_LOG, bp2, out, 32000, 512);
    }
}